// round 1
// baseline (speedup 1.0000x reference)
#include <cuda_runtime.h>
#include <math.h>

#define M_TOTAL 81920
#define NGROUP  2048          // M/40
#define N_ENT   14541
#define N_REL   237
#define G4      400
#define F6      600

// ---------------- scratch (device globals: no allocation allowed) ----------
__device__ float g_Pf_e[N_ENT*G4];
__device__ float g_Pf_r[N_REL*G4];
__device__ float g_Pb_e[N_ENT*G4];
__device__ float g_Pb_r[N_REL*G4];
__device__ float g_Pp_e[N_ENT*G4];
__device__ float g_Pp_r[N_REL*G4];
__device__ float g_out[(size_t)M_TOTAL*F6];   // BiLSTM concat output [M,600]
__device__ float g_hG [(size_t)M_TOTAL*F6];   // GAT1 projected features
__device__ float g_op [(size_t)M_TOTAL*100];  // process-LSTM last hidden

__device__ __forceinline__ float sigmoidf_(float x){
    return __fdividef(1.f, 1.f + __expf(-x));
}
__device__ __forceinline__ float tanhf_(float x){
    float xc = fminf(fmaxf(x,-15.f),15.f);
    float e = __expf(2.f*xc);
    return __fdividef(e-1.f, e+1.f);
}

// ---------------------------------------------------------------------------
// K0: vocabulary-level input projections  P[e][g] = sum_k emb[e][k]*Wih[g][k]
// grid = (228, 6), block = 256.  smem: emb tile 64x101 + full W 400x100
// ---------------------------------------------------------------------------
#define PROJ_SMEM ((64*101 + 400*100)*4)
__global__ void __launch_bounds__(256,1) proj_kernel(
    const float* __restrict__ ent,  const float* __restrict__ rel,
    const float* __restrict__ ent1, const float* __restrict__ rel1,
    const float* __restrict__ Wf,   const float* __restrict__ Wb,
    const float* __restrict__ Wp)
{
    const float* emb; const float* W; float* P; int nrows;
    switch (blockIdx.y){
      case 0:  emb=ent;  W=Wf; P=g_Pf_e; nrows=N_ENT; break;
      case 1:  emb=rel;  W=Wf; P=g_Pf_r; nrows=N_REL; break;
      case 2:  emb=ent;  W=Wb; P=g_Pb_e; nrows=N_ENT; break;
      case 3:  emb=rel;  W=Wb; P=g_Pb_r; nrows=N_REL; break;
      case 4:  emb=ent1; W=Wp; P=g_Pp_e; nrows=N_ENT; break;
      default: emb=rel1; W=Wp; P=g_Pp_r; nrows=N_REL; break;
    }
    int r0 = blockIdx.x*64;
    if (r0 >= nrows) return;
    extern __shared__ float sm[];
    float* esm = sm;            // 64 x 101 (odd pitch -> conflict free)
    float* wsm = sm + 64*101;   // 400 x 100
    int tid = threadIdx.x;
    for (int i=tid;i<40000;i+=256) wsm[i]=W[i];
    for (int i=tid;i<6400;i+=256){
        int r=i/100, k=i-r*100;
        esm[r*101+k] = (r0+r < nrows) ? emb[(size_t)(r0+r)*100+k] : 0.f;
    }
    __syncthreads();
    int warp=tid>>5, lane=tid&31;
    int gb = warp*50;                 // warp owns 50 gates
    float acc0[50], acc1[50];
    #pragma unroll
    for (int g=0;g<50;g++){ acc0[g]=0.f; acc1[g]=0.f; }
    #pragma unroll 1
    for (int k=0;k<100;k++){
        float x0 = esm[lane*101+k];
        float x1 = esm[(lane+32)*101+k];
        const float* wp = wsm + gb*100 + k;
        #pragma unroll
        for (int g=0;g<50;g++){
            float w = wp[g*100];
            acc0[g]=fmaf(w,x0,acc0[g]);
            acc1[g]=fmaf(w,x1,acc1[g]);
        }
    }
    int e0=r0+lane, e1=e0+32;
    if (e0<nrows){
        float* p=P+(size_t)e0*G4+gb;
        #pragma unroll
        for (int g=0;g<50;g++) p[g]=acc0[g];
    }
    if (e1<nrows){
        float* p=P+(size_t)e1*G4+gb;
        #pragma unroll
        for (int g=0;g<50;g++) p[g]=acc1[g];
    }
}

// ---------------------------------------------------------------------------
// K1: fused triple-LSTM recurrence. 64 rows/block, 256 threads.
// gates[64][405] (odd pitch), h[64][101], Whh streamed in 400x50 chunks.
// ---------------------------------------------------------------------------
#define LSTM_SMEM ((64*405 + 64*101 + 400*50)*4)
__global__ void __launch_bounds__(256,1) lstm_kernel(
    const int* __restrict__ bh, const int* __restrict__ br, const int* __restrict__ bt,
    const float* __restrict__ Whh_f, const float* __restrict__ Whh_b, const float* __restrict__ Whh_p,
    const float* __restrict__ b_f,   const float* __restrict__ b_b,   const float* __restrict__ b_p)
{
    extern __shared__ float sm[];
    float* gates = sm;                 // 64*405
    float* hsm   = gates + 64*405;     // 64*101
    float* wc    = hsm   + 64*101;     // 400*50
    __shared__ int idxs[3][64];

    int tid  = threadIdx.x;
    int warp = tid>>5, lane = tid&31;
    int row0 = blockIdx.x*64;
    if (tid < 64)       idxs[0][tid]     = bh[row0+tid];
    else if (tid < 128) idxs[1][tid-64]  = br[row0+tid-64];
    else if (tid < 192) idxs[2][tid-128] = bt[row0+tid-128];
    __syncthreads();

    for (int l=0;l<3;l++){
        const float* Pent = (l==0)?g_Pf_e:(l==1)?g_Pb_e:g_Pp_e;
        const float* Prel = (l==0)?g_Pf_r:(l==1)?g_Pb_r:g_Pp_r;
        const float* Whh  = (l==0)?Whh_f :(l==1)?Whh_b :Whh_p;
        const float* bias = (l==0)?b_f   :(l==1)?b_b   :b_p;

        float creg[25];
        #pragma unroll
        for (int i=0;i<25;i++) creg[i]=0.f;
        for (int i=tid;i<64*101;i+=256) hsm[i]=0.f;
        __syncthreads();

        for (int s=0;s<3;s++){
            int pos = (l==1) ? (2-s) : s;      // backward LSTM walks reversed
            const float* tab = (pos==1) ? Prel : Pent;
            // gather precomputed gate inputs (400 floats/row)
            for (int r=warp;r<64;r+=8){
                const float* src = tab + (size_t)idxs[pos][r]*G4;
                float* dst = gates + r*405;
                for (int k=lane;k<G4;k+=32) dst[k]=src[k];
            }
            __syncthreads();

            if (s>0){   // + h @ Whh^T
                int gb = warp*50;
                float acc0[50], acc1[50];
                #pragma unroll
                for (int g=0;g<50;g++){
                    acc0[g]=gates[lane*405+gb+g];
                    acc1[g]=gates[(lane+32)*405+gb+g];
                }
                for (int kc=0;kc<100;kc+=50){
                    __syncthreads();
                    for (int i=tid;i<20000;i+=256){
                        int g=i/50, kk=i-g*50;
                        wc[i]=Whh[g*100+kc+kk];
                    }
                    __syncthreads();
                    #pragma unroll 1
                    for (int kk=0;kk<50;kk++){
                        float x0 = hsm[lane*101+kc+kk];
                        float x1 = hsm[(lane+32)*101+kc+kk];
                        const float* wr = wc + gb*50 + kk;
                        #pragma unroll
                        for (int g=0;g<50;g++){
                            float w = wr[g*50];
                            acc0[g]=fmaf(w,x0,acc0[g]);
                            acc1[g]=fmaf(w,x1,acc1[g]);
                        }
                    }
                }
                __syncthreads();
                #pragma unroll
                for (int g=0;g<50;g++){
                    gates[lane*405+gb+g]     =acc0[g];
                    gates[(lane+32)*405+gb+g]=acc1[g];
                }
                __syncthreads();
            }

            // elementwise LSTM cell, thread owns 25 (row,j) pairs
            #pragma unroll
            for (int i=0;i<25;i++){
                int e = tid + i*256;
                int row = e/100, j = e - row*100;
                const float* gr = gates + row*405;
                float iv = gr[j]     + bias[j];
                float fv = gr[100+j] + bias[100+j];
                float gv = gr[200+j] + bias[200+j];
                float ov = gr[300+j] + bias[300+j];
                float c  = sigmoidf_(fv)*creg[i] + sigmoidf_(iv)*tanhf_(gv);
                creg[i]  = c;
                float h  = sigmoidf_(ov)*tanhf_(c);
                hsm[row*101+j]=h;
                size_t grow = (size_t)(row0+row);
                if (l==0)        g_out[grow*600 + s*200 + j]             = h;
                else if (l==1)   g_out[grow*600 + (2-s)*200 + 100 + j]   = h;
                else if (s==2)   g_op [grow*100 + j]                     = h;
            }
            __syncthreads();
        }
    }
}

// ---------------------------------------------------------------------------
// K2: GAT1 GEMM  hG = g_out[81920,600] @ W_att1[600,600]
// 64x64 tile, 256 threads, 4x4 micro tiles, kc=24.
// ---------------------------------------------------------------------------
__global__ void __launch_bounds__(256,1) gat1_gemm(const float* __restrict__ W1)
{
    __shared__ float As[64][25];
    __shared__ float Bs[24][68];
    int tid=threadIdx.x;
    int tx=tid&15, ty=tid>>4;
    int row0=blockIdx.x*64, col0=blockIdx.y*64;
    float acc[4][4];
    #pragma unroll
    for (int i=0;i<4;i++)
        #pragma unroll
        for (int j=0;j<4;j++) acc[i][j]=0.f;

    for (int k0=0;k0<600;k0+=24){
        for (int i=tid;i<64*24;i+=256){
            int r=i/24, kk=i-r*24;
            As[r][kk]=g_out[(size_t)(row0+r)*600 + k0+kk];
        }
        for (int i=tid;i<24*64;i+=256){
            int kk=i/64, n=i-kk*64; int c=col0+n;
            Bs[kk][n]=(c<600)? W1[(k0+kk)*600+c] : 0.f;
        }
        __syncthreads();
        #pragma unroll
        for (int kk=0;kk<24;kk++){
            float a[4],b[4];
            #pragma unroll
            for (int i=0;i<4;i++){ a[i]=As[ty*4+i][kk]; b[i]=Bs[kk][tx*4+i]; }
            #pragma unroll
            for (int i=0;i<4;i++)
                #pragma unroll
                for (int j=0;j<4;j++) acc[i][j]=fmaf(a[i],b[j],acc[i][j]);
        }
        __syncthreads();
    }
    #pragma unroll
    for (int i=0;i<4;i++)
        #pragma unroll
        for (int j=0;j<4;j++){
            int c=col0+tx*4+j;
            if (c<600) g_hG[(size_t)(row0+ty*4+i)*600+c]=acc[i][j];
        }
}

// ---------------------------------------------------------------------------
// K3: GAT1 attention per group of 40 rows (+ out2 copy on even groups)
// ---------------------------------------------------------------------------
#define GAT1_SMEM ((40*600 + 48 + 40)*4)
__global__ void __launch_bounds__(256,1) gat1_att(
    const float* __restrict__ a1, float* __restrict__ out_att, float* __restrict__ out2)
{
    extern __shared__ float sm[];
    float* hg   = sm;            // 40*600
    float* ebuf = sm + 24000;    // 48 (slot 40 = node0 . a[600:1200])
    float* att  = ebuf + 48;     // 40
    int b=blockIdx.x, tid=threadIdx.x;
    const float* src = g_hG + (size_t)b*24000;
    for (int i=tid;i<24000;i+=256) hg[i]=src[i];
    __syncthreads();

    int warp=tid>>5, lane=tid&31;
    for (int t=warp;t<41;t+=8){
        const float* rowp = (t<40)? hg + t*600 : hg;
        const float* av   = (t<40)? a1        : a1+600;
        float s=0.f;
        for (int k=lane;k<600;k+=32) s += rowp[k]*av[k];
        #pragma unroll
        for (int o=16;o;o>>=1) s += __shfl_down_sync(0xffffffffu, s, o);
        if (lane==0) ebuf[t]=s;
    }
    __syncthreads();
    if (tid<40){
        float x = ebuf[tid] + ebuf[40];
        ebuf[tid] = (x>=0.f)? x : 0.2f*x;
    }
    __syncthreads();
    if (tid==0){
        float m=-1e30f;
        for (int n=0;n<40;n++) m = fmaxf(m, ebuf[n]);
        float ssum=0.f;
        for (int n=0;n<40;n++){ float ex=expf(ebuf[n]-m); att[n]=ex; ssum+=ex; }
        float inv=1.f/ssum;
        for (int n=0;n<40;n++){ float a=att[n]*inv - 0.001f; att[n]=(a>0.f)?a:0.f; }
    }
    __syncthreads();
    for (int f=tid;f<600;f+=256){
        float acc=0.f;
        #pragma unroll 8
        for (int n=0;n<40;n++) acc += att[n]*hg[n*600+f];
        out_att[(size_t)b*600+f]=acc;
    }
    if ((b&1)==0){
        const float* srow = g_out + (size_t)(b*40)*600;
        float* drow = out2 + (size_t)(b>>1)*600;
        for (int f=tid;f<600;f+=256) drow[f]=srow[f];
    }
}

// ---------------------------------------------------------------------------
// K4: GAT2 fully fused per group (projection [40,100]@[100,100] + attention)
// ---------------------------------------------------------------------------
#define GAT2_SMEM ((4000 + 10000 + 4000 + 48 + 40)*4)
__global__ void __launch_bounds__(256,1) gat2_kernel(
    const float* __restrict__ W2, const float* __restrict__ a2,
    float* __restrict__ output_att, float* __restrict__ op2)
{
    extern __shared__ float sm[];
    float* ops  = sm;            // 40*100
    float* Ws   = ops + 4000;    // 100*100
    float* hg   = Ws  + 10000;   // 40*100
    float* ebuf = hg  + 4000;    // 48
    float* att  = ebuf + 48;     // 40
    int b=blockIdx.x, tid=threadIdx.x;
    const float* src = g_op + (size_t)b*4000;
    for (int i=tid;i<4000;i+=256)  ops[i]=src[i];
    for (int i=tid;i<10000;i+=256) Ws[i]=W2[i];
    __syncthreads();
    for (int i=tid;i<4000;i+=256){
        int n=i/100, o=i-n*100;
        float acc=0.f;
        #pragma unroll 4
        for (int k=0;k<100;k++) acc=fmaf(ops[n*100+k], Ws[k*100+o], acc);
        hg[i]=acc;
    }
    __syncthreads();
    int warp=tid>>5, lane=tid&31;
    for (int t=warp;t<41;t+=8){
        const float* rowp = (t<40)? hg + t*100 : hg;
        const float* av   = (t<40)? a2        : a2+100;
        float s=0.f;
        for (int k=lane;k<100;k+=32) s += rowp[k]*av[k];
        #pragma unroll
        for (int o=16;o;o>>=1) s += __shfl_down_sync(0xffffffffu, s, o);
        if (lane==0) ebuf[t]=s;
    }
    __syncthreads();
    if (tid<40){
        float x = ebuf[tid] + ebuf[40];
        ebuf[tid] = (x>=0.f)? x : 0.2f*x;
    }
    __syncthreads();
    if (tid==0){
        float m=-1e30f;
        for (int n=0;n<40;n++) m = fmaxf(m, ebuf[n]);
        float ssum=0.f;
        for (int n=0;n<40;n++){ float ex=expf(ebuf[n]-m); att[n]=ex; ssum+=ex; }
        float inv=1.f/ssum;
        for (int n=0;n<40;n++){ float a=att[n]*inv - 0.001f; att[n]=(a>0.f)?a:0.f; }
    }
    __syncthreads();
    for (int f=tid;f<100;f+=256){
        float acc=0.f;
        #pragma unroll 8
        for (int n=0;n<40;n++) acc += att[n]*hg[n*100+f];
        output_att[(size_t)b*100+f]=acc;
    }
    if ((b&1)==0){
        const float* srow = g_op + (size_t)(b*40)*100;
        float* drow = op2 + (size_t)(b>>1)*100;
        for (int f=tid;f<100;f+=256) drow[f]=srow[f];
    }
}

// ---------------------------------------------------------------------------
extern "C" void kernel_launch(void* const* d_in, const int* in_sizes, int n_in,
                              void* d_out, int out_size)
{
    const int*   bh    = (const int*)  d_in[0];
    const int*   br    = (const int*)  d_in[1];
    const int*   bt    = (const int*)  d_in[2];
    const float* ent   = (const float*)d_in[3];
    const float* rel   = (const float*)d_in[4];
    const float* ent1  = (const float*)d_in[5];
    const float* rel1  = (const float*)d_in[6];
    const float* Wih_f = (const float*)d_in[7];
    const float* Whh_f = (const float*)d_in[8];
    const float* b_f   = (const float*)d_in[9];
    const float* Wih_b = (const float*)d_in[10];
    const float* Whh_b = (const float*)d_in[11];
    const float* b_b   = (const float*)d_in[12];
    const float* Wih_p = (const float*)d_in[13];
    const float* Whh_p = (const float*)d_in[14];
    const float* b_p   = (const float*)d_in[15];
    const float* W1    = (const float*)d_in[16];
    const float* a1    = (const float*)d_in[17];
    const float* W2    = (const float*)d_in[18];
    const float* a2    = (const float*)d_in[19];

    float* out        = (float*)d_out;
    float* out2       = out;                          // [1024,600]
    float* out_att    = out + 1024*600;               // [2048,600]
    float* op2        = out + 1024*600 + 2048*600;    // [1024,100]
    float* output_att = op2 + 1024*100;               // [2048,100]

    cudaFuncSetAttribute(proj_kernel, cudaFuncAttributeMaxDynamicSharedMemorySize, PROJ_SMEM);
    cudaFuncSetAttribute(lstm_kernel, cudaFuncAttributeMaxDynamicSharedMemorySize, LSTM_SMEM);
    cudaFuncSetAttribute(gat1_att,    cudaFuncAttributeMaxDynamicSharedMemorySize, GAT1_SMEM);
    cudaFuncSetAttribute(gat2_kernel, cudaFuncAttributeMaxDynamicSharedMemorySize, GAT2_SMEM);

    dim3 pg((N_ENT+63)/64, 6);
    proj_kernel<<<pg, 256, PROJ_SMEM>>>(ent, rel, ent1, rel1, Wih_f, Wih_b, Wih_p);

    lstm_kernel<<<M_TOTAL/64, 256, LSTM_SMEM>>>(bh, br, bt,
                                                Whh_f, Whh_b, Whh_p,
                                                b_f, b_b, b_p);

    dim3 gg(M_TOTAL/64, 10);
    gat1_gemm<<<gg, 256>>>(W1);

    gat1_att<<<NGROUP, 256, GAT1_SMEM>>>(a1, out_att, out2);

    gat2_kernel<<<NGROUP, 256, GAT2_SMEM>>>(W2, a2, output_att, op2);

    (void)in_sizes; (void)n_in; (void)out_size;
}

// round 2
// speedup vs baseline: 1.7334x; 1.7334x over previous
#include <cuda_runtime.h>
#include <math.h>

#define M_TOTAL 81920
#define NGROUP  2048
#define NENT    14541
#define NRELS   237

// ---------------- scratch (device globals: no allocation allowed) ----------
__device__ float g_Pe[3][NENT*400];     // Wih_l @ ent-emb   (per vocab entity)
__device__ float g_Pr[3][NRELS*400];    // Wih_l @ rel-emb
__device__ float g_h1c1[3][NENT*200];   // step-1 h (0..99) and c (100..199) per entity
__device__ float g_R1[3][NENT*400];     // Whh_l @ h1        (per vocab entity)
__device__ float g_out[(size_t)M_TOTAL*600];
__device__ float g_hG [(size_t)M_TOTAL*600];
__device__ float g_op [(size_t)M_TOTAL*100];

__device__ __forceinline__ float sigmoidf_(float x){
    return __fdividef(1.f, 1.f + __expf(-x));
}
__device__ __forceinline__ float tanhf_(float x){
    float xc = fminf(fmaxf(x,-15.f),15.f);
    float e = __expf(2.f*xc);
    return __fdividef(e-1.f, e+1.f);
}

// ---------------------------------------------------------------------------
// K0: vocab-level GEMMs.  P[r][g] = sum_k X[r][k] * W[g*100+k]
// phase 0 (grid.y 0..5): input-projection tables  Wih @ emb
// phase 1 (grid.y 0..2): recurrent tables         Whh @ h1
// ---------------------------------------------------------------------------
#define PROJ_SMEM ((64*101 + 400*100)*4)
__global__ void __launch_bounds__(256,1) proj_kernel(int phase,
    const float* __restrict__ ent,  const float* __restrict__ rel,
    const float* __restrict__ ent1, const float* __restrict__ rel1,
    const float* __restrict__ Wf,   const float* __restrict__ Wb,
    const float* __restrict__ Wp,
    const float* __restrict__ Whf,  const float* __restrict__ Whb,
    const float* __restrict__ Whp)
{
    const float* X; const float* W; float* P; int nrows; int xs;
    if (phase == 0){
        xs = 100;
        switch (blockIdx.y){
          case 0:  X=ent;  W=Wf; P=g_Pe[0]; nrows=NENT;  break;
          case 1:  X=rel;  W=Wf; P=g_Pr[0]; nrows=NRELS; break;
          case 2:  X=ent;  W=Wb; P=g_Pe[1]; nrows=NENT;  break;
          case 3:  X=rel;  W=Wb; P=g_Pr[1]; nrows=NRELS; break;
          case 4:  X=ent1; W=Wp; P=g_Pe[2]; nrows=NENT;  break;
          default: X=rel1; W=Wp; P=g_Pr[2]; nrows=NRELS; break;
        }
    } else {
        xs = 200; nrows = NENT;
        switch (blockIdx.y){
          case 0:  X=g_h1c1[0]; W=Whf; P=g_R1[0]; break;
          case 1:  X=g_h1c1[1]; W=Whb; P=g_R1[1]; break;
          default: X=g_h1c1[2]; W=Whp; P=g_R1[2]; break;
        }
    }
    int r0 = blockIdx.x*64;
    if (r0 >= nrows) return;
    extern __shared__ float sm[];
    float* esm = sm;            // 64 x 101
    float* wsm = sm + 64*101;   // 400 x 100
    int tid = threadIdx.x;
    for (int i=tid;i<40000;i+=256) wsm[i]=W[i];
    for (int i=tid;i<6400;i+=256){
        int r=i/100, k=i-r*100;
        esm[r*101+k] = (r0+r < nrows) ? X[(size_t)(r0+r)*xs+k] : 0.f;
    }
    __syncthreads();
    int warp=tid>>5, lane=tid&31;
    int gb = warp*50;
    float acc0[50], acc1[50];
    #pragma unroll
    for (int g=0;g<50;g++){ acc0[g]=0.f; acc1[g]=0.f; }
    #pragma unroll 1
    for (int k=0;k<100;k++){
        float x0 = esm[lane*101+k];
        float x1 = esm[(lane+32)*101+k];
        const float* wp = wsm + gb*100 + k;
        #pragma unroll
        for (int g=0;g<50;g++){
            float w = wp[g*100];
            acc0[g]=fmaf(w,x0,acc0[g]);
            acc1[g]=fmaf(w,x1,acc1[g]);
        }
    }
    int e0=r0+lane, e1=e0+32;
    if (e0<nrows){
        float* p=P+(size_t)e0*400+gb;
        #pragma unroll
        for (int g=0;g<50;g++) p[g]=acc0[g];
    }
    if (e1<nrows){
        float* p=P+(size_t)e1*400+gb;
        #pragma unroll
        for (int g=0;g<50;g++) p[g]=acc1[g];
    }
}

// ---------------------------------------------------------------------------
// K0b: per-entity step-1 LSTM cell (h=c=0): c1 = sig(i)tanh(g), h1 = sig(o)tanh(c1)
// ---------------------------------------------------------------------------
__global__ void step1_kernel(const float* __restrict__ b_f,
                             const float* __restrict__ b_b,
                             const float* __restrict__ b_p)
{
    int idx = blockIdx.x*256 + threadIdx.x;
    if (idx >= 3*NENT*100) return;
    int l   = idx / (NENT*100);
    int rem = idx - l*(NENT*100);
    int e = rem/100, j = rem - e*100;
    const float* P = g_Pe[l] + (size_t)e*400;
    const float* b = (l==0)? b_f : (l==1)? b_b : b_p;
    float iv = P[j]     + b[j];
    float gv = P[200+j] + b[200+j];
    float ov = P[300+j] + b[300+j];
    float c1 = sigmoidf_(iv) * tanhf_(gv);
    float h1 = sigmoidf_(ov) * tanhf_(c1);
    g_h1c1[l][(size_t)e*200 + j]       = h1;
    g_h1c1[l][(size_t)e*200 + 100 + j] = c1;
}

// ---------------------------------------------------------------------------
// K1: per-row LSTM steps. Step1/2 are pure gathers + cells (vocab tables);
// only the step-3 recurrence h2@Whh^T is a per-row matmul (1 per LSTM).
// ---------------------------------------------------------------------------
#define LSTM_SMEM ((64*405 + 64*101 + 400*50)*4)
__global__ void __launch_bounds__(256,1) lstm_kernel(
    const int* __restrict__ bh, const int* __restrict__ br, const int* __restrict__ bt,
    const float* __restrict__ Whh_f, const float* __restrict__ Whh_b, const float* __restrict__ Whh_p,
    const float* __restrict__ b_f,   const float* __restrict__ b_b,   const float* __restrict__ b_p)
{
    extern __shared__ float sm[];
    float* gates = sm;                 // 64*405 (odd pitch)
    float* hsm   = gates + 64*405;     // 64*101
    float* wc    = hsm   + 64*101;     // 400*50
    __shared__ int ih[64], ir[64], it[64];

    int tid=threadIdx.x, warp=tid>>5, lane=tid&31;
    int row0=blockIdx.x*64;
    if (tid<64)        ih[tid]     = bh[row0+tid];
    else if (tid<128)  ir[tid-64]  = br[row0+tid-64];
    else if (tid<192)  it[tid-128] = bt[row0+tid-128];
    __syncthreads();

    for (int l=0;l<3;l++){
        const float* Pe  = g_Pe[l];
        const float* Pr  = g_Pr[l];
        const float* R1  = g_R1[l];
        const float* HC  = g_h1c1[l];
        const float* Whh = (l==0)?Whh_f:(l==1)?Whh_b:Whh_p;
        const float* bias= (l==0)?b_f  :(l==1)?b_b  :b_p;

        float creg[25];
        // ---- step1 (precomputed) + step2 (gather + cell) ----
        #pragma unroll
        for (int i=0;i<25;i++){
            int e=tid+i*256; int row=e/100; int j=e-row*100;
            int fi = (l==1)? it[row] : ih[row];
            size_t grow=(size_t)(row0+row);
            float h1 = HC[(size_t)fi*200 + j];
            float c1 = HC[(size_t)fi*200 + 100 + j];
            if (l==0)      g_out[grow*600 + j]       = h1;
            else if (l==1) g_out[grow*600 + 500 + j] = h1;
            const float* pr = Pr + (size_t)ir[row]*400;
            const float* r1 = R1 + (size_t)fi*400;
            float iv = pr[j]     + r1[j]     + bias[j];
            float fv = pr[100+j] + r1[100+j] + bias[100+j];
            float gv = pr[200+j] + r1[200+j] + bias[200+j];
            float ov = pr[300+j] + r1[300+j] + bias[300+j];
            float c2 = sigmoidf_(fv)*c1 + sigmoidf_(iv)*tanhf_(gv);
            float h2 = sigmoidf_(ov)*tanhf_(c2);
            creg[i] = c2;
            hsm[row*101+j] = h2;
            if (l==0)      g_out[grow*600 + 200 + j] = h2;
            else if (l==1) g_out[grow*600 + 300 + j] = h2;
        }
        __syncthreads();

        // ---- step3: gather input projections into gates ----
        for (int r=warp;r<64;r+=8){
            int li = (l==1)? ih[r] : it[r];
            const float* src = Pe + (size_t)li*400;
            float* dst = gates + r*405;
            for (int k=lane;k<400;k+=32) dst[k]=src[k];
        }
        __syncthreads();

        // ---- step3 recurrent matmul: gates += h2 @ Whh^T ----
        int gb = warp*50;
        float acc0[50], acc1[50];
        #pragma unroll
        for (int g=0;g<50;g++){
            acc0[g]=gates[lane*405+gb+g];
            acc1[g]=gates[(lane+32)*405+gb+g];
        }
        for (int kc=0;kc<100;kc+=50){
            __syncthreads();
            for (int i2=tid;i2<20000;i2+=256){
                int g=i2/50, kk=i2-g*50;
                wc[i2]=Whh[g*100+kc+kk];
            }
            __syncthreads();
            #pragma unroll 1
            for (int kk=0;kk<50;kk++){
                float x0=hsm[lane*101+kc+kk];
                float x1=hsm[(lane+32)*101+kc+kk];
                const float* wr = wc + gb*50 + kk;
                #pragma unroll
                for (int g=0;g<50;g++){
                    float w = wr[g*50];
                    acc0[g]=fmaf(w,x0,acc0[g]);
                    acc1[g]=fmaf(w,x1,acc1[g]);
                }
            }
        }
        __syncthreads();
        #pragma unroll
        for (int g=0;g<50;g++){
            gates[lane*405+gb+g]     =acc0[g];
            gates[(lane+32)*405+gb+g]=acc1[g];
        }
        __syncthreads();

        // ---- step3 cell ----
        #pragma unroll
        for (int i=0;i<25;i++){
            int e=tid+i*256; int row=e/100; int j=e-row*100;
            const float* gr = gates + row*405;
            float iv=gr[j]+bias[j],      fv=gr[100+j]+bias[100+j];
            float gv=gr[200+j]+bias[200+j], ov=gr[300+j]+bias[300+j];
            float c3 = sigmoidf_(fv)*creg[i] + sigmoidf_(iv)*tanhf_(gv);
            float h3 = sigmoidf_(ov)*tanhf_(c3);
            size_t grow=(size_t)(row0+row);
            if (l==0)      g_out[grow*600 + 400 + j]=h3;
            else if (l==1) g_out[grow*600 + 100 + j]=h3;
            else           g_op [grow*100 + j]      =h3;
        }
        __syncthreads();
    }
}

// ---------------------------------------------------------------------------
// K2: GAT1 GEMM  g_hG = g_out[81920,600] @ W1[600,600]
// 128x128 tile, 256 threads, 8x8 micro (4+4 split), kc=24, all LDS vectorized.
// ---------------------------------------------------------------------------
__global__ void __launch_bounds__(256,1) gat1_gemm(const float* __restrict__ W1)
{
    __shared__ __align__(16) float As[24][132];   // A^T: As[kk][row]
    __shared__ __align__(16) float Bs[24][132];   // Bs[kk][col]
    int tid=threadIdx.x;
    int tx=tid&15, ty=tid>>4;
    int col0=blockIdx.x*128, row0=blockIdx.y*128;
    float acc[8][8];
    #pragma unroll
    for (int i=0;i<8;i++)
        #pragma unroll
        for (int j=0;j<8;j++) acc[i][j]=0.f;

    for (int k0=0;k0<600;k0+=24){
        // A: 128 rows x 24 k, transpose into As
        #pragma unroll
        for (int u=0;u<3;u++){
            int idx=tid+u*256; int r=idx/6; int kq=idx-r*6;
            float4 v = *(const float4*)(g_out + (size_t)(row0+r)*600 + k0 + kq*4);
            As[kq*4+0][r]=v.x; As[kq*4+1][r]=v.y;
            As[kq*4+2][r]=v.z; As[kq*4+3][r]=v.w;
        }
        // B: 24 k x 128 cols
        #pragma unroll
        for (int u=0;u<3;u++){
            int idx=tid+u*256; int kk=idx/32; int cq=idx-kk*32;
            int c=col0+cq*4;
            float4 v = make_float4(0.f,0.f,0.f,0.f);
            if (c < 600) v = *(const float4*)(W1 + (size_t)(k0+kk)*600 + c);
            *(float4*)&Bs[kk][cq*4] = v;
        }
        __syncthreads();
        #pragma unroll
        for (int kk=0;kk<24;kk++){
            float4 a0 = *(const float4*)&As[kk][ty*4];
            float4 a1 = *(const float4*)&As[kk][64+ty*4];
            float4 b0 = *(const float4*)&Bs[kk][tx*4];
            float4 b1 = *(const float4*)&Bs[kk][64+tx*4];
            float av[8]={a0.x,a0.y,a0.z,a0.w,a1.x,a1.y,a1.z,a1.w};
            float bv[8]={b0.x,b0.y,b0.z,b0.w,b1.x,b1.y,b1.z,b1.w};
            #pragma unroll
            for (int i=0;i<8;i++)
                #pragma unroll
                for (int j=0;j<8;j++) acc[i][j]=fmaf(av[i],bv[j],acc[i][j]);
        }
        __syncthreads();
    }
    #pragma unroll
    for (int hi=0;hi<2;hi++)
        #pragma unroll
        for (int i=0;i<4;i++){
            size_t r = (size_t)(row0 + hi*64 + ty*4 + i);
            #pragma unroll
            for (int hj=0;hj<2;hj++){
                int c = col0 + hj*64 + tx*4;
                if (c < 600){
                    int ri=hi*4+i, cj=hj*4;
                    float4 v = make_float4(acc[ri][cj],acc[ri][cj+1],acc[ri][cj+2],acc[ri][cj+3]);
                    *(float4*)(g_hG + r*600 + c) = v;
                }
            }
        }
}

// ---------------------------------------------------------------------------
// K3: GAT1 attention per group of 40 rows, streaming from L2 (tiny smem).
// ---------------------------------------------------------------------------
__global__ void __launch_bounds__(256,1) gat1_att(
    const float* __restrict__ a1, float* __restrict__ out_att, float* __restrict__ out2)
{
    __shared__ __align__(16) float a1s[1200];
    __shared__ float ebuf[41];
    __shared__ float att[40];
    __shared__ float red[2];
    int b=blockIdx.x, tid=threadIdx.x, warp=tid>>5, lane=tid&31;
    for (int i=tid;i<1200;i+=256) a1s[i]=a1[i];
    __syncthreads();
    const float* base = g_hG + (size_t)b*24000;
    for (int t=warp;t<41;t+=8){
        const float* rowp = (t<40)? base + t*600 : base;
        const float* av   = (t<40)? a1s         : a1s+600;
        float s=0.f;
        for (int kk=lane;kk<150;kk+=32){
            float4 r4 = *(const float4*)(rowp + kk*4);
            float4 a4 = *(const float4*)(av   + kk*4);
            s += r4.x*a4.x + r4.y*a4.y + r4.z*a4.z + r4.w*a4.w;
        }
        #pragma unroll
        for (int o=16;o;o>>=1) s += __shfl_xor_sync(0xffffffffu, s, o);
        if (lane==0) ebuf[t]=s;
    }
    __syncthreads();
    if (tid<40){
        float x = ebuf[tid] + ebuf[40];
        ebuf[tid] = (x>0.f)? x : 0.2f*x;
    }
    __syncthreads();
    if (tid<32){
        float v = ebuf[tid];
        if (tid<8) v = fmaxf(v, ebuf[tid+32]);
        #pragma unroll
        for (int o=16;o;o>>=1) v = fmaxf(v, __shfl_xor_sync(0xffffffffu, v, o));
        if (tid==0) red[0]=v;
    }
    __syncthreads();
    if (tid<40) att[tid]=__expf(ebuf[tid]-red[0]);
    __syncthreads();
    if (tid<32){
        float v = att[tid] + ((tid<8)? att[tid+32] : 0.f);
        #pragma unroll
        for (int o=16;o;o>>=1) v += __shfl_xor_sync(0xffffffffu, v, o);
        if (tid==0) red[1]=1.f/v;
    }
    __syncthreads();
    if (tid<40) att[tid]=fmaxf(att[tid]*red[1]-0.001f, 0.f);
    __syncthreads();
    for (int f=tid; f<600; f+=256){
        float acc=0.f;
        #pragma unroll 8
        for (int n=0;n<40;n++) acc += att[n]*base[n*600+f];
        out_att[(size_t)b*600+f]=acc;
    }
    if ((b&1)==0){
        const float* srow = g_out + (size_t)b*40*600;
        float* drow = out2 + (size_t)(b>>1)*600;
        for (int f=tid;f<600;f+=256) drow[f]=srow[f];
    }
}

// ---------------------------------------------------------------------------
// K4: GAT2 fused per group (proj [40,100]@[100,100] + attention)
// ---------------------------------------------------------------------------
#define GAT2_SMEM ((4000 + 10000 + 4000)*4)
__global__ void __launch_bounds__(256,1) gat2_kernel(
    const float* __restrict__ W2, const float* __restrict__ a2,
    float* __restrict__ output_att, float* __restrict__ op2)
{
    extern __shared__ float sm[];
    float* ops = sm;            // 40*100
    float* Ws  = ops + 4000;    // 100*100
    float* hg  = Ws  + 10000;   // 40*100
    __shared__ float a2s[200];
    __shared__ float ebuf[41];
    __shared__ float att[40];
    __shared__ float red[2];
    int b=blockIdx.x, tid=threadIdx.x, warp=tid>>5, lane=tid&31;
    const float* src = g_op + (size_t)b*4000;
    for (int i=tid;i<4000;i+=256)  ops[i]=src[i];
    for (int i=tid;i<10000;i+=256) Ws[i]=W2[i];
    if (tid<200) a2s[tid]=a2[tid];
    __syncthreads();
    for (int i=tid;i<4000;i+=256){
        int n=i/100, o=i-n*100;
        float acc=0.f;
        #pragma unroll 4
        for (int k=0;k<100;k++) acc=fmaf(ops[n*100+k], Ws[k*100+o], acc);
        hg[i]=acc;
    }
    __syncthreads();
    for (int t=warp;t<41;t+=8){
        const float* rowp = (t<40)? hg + t*100 : hg;
        const float* av   = (t<40)? a2s        : a2s+100;
        float s=0.f;
        for (int k=lane;k<100;k+=32) s += rowp[k]*av[k];
        #pragma unroll
        for (int o=16;o;o>>=1) s += __shfl_xor_sync(0xffffffffu, s, o);
        if (lane==0) ebuf[t]=s;
    }
    __syncthreads();
    if (tid<40){
        float x = ebuf[tid] + ebuf[40];
        ebuf[tid] = (x>0.f)? x : 0.2f*x;
    }
    __syncthreads();
    if (tid<32){
        float v = ebuf[tid];
        if (tid<8) v = fmaxf(v, ebuf[tid+32]);
        #pragma unroll
        for (int o=16;o;o>>=1) v = fmaxf(v, __shfl_xor_sync(0xffffffffu, v, o));
        if (tid==0) red[0]=v;
    }
    __syncthreads();
    if (tid<40) att[tid]=__expf(ebuf[tid]-red[0]);
    __syncthreads();
    if (tid<32){
        float v = att[tid] + ((tid<8)? att[tid+32] : 0.f);
        #pragma unroll
        for (int o=16;o;o>>=1) v += __shfl_xor_sync(0xffffffffu, v, o);
        if (tid==0) red[1]=1.f/v;
    }
    __syncthreads();
    if (tid<40) att[tid]=fmaxf(att[tid]*red[1]-0.001f, 0.f);
    __syncthreads();
    if (tid<100){
        float acc=0.f;
        #pragma unroll 8
        for (int n=0;n<40;n++) acc += att[n]*hg[n*100+tid];
        output_att[(size_t)b*100+tid]=acc;
    }
    if ((b&1)==0){
        const float* srow = g_op + (size_t)b*40*100;
        float* drow = op2 + (size_t)(b>>1)*100;
        if (tid<100) drow[tid]=srow[tid];
    }
}

// ---------------------------------------------------------------------------
extern "C" void kernel_launch(void* const* d_in, const int* in_sizes, int n_in,
                              void* d_out, int out_size)
{
    const int*   bh    = (const int*)  d_in[0];
    const int*   br    = (const int*)  d_in[1];
    const int*   bt    = (const int*)  d_in[2];
    const float* ent   = (const float*)d_in[3];
    const float* rel   = (const float*)d_in[4];
    const float* ent1  = (const float*)d_in[5];
    const float* rel1  = (const float*)d_in[6];
    const float* Wih_f = (const float*)d_in[7];
    const float* Whh_f = (const float*)d_in[8];
    const float* b_f   = (const float*)d_in[9];
    const float* Wih_b = (const float*)d_in[10];
    const float* Whh_b = (const float*)d_in[11];
    const float* b_b   = (const float*)d_in[12];
    const float* Wih_p = (const float*)d_in[13];
    const float* Whh_p = (const float*)d_in[14];
    const float* b_p   = (const float*)d_in[15];
    const float* W1    = (const float*)d_in[16];
    const float* a1    = (const float*)d_in[17];
    const float* W2    = (const float*)d_in[18];
    const float* a2    = (const float*)d_in[19];

    float* out        = (float*)d_out;
    float* out2       = out;                          // [1024,600]
    float* out_att    = out + 1024*600;               // [2048,600]
    float* op2        = out + 1024*600 + 2048*600;    // [1024,100]
    float* output_att = op2 + 1024*100;               // [2048,100]

    cudaFuncSetAttribute(proj_kernel, cudaFuncAttributeMaxDynamicSharedMemorySize, PROJ_SMEM);
    cudaFuncSetAttribute(lstm_kernel, cudaFuncAttributeMaxDynamicSharedMemorySize, LSTM_SMEM);
    cudaFuncSetAttribute(gat2_kernel, cudaFuncAttributeMaxDynamicSharedMemorySize, GAT2_SMEM);

    dim3 pg0((NENT+63)/64, 6);
    proj_kernel<<<pg0, 256, PROJ_SMEM>>>(0, ent, rel, ent1, rel1,
                                         Wih_f, Wih_b, Wih_p, Whh_f, Whh_b, Whh_p);

    int s1blocks = (3*NENT*100 + 255)/256;
    step1_kernel<<<s1blocks, 256>>>(b_f, b_b, b_p);

    dim3 pg1((NENT+63)/64, 3);
    proj_kernel<<<pg1, 256, PROJ_SMEM>>>(1, ent, rel, ent1, rel1,
                                         Wih_f, Wih_b, Wih_p, Whh_f, Whh_b, Whh_p);

    lstm_kernel<<<M_TOTAL/64, 256, LSTM_SMEM>>>(bh, br, bt,
                                                Whh_f, Whh_b, Whh_p,
                                                b_f, b_b, b_p);

    dim3 gg(5, M_TOTAL/128);
    gat1_gemm<<<gg, 256>>>(W1);

    gat1_att<<<NGROUP, 256>>>(a1, out_att, out2);

    gat2_kernel<<<NGROUP, 256, GAT2_SMEM>>>(W2, a2, output_att, op2);

    (void)in_sizes; (void)n_in; (void)out_size;
}

// round 3
// speedup vs baseline: 2.7467x; 1.5846x over previous
#include <cuda_runtime.h>
#include <math.h>

#define M_TOTAL 81920
#define NGROUP  2048
#define NENT    14541
#define NRELS   237

typedef unsigned long long u64t;

// ---------------- scratch (device globals: no allocation allowed) ----------
__device__ float g_Pe[3][NENT*400];     // Wih_l @ ent-emb   (per vocab entity)
__device__ float g_Pr[3][NRELS*400];    // Wih_l @ rel-emb
__device__ float g_h1c1[3][NENT*200];   // step-1 h (0..99) and c (100..199)
__device__ float g_R1[3][NENT*400];     // Whh_l @ h1        (per vocab entity)
__device__ float g_h2[(size_t)3*M_TOTAL*100];
__device__ float g_c2[(size_t)3*M_TOTAL*100];
__device__ float g_R2[(size_t)3*M_TOTAL*400];
__device__ float g_out[(size_t)M_TOTAL*600];
__device__ float g_hG [(size_t)M_TOTAL*600];
__device__ float g_op [(size_t)M_TOTAL*100];

__device__ __forceinline__ float sigmoidf_(float x){
    return __fdividef(1.f, 1.f + __expf(-x));
}
__device__ __forceinline__ float tanhf_(float x){
    float xc = fminf(fmaxf(x,-15.f),15.f);
    float e = __expf(2.f*xc);
    return __fdividef(e-1.f, e+1.f);
}
__device__ __forceinline__ u64t ffma2(u64t a, u64t b, u64t c){
    u64t d;
    asm("fma.rn.f32x2 %0, %1, %2, %3;" : "=l"(d) : "l"(a), "l"(b), "l"(c));
    return d;
}
__device__ __forceinline__ void lds2(u64t &x, u64t &y, unsigned addr){
    asm volatile("ld.shared.v2.u64 {%0,%1}, [%2];" : "=l"(x), "=l"(y) : "r"(addr));
}

// ---------------------------------------------------------------------------
// K0: vocab-level GEMMs.  P[r][g] = sum_k X[r][k] * W[g*100+k]
// ---------------------------------------------------------------------------
#define PROJ_SMEM ((64*101 + 400*100)*4)
__global__ void __launch_bounds__(256,1) proj_kernel(int phase,
    const float* __restrict__ ent,  const float* __restrict__ rel,
    const float* __restrict__ ent1, const float* __restrict__ rel1,
    const float* __restrict__ Wf,   const float* __restrict__ Wb,
    const float* __restrict__ Wp,
    const float* __restrict__ Whf,  const float* __restrict__ Whb,
    const float* __restrict__ Whp)
{
    const float* X; const float* W; float* P; int nrows; int xs;
    if (phase == 0){
        xs = 100;
        switch (blockIdx.y){
          case 0:  X=ent;  W=Wf; P=g_Pe[0]; nrows=NENT;  break;
          case 1:  X=rel;  W=Wf; P=g_Pr[0]; nrows=NRELS; break;
          case 2:  X=ent;  W=Wb; P=g_Pe[1]; nrows=NENT;  break;
          case 3:  X=rel;  W=Wb; P=g_Pr[1]; nrows=NRELS; break;
          case 4:  X=ent1; W=Wp; P=g_Pe[2]; nrows=NENT;  break;
          default: X=rel1; W=Wp; P=g_Pr[2]; nrows=NRELS; break;
        }
    } else {
        xs = 200; nrows = NENT;
        switch (blockIdx.y){
          case 0:  X=g_h1c1[0]; W=Whf; P=g_R1[0]; break;
          case 1:  X=g_h1c1[1]; W=Whb; P=g_R1[1]; break;
          default: X=g_h1c1[2]; W=Whp; P=g_R1[2]; break;
        }
    }
    int r0 = blockIdx.x*64;
    if (r0 >= nrows) return;
    extern __shared__ float sm[];
    float* esm = sm;            // 64 x 101
    float* wsm = sm + 64*101;   // 400 x 100
    int tid = threadIdx.x;
    for (int i=tid;i<40000;i+=256) wsm[i]=W[i];
    for (int i=tid;i<6400;i+=256){
        int r=i/100, k=i-r*100;
        esm[r*101+k] = (r0+r < nrows) ? X[(size_t)(r0+r)*xs+k] : 0.f;
    }
    __syncthreads();
    int warp=tid>>5, lane=tid&31;
    int gb = warp*50;
    float acc0[50], acc1[50];
    #pragma unroll
    for (int g=0;g<50;g++){ acc0[g]=0.f; acc1[g]=0.f; }
    #pragma unroll 1
    for (int k=0;k<100;k++){
        float x0 = esm[lane*101+k];
        float x1 = esm[(lane+32)*101+k];
        const float* wp = wsm + gb*100 + k;
        #pragma unroll
        for (int g=0;g<50;g++){
            float w = wp[g*100];
            acc0[g]=fmaf(w,x0,acc0[g]);
            acc1[g]=fmaf(w,x1,acc1[g]);
        }
    }
    int e0=r0+lane, e1=e0+32;
    if (e0<nrows){
        float* p=P+(size_t)e0*400+gb;
        #pragma unroll
        for (int g=0;g<50;g++) p[g]=acc0[g];
    }
    if (e1<nrows){
        float* p=P+(size_t)e1*400+gb;
        #pragma unroll
        for (int g=0;g<50;g++) p[g]=acc1[g];
    }
}

// ---------------------------------------------------------------------------
// K0b: per-entity step-1 LSTM cell
// ---------------------------------------------------------------------------
__global__ void step1_kernel(const float* __restrict__ b_f,
                             const float* __restrict__ b_b,
                             const float* __restrict__ b_p)
{
    int idx = blockIdx.x*256 + threadIdx.x;
    if (idx >= 3*NENT*100) return;
    int l   = idx / (NENT*100);
    int rem = idx - l*(NENT*100);
    int e = rem/100, j = rem - e*100;
    const float* P = g_Pe[l] + (size_t)e*400;
    const float* b = (l==0)? b_f : (l==1)? b_b : b_p;
    float iv = P[j]     + b[j];
    float gv = P[200+j] + b[200+j];
    float ov = P[300+j] + b[300+j];
    float c1 = sigmoidf_(iv) * tanhf_(gv);
    float h1 = sigmoidf_(ov) * tanhf_(c1);
    g_h1c1[l][(size_t)e*200 + j]       = h1;
    g_h1c1[l][(size_t)e*200 + 100 + j] = c1;
}

// ---------------------------------------------------------------------------
// K1a: step1 gather + step2 cell (elementwise). Produces h2,c2 per row per l.
// ---------------------------------------------------------------------------
__global__ void __launch_bounds__(256,4) step12_kernel(
    const int* __restrict__ bh, const int* __restrict__ br, const int* __restrict__ bt,
    const float* __restrict__ b_f, const float* __restrict__ b_b, const float* __restrict__ b_p)
{
    __shared__ int ih[64], ir[64], it[64];
    int tid=threadIdx.x; int row0=blockIdx.x*64;
    if (tid<64)        ih[tid]     = bh[row0+tid];
    else if (tid<128)  ir[tid-64]  = br[row0+tid-64];
    else if (tid<192)  it[tid-128] = bt[row0+tid-128];
    __syncthreads();
    for (int l=0;l<3;l++){
        const float* Pr  = g_Pr[l];
        const float* R1  = g_R1[l];
        const float* HC  = g_h1c1[l];
        const float* bias= (l==0)?b_f:(l==1)?b_b:b_p;
        #pragma unroll
        for (int i=0;i<25;i++){
            int e=tid+i*256; int row=e/100, j=e-row*100;
            int fi = (l==1)? it[row] : ih[row];
            size_t grow=(size_t)(row0+row);
            float h1 = HC[(size_t)fi*200 + j];
            float c1 = HC[(size_t)fi*200 + 100 + j];
            if (l==0)      g_out[grow*600 + j]       = h1;
            else if (l==1) g_out[grow*600 + 500 + j] = h1;
            const float* pr = Pr + (size_t)ir[row]*400;
            const float* r1 = R1 + (size_t)fi*400;
            float iv = pr[j]     + r1[j]     + bias[j];
            float fv = pr[100+j] + r1[100+j] + bias[100+j];
            float gv = pr[200+j] + r1[200+j] + bias[200+j];
            float ov = pr[300+j] + r1[300+j] + bias[300+j];
            float c2 = sigmoidf_(fv)*c1 + sigmoidf_(iv)*tanhf_(gv);
            float h2 = sigmoidf_(ov)*tanhf_(c2);
            g_h2[(size_t)l*M_TOTAL*100 + grow*100 + j] = h2;
            g_c2[(size_t)l*M_TOTAL*100 + grow*100 + j] = c2;
            if (l==0)      g_out[grow*600 + 200 + j] = h2;
            else if (l==1) g_out[grow*600 + 300 + j] = h2;
        }
    }
}

// ---------------------------------------------------------------------------
// K2: unified f32x2 GEMM, 128x128 tile, 256 threads, KC=20.
// which==0: g_hG = g_out[81920,600] @ W1[600,600]           (B row-major)
// which==1: g_R2[l] = g_h2[l][81920,100] @ Whh_l^T[100,400] (B transposed)
// ---------------------------------------------------------------------------
__global__ void __launch_bounds__(256,2) gemm_f32x2(int which,
    const float* __restrict__ W1,
    const float* __restrict__ Whf, const float* __restrict__ Whb,
    const float* __restrict__ Whp)
{
    __shared__ float2 As2[20*128];   // duplicated {a,a}, [kk][row]
    __shared__ float  Bs [20*128];   // [kk][col]

    const float* A; const float* Bm; float* Cp; int N, K, tb;
    if (which == 0){ A=g_out; Bm=W1; Cp=g_hG; N=600; K=600; tb=0; }
    else {
        int l = blockIdx.z;
        A  = g_h2 + (size_t)l*M_TOTAL*100;
        Bm = (l==0)? Whf : (l==1)? Whb : Whp;
        Cp = g_R2 + (size_t)l*M_TOTAL*400;
        N=400; K=100; tb=1;
    }
    int tid=threadIdx.x, tx=tid&15, ty=tid>>4;
    int col0=blockIdx.x*128, row0=blockIdx.y*128;

    u64t acc[8][4];
    #pragma unroll
    for (int i=0;i<8;i++)
        #pragma unroll
        for (int j=0;j<4;j++) acc[i][j]=0ULL;

    unsigned asb = (unsigned)__cvta_generic_to_shared(As2) + ty*32;
    unsigned bsb = (unsigned)__cvta_generic_to_shared(Bs)  + tx*16;

    for (int k0=0;k0<K;k0+=20){
        // stage A: 128 rows x 20 k, transposed + duplicated
        #pragma unroll
        for (int u=0;u<3;u++){
            int idx=tid+u*256;
            if (idx<640){
                int r=idx/5, kq=idx-r*5;
                float4 v = *(const float4*)(A + (size_t)(row0+r)*K + k0 + kq*4);
                As2[(kq*4+0)*128 + r] = make_float2(v.x, v.x);
                As2[(kq*4+1)*128 + r] = make_float2(v.y, v.y);
                As2[(kq*4+2)*128 + r] = make_float2(v.z, v.z);
                As2[(kq*4+3)*128 + r] = make_float2(v.w, v.w);
            }
        }
        // stage B
        if (tb == 0){
            #pragma unroll
            for (int u=0;u<3;u++){
                int idx=tid+u*256;
                if (idx<640){
                    int kk=idx/32, cq=idx-kk*32;
                    int c=col0+cq*4;
                    float4 v = make_float4(0.f,0.f,0.f,0.f);
                    if (c < N) v = *(const float4*)(Bm + (size_t)(k0+kk)*N + c);
                    *(float4*)&Bs[kk*128 + cq*4] = v;
                }
            }
        } else {
            for (int i=tid;i<2560;i+=256){
                int n=i/20, kk=i-n*20;
                int g=col0+n;
                Bs[kk*128+n] = (g<N)? Bm[(size_t)g*K + k0+kk] : 0.f;
            }
        }
        __syncthreads();
        #pragma unroll
        for (int kk=0;kk<20;kk++){
            u64t a0,a1,a2,a3,a4,a5,a6,a7,b0,b1,b2,b3;
            unsigned ar = asb + kk*1024;
            unsigned br2= bsb + kk*512;
            lds2(a0,a1, ar);
            lds2(a2,a3, ar+16);
            lds2(a4,a5, ar+512);
            lds2(a6,a7, ar+528);
            lds2(b0,b1, br2);
            lds2(b2,b3, br2+256);
            u64t av[8]={a0,a1,a2,a3,a4,a5,a6,a7};
            u64t bv[4]={b0,b1,b2,b3};
            #pragma unroll
            for (int i=0;i<8;i++)
                #pragma unroll
                for (int j=0;j<4;j++) acc[i][j]=ffma2(av[i],bv[j],acc[i][j]);
        }
        __syncthreads();
    }
    #pragma unroll
    for (int i=0;i<8;i++){
        int row = (i<4)? (ty*4+i) : (64+ty*4+i-4);
        size_t rbase = (size_t)(row0+row)*N;
        #pragma unroll
        for (int j=0;j<4;j++){
            int c = col0 + ((j<2)? (tx*4 + j*2) : (64 + tx*4 + (j-2)*2));
            if (c < N) *(u64t*)(Cp + rbase + c) = acc[i][j];
        }
    }
}

// ---------------------------------------------------------------------------
// K1b: step3 cell (elementwise): gates = Pe[li] + R2 + bias -> h3
// ---------------------------------------------------------------------------
__global__ void __launch_bounds__(256,4) step3_kernel(
    const int* __restrict__ bh, const int* __restrict__ bt,
    const float* __restrict__ b_f, const float* __restrict__ b_b, const float* __restrict__ b_p)
{
    __shared__ int ih[64], it[64];
    int tid=threadIdx.x; int row0=blockIdx.x*64;
    if (tid<64)        ih[tid]    = bh[row0+tid];
    else if (tid<128)  it[tid-64] = bt[row0+tid-64];
    __syncthreads();
    for (int l=0;l<3;l++){
        const float* Pe  = g_Pe[l];
        const float* R2  = g_R2 + (size_t)l*M_TOTAL*400;
        const float* C2  = g_c2 + (size_t)l*M_TOTAL*100;
        const float* bias= (l==0)?b_f:(l==1)?b_b:b_p;
        #pragma unroll
        for (int i=0;i<25;i++){
            int e=tid+i*256; int row=e/100, j=e-row*100;
            int li = (l==1)? ih[row] : it[row];
            size_t grow=(size_t)(row0+row);
            const float* pe = Pe + (size_t)li*400;
            const float* r2 = R2 + grow*400;
            float iv = pe[j]     + r2[j]     + bias[j];
            float fv = pe[100+j] + r2[100+j] + bias[100+j];
            float gv = pe[200+j] + r2[200+j] + bias[200+j];
            float ov = pe[300+j] + r2[300+j] + bias[300+j];
            float c3 = sigmoidf_(fv)*C2[grow*100+j] + sigmoidf_(iv)*tanhf_(gv);
            float h3 = sigmoidf_(ov)*tanhf_(c3);
            if (l==0)      g_out[grow*600 + 400 + j]=h3;
            else if (l==1) g_out[grow*600 + 100 + j]=h3;
            else           g_op [grow*100 + j]      =h3;
        }
    }
}

// ---------------------------------------------------------------------------
// K3: GAT1 attention per group of 40 rows
// ---------------------------------------------------------------------------
__global__ void __launch_bounds__(256,1) gat1_att(
    const float* __restrict__ a1, float* __restrict__ out_att, float* __restrict__ out2)
{
    __shared__ __align__(16) float a1s[1200];
    __shared__ float ebuf[41];
    __shared__ float att[40];
    __shared__ float red[2];
    int b=blockIdx.x, tid=threadIdx.x, warp=tid>>5, lane=tid&31;
    for (int i=tid;i<1200;i+=256) a1s[i]=a1[i];
    __syncthreads();
    const float* base = g_hG + (size_t)b*24000;
    for (int t=warp;t<41;t+=8){
        const float* rowp = (t<40)? base + t*600 : base;
        const float* av   = (t<40)? a1s         : a1s+600;
        float s=0.f;
        for (int kk=lane;kk<150;kk+=32){
            float4 r4 = *(const float4*)(rowp + kk*4);
            float4 a4 = *(const float4*)(av   + kk*4);
            s += r4.x*a4.x + r4.y*a4.y + r4.z*a4.z + r4.w*a4.w;
        }
        #pragma unroll
        for (int o=16;o;o>>=1) s += __shfl_xor_sync(0xffffffffu, s, o);
        if (lane==0) ebuf[t]=s;
    }
    __syncthreads();
    if (tid<40){
        float x = ebuf[tid] + ebuf[40];
        ebuf[tid] = (x>0.f)? x : 0.2f*x;
    }
    __syncthreads();
    if (tid<32){
        float v = ebuf[tid];
        if (tid<8) v = fmaxf(v, ebuf[tid+32]);
        #pragma unroll
        for (int o=16;o;o>>=1) v = fmaxf(v, __shfl_xor_sync(0xffffffffu, v, o));
        if (tid==0) red[0]=v;
    }
    __syncthreads();
    if (tid<40) att[tid]=__expf(ebuf[tid]-red[0]);
    __syncthreads();
    if (tid<32){
        float v = att[tid] + ((tid<8)? att[tid+32] : 0.f);
        #pragma unroll
        for (int o=16;o;o>>=1) v += __shfl_xor_sync(0xffffffffu, v, o);
        if (tid==0) red[1]=1.f/v;
    }
    __syncthreads();
    if (tid<40) att[tid]=fmaxf(att[tid]*red[1]-0.001f, 0.f);
    __syncthreads();
    for (int f=tid; f<600; f+=256){
        float acc=0.f;
        #pragma unroll 8
        for (int n=0;n<40;n++) acc += att[n]*base[n*600+f];
        out_att[(size_t)b*600+f]=acc;
    }
    if ((b&1)==0){
        const float* srow = g_out + (size_t)b*40*600;
        float* drow = out2 + (size_t)(b>>1)*600;
        for (int f=tid;f<600;f+=256) drow[f]=srow[f];
    }
}

// ---------------------------------------------------------------------------
// K4: GAT2 fused per group
// ---------------------------------------------------------------------------
#define GAT2_SMEM ((4000 + 10000 + 4000)*4)
__global__ void __launch_bounds__(256,1) gat2_kernel(
    const float* __restrict__ W2, const float* __restrict__ a2,
    float* __restrict__ output_att, float* __restrict__ op2)
{
    extern __shared__ float sm[];
    float* ops = sm;
    float* Ws  = ops + 4000;
    float* hg  = Ws  + 10000;
    __shared__ float a2s[200];
    __shared__ float ebuf[41];
    __shared__ float att[40];
    __shared__ float red[2];
    int b=blockIdx.x, tid=threadIdx.x, warp=tid>>5, lane=tid&31;
    const float* src = g_op + (size_t)b*4000;
    for (int i=tid;i<4000;i+=256)  ops[i]=src[i];
    for (int i=tid;i<10000;i+=256) Ws[i]=W2[i];
    if (tid<200) a2s[tid]=a2[tid];
    __syncthreads();
    for (int i=tid;i<4000;i+=256){
        int n=i/100, o=i-n*100;
        float acc=0.f;
        #pragma unroll 4
        for (int k=0;k<100;k++) acc=fmaf(ops[n*100+k], Ws[k*100+o], acc);
        hg[i]=acc;
    }
    __syncthreads();
    for (int t=warp;t<41;t+=8){
        const float* rowp = (t<40)? hg + t*100 : hg;
        const float* av   = (t<40)? a2s        : a2s+100;
        float s=0.f;
        for (int k=lane;k<100;k+=32) s += rowp[k]*av[k];
        #pragma unroll
        for (int o=16;o;o>>=1) s += __shfl_xor_sync(0xffffffffu, s, o);
        if (lane==0) ebuf[t]=s;
    }
    __syncthreads();
    if (tid<40){
        float x = ebuf[tid] + ebuf[40];
        ebuf[tid] = (x>0.f)? x : 0.2f*x;
    }
    __syncthreads();
    if (tid<32){
        float v = ebuf[tid];
        if (tid<8) v = fmaxf(v, ebuf[tid+32]);
        #pragma unroll
        for (int o=16;o;o>>=1) v = fmaxf(v, __shfl_xor_sync(0xffffffffu, v, o));
        if (tid==0) red[0]=v;
    }
    __syncthreads();
    if (tid<40) att[tid]=__expf(ebuf[tid]-red[0]);
    __syncthreads();
    if (tid<32){
        float v = att[tid] + ((tid<8)? att[tid+32] : 0.f);
        #pragma unroll
        for (int o=16;o;o>>=1) v += __shfl_xor_sync(0xffffffffu, v, o);
        if (tid==0) red[1]=1.f/v;
    }
    __syncthreads();
    if (tid<40) att[tid]=fmaxf(att[tid]*red[1]-0.001f, 0.f);
    __syncthreads();
    if (tid<100){
        float acc=0.f;
        #pragma unroll 8
        for (int n=0;n<40;n++) acc += att[n]*hg[n*100+tid];
        output_att[(size_t)b*100+tid]=acc;
    }
    if ((b&1)==0){
        const float* srow = g_op + (size_t)b*40*100;
        float* drow = op2 + (size_t)(b>>1)*100;
        if (tid<100) drow[tid]=srow[tid];
    }
}

// ---------------------------------------------------------------------------
extern "C" void kernel_launch(void* const* d_in, const int* in_sizes, int n_in,
                              void* d_out, int out_size)
{
    const int*   bh    = (const int*)  d_in[0];
    const int*   br    = (const int*)  d_in[1];
    const int*   bt    = (const int*)  d_in[2];
    const float* ent   = (const float*)d_in[3];
    const float* rel   = (const float*)d_in[4];
    const float* ent1  = (const float*)d_in[5];
    const float* rel1  = (const float*)d_in[6];
    const float* Wih_f = (const float*)d_in[7];
    const float* Whh_f = (const float*)d_in[8];
    const float* b_f   = (const float*)d_in[9];
    const float* Wih_b = (const float*)d_in[10];
    const float* Whh_b = (const float*)d_in[11];
    const float* b_b   = (const float*)d_in[12];
    const float* Wih_p = (const float*)d_in[13];
    const float* Whh_p = (const float*)d_in[14];
    const float* b_p   = (const float*)d_in[15];
    const float* W1    = (const float*)d_in[16];
    const float* a1    = (const float*)d_in[17];
    const float* W2    = (const float*)d_in[18];
    const float* a2    = (const float*)d_in[19];

    float* out        = (float*)d_out;
    float* out2       = out;                          // [1024,600]
    float* out_att    = out + 1024*600;               // [2048,600]
    float* op2        = out + 1024*600 + 2048*600;    // [1024,100]
    float* output_att = op2 + 1024*100;               // [2048,100]

    cudaFuncSetAttribute(proj_kernel, cudaFuncAttributeMaxDynamicSharedMemorySize, PROJ_SMEM);
    cudaFuncSetAttribute(gat2_kernel, cudaFuncAttributeMaxDynamicSharedMemorySize, GAT2_SMEM);

    dim3 pg0((NENT+63)/64, 6);
    proj_kernel<<<pg0, 256, PROJ_SMEM>>>(0, ent, rel, ent1, rel1,
                                         Wih_f, Wih_b, Wih_p, Whh_f, Whh_b, Whh_p);

    int s1blocks = (3*NENT*100 + 255)/256;
    step1_kernel<<<s1blocks, 256>>>(b_f, b_b, b_p);

    dim3 pg1((NENT+63)/64, 3);
    proj_kernel<<<pg1, 256, PROJ_SMEM>>>(1, ent, rel, ent1, rel1,
                                         Wih_f, Wih_b, Wih_p, Whh_f, Whh_b, Whh_p);

    step12_kernel<<<M_TOTAL/64, 256>>>(bh, br, bt, b_f, b_b, b_p);

    dim3 rg(4, M_TOTAL/128, 3);
    gemm_f32x2<<<rg, 256>>>(1, W1, Whh_f, Whh_b, Whh_p);

    step3_kernel<<<M_TOTAL/64, 256>>>(bh, bt, b_f, b_b, b_p);

    dim3 gg(5, M_TOTAL/128, 1);
    gemm_f32x2<<<gg, 256>>>(0, W1, Whh_f, Whh_b, Whh_p);

    gat1_att<<<NGROUP, 256>>>(a1, out_att, out2);

    gat2_kernel<<<NGROUP, 256, GAT2_SMEM>>>(W2, a2, output_att, op2);

    (void)in_sizes; (void)n_in; (void)out_size;
}

// round 5
// speedup vs baseline: 4.3391x; 1.5798x over previous
#include <cuda_runtime.h>
#include <cuda_bf16.h>
#include <math.h>
#include <cstdint>

#define M_TOTAL 81920
#define NGROUP  2048
#define NENT    14541
#define NRELS   237
#define K_PAD   640     // padded K for the 600-wide GEMM A/B
#define K_PAD2  128     // padded K for the recurrence GEMM

// ---------------- scratch (device globals: no allocation allowed) ----------
__device__ float g_Pe[3][NENT*400];
__device__ float g_Pr[3][NRELS*400];
__device__ float g_h1c1[3][NENT*200];
__device__ float g_R1[3][NENT*400];
__device__ float g_c2[(size_t)3*M_TOTAL*100];
__device__ float g_R2[(size_t)3*M_TOTAL*400];
__device__ float g_out[(size_t)M_TOTAL*600];
__device__ float g_hG [(size_t)M_TOTAL*600];
__device__ float g_op [(size_t)M_TOTAL*100];
// bf16 hi/lo splits (padding regions stay zero from static init; never written)
__device__ __align__(16) __nv_bfloat16 g_Ah[(size_t)M_TOTAL*K_PAD];
__device__ __align__(16) __nv_bfloat16 g_Al[(size_t)M_TOTAL*K_PAD];
__device__ __align__(16) __nv_bfloat16 g_BTh[640*K_PAD];     // W1^T split, padded rows
__device__ __align__(16) __nv_bfloat16 g_BTl[640*K_PAD];
__device__ __align__(16) __nv_bfloat16 g_h2h[(size_t)3*M_TOTAL*K_PAD2];
__device__ __align__(16) __nv_bfloat16 g_h2l[(size_t)3*M_TOTAL*K_PAD2];
__device__ __align__(16) __nv_bfloat16 g_WTh[3][512*K_PAD2]; // Whh (already [400,100]) split
__device__ __align__(16) __nv_bfloat16 g_WTl[3][512*K_PAD2];

__device__ __forceinline__ float sigmoidf_(float x){
    return __fdividef(1.f, 1.f + __expf(-x));
}
__device__ __forceinline__ float tanhf_(float x){
    float xc = fminf(fmaxf(x,-15.f),15.f);
    float e = __expf(2.f*xc);
    return __fdividef(e-1.f, e+1.f);
}
__device__ __forceinline__ void split2(float v, __nv_bfloat16* ph, __nv_bfloat16* pl){
    __nv_bfloat16 h = __float2bfloat16(v);
    *ph = h;
    *pl = __float2bfloat16(v - __bfloat162float(h));
}
__device__ __forceinline__ void store_splitA(size_t row, int col, float v){
    split2(v, &g_Ah[row*K_PAD + col], &g_Al[row*K_PAD + col]);
}

// ======================= HMMA GEMM plumbing =================================
__device__ __forceinline__ void cp16(unsigned saddr, const void* g){
    asm volatile("cp.async.cg.shared.global [%0], [%1], 16;" :: "r"(saddr), "l"(g));
}
__device__ __forceinline__ void cp_commit(){
    asm volatile("cp.async.commit_group;" ::: "memory");
}
template<int N> __device__ __forceinline__ void cp_wait(){
    asm volatile("cp.async.wait_group %0;" :: "n"(N) : "memory");
}
__device__ __forceinline__ void ldm4(uint32_t* r, unsigned addr){
    asm volatile("ldmatrix.sync.aligned.m8n8.x4.shared.b16 {%0,%1,%2,%3}, [%4];"
        : "=r"(r[0]), "=r"(r[1]), "=r"(r[2]), "=r"(r[3]) : "r"(addr));
}
__device__ __forceinline__ void mma16816(float* d, const uint32_t* a, uint32_t b0, uint32_t b1){
    asm volatile("mma.sync.aligned.m16n8k16.row.col.f32.bf16.bf16.f32 "
        "{%0,%1,%2,%3},{%4,%5,%6,%7},{%8,%9},{%0,%1,%2,%3};"
        : "+f"(d[0]), "+f"(d[1]), "+f"(d[2]), "+f"(d[3])
        : "r"(a[0]), "r"(a[1]), "r"(a[2]), "r"(a[3]), "r"(b0), "r"(b1));
}

#define STG_BYTES 65536                 // Ah 16K | Al 16K | Bh 16K | Bl 16K
#define MM_SMEM   (2*STG_BYTES)

__device__ __forceinline__ void stage2(unsigned sb,
    const __nv_bfloat16* Ah, const __nv_bfloat16* Al, size_t lda,
    const __nv_bfloat16* Bh, const __nv_bfloat16* Bl, size_t ldb, int tid)
{
    for (int i=tid;i<1024;i+=256){
        int r=i>>3, c=i&7;
        unsigned off = (unsigned)((r*128 + c*16) ^ ((r&7)<<4));
        cp16(sb + off,          Ah + (size_t)r*lda + c*8);
        cp16(sb + 16384 + off,  Al + (size_t)r*lda + c*8);
        cp16(sb + 32768 + off,  Bh + (size_t)r*ldb + c*8);
        cp16(sb + 49152 + off,  Bl + (size_t)r*ldb + c*8);
    }
}

// ---------------------------------------------------------------------------
// mma_gemm: C = A @ B^T with 3-term bf16 split, m16n8k16 HMMA.
// which==0: g_hG = g_out @ W1      (A splits g_Ah/Al, B^T splits g_BTh/l)
// which==1: g_R2[l] = h2 @ Whh^T   (blockIdx.z = l)
// ---------------------------------------------------------------------------
__global__ void __launch_bounds__(256,1) mma_gemm(int which)
{
    extern __shared__ char smraw[];
    unsigned sbase;
    asm("{ .reg .u64 t; cvta.to.shared.u64 t, %1; cvt.u32.u64 %0, t; }" : "=r"(sbase) : "l"(smraw));

    const __nv_bfloat16 *Ah,*Al,*Bh,*Bl; float* C;
    int Nvalid, ldc, nch; size_t lda, ldb;
    if (which==0){
        Ah=g_Ah; Al=g_Al; Bh=g_BTh; Bl=g_BTl; C=g_hG;
        Nvalid=600; ldc=600; nch=10; lda=K_PAD; ldb=K_PAD;
    } else {
        int l = blockIdx.z;
        Ah = g_h2h + (size_t)l*M_TOTAL*K_PAD2;
        Al = g_h2l + (size_t)l*M_TOTAL*K_PAD2;
        Bh = g_WTh[l]; Bl = g_WTl[l];
        C  = g_R2 + (size_t)l*M_TOTAL*400;
        Nvalid=400; ldc=400; nch=2; lda=K_PAD2; ldb=K_PAD2;
    }
    int tid=threadIdx.x, wid=tid>>5, lane=tid&31;
    int wm = wid & 1, wn = wid >> 1;            // warp grid 2 (M) x 4 (N)
    int ncol0 = blockIdx.x*128, mrow0 = blockIdx.y*128;

    const __nv_bfloat16* Ah0 = Ah + (size_t)mrow0*lda;
    const __nv_bfloat16* Al0 = Al + (size_t)mrow0*lda;
    const __nv_bfloat16* Bh0 = Bh + (size_t)ncol0*ldb;
    const __nv_bfloat16* Bl0 = Bl + (size_t)ncol0*ldb;

    float acc[4][4][4];
    #pragma unroll
    for (int i=0;i<4;i++)
        #pragma unroll
        for (int j=0;j<4;j++)
            #pragma unroll
            for (int q=0;q<4;q++) acc[i][j][q]=0.f;

    stage2(sbase,             Ah0,    Al0,    lda, Bh0,    Bl0,    ldb, tid); cp_commit();
    stage2(sbase + STG_BYTES, Ah0+64, Al0+64, lda, Bh0+64, Bl0+64, ldb, tid); cp_commit();

    // per-lane ldmatrix address components
    int lr  = lane & 15;
    int lhb = (lane >> 4) << 4;   // 0 or 16 bytes (k half)

    for (int k=0;k<nch;k++){
        if (k < nch-1) cp_wait<1>(); else cp_wait<0>();
        __syncthreads();
        unsigned st = sbase + (unsigned)(k&1)*STG_BYTES;
        unsigned sAh = st, sAl = st+16384, sBh = st+32768, sBl = st+49152;

        #pragma unroll
        for (int kk=0;kk<4;kk++){
            int cb = kk*32 + lhb;
            uint32_t ah[4][4], al[4][4], bh[2][4], bl[2][4];
            #pragma unroll
            for (int mt=0;mt<4;mt++){
                int r = wm*64 + mt*16 + lr;
                unsigned off = (unsigned)((r*128 + cb) ^ ((r&7)<<4));
                ldm4(ah[mt], sAh + off);
                ldm4(al[mt], sAl + off);
            }
            #pragma unroll
            for (int ng=0;ng<2;ng++){
                int n = wn*32 + ng*16 + lr;
                unsigned off = (unsigned)((n*128 + cb) ^ ((n&7)<<4));
                ldm4(bh[ng], sBh + off);
                ldm4(bl[ng], sBl + off);
            }
            #pragma unroll
            for (int mt=0;mt<4;mt++){
                #pragma unroll
                for (int nt=0;nt<4;nt++){
                    int ng = nt>>1, s = nt&1;
                    mma16816(acc[mt][nt], ah[mt], bh[ng][s], bh[ng][s+2]);
                    mma16816(acc[mt][nt], ah[mt], bl[ng][s], bl[ng][s+2]);
                    mma16816(acc[mt][nt], al[mt], bh[ng][s], bh[ng][s+2]);
                }
            }
        }
        __syncthreads();
        if (k+2 < nch){
            stage2(st, Ah0 + (k+2)*64, Al0 + (k+2)*64, lda,
                       Bh0 + (k+2)*64, Bl0 + (k+2)*64, ldb, tid);
            cp_commit();
        }
    }

    // epilogue
    #pragma unroll
    for (int mt=0;mt<4;mt++){
        int rbase = mrow0 + wm*64 + mt*16 + (lane>>2);
        #pragma unroll
        for (int nt=0;nt<4;nt++){
            int col = ncol0 + wn*32 + nt*8 + (lane&3)*2;
            if (col < Nvalid){
                *(float2*)(C + (size_t)rbase*ldc + col)     = make_float2(acc[mt][nt][0], acc[mt][nt][1]);
                *(float2*)(C + (size_t)(rbase+8)*ldc + col) = make_float2(acc[mt][nt][2], acc[mt][nt][3]);
            }
        }
    }
}

// ---------------------------------------------------------------------------
// convB: B^T splits of W1 (rows n<600, cols k<600; pads stay zero)
// ---------------------------------------------------------------------------
__global__ void convB_kernel(const float* __restrict__ W1)
{
    int i = blockIdx.x*256 + threadIdx.x;
    if (i >= 600*600) return;
    int n = i / 600, k = i - n*600;
    split2(W1[(size_t)k*600 + n], &g_BTh[(size_t)n*K_PAD + k], &g_BTl[(size_t)n*K_PAD + k]);
}
// convW: splits of Whh_l ([400,100] row-major == B^T layout already)
__global__ void convW_kernel(const float* __restrict__ Whf,
                             const float* __restrict__ Whb,
                             const float* __restrict__ Whp)
{
    int i = blockIdx.x*256 + threadIdx.x;
    if (i >= 3*400*100) return;
    int l = i / 40000; int rem = i - l*40000;
    int n = rem/100, k = rem - n*100;
    const float* W = (l==0)? Whf : (l==1)? Whb : Whp;
    split2(W[n*100+k], &g_WTh[l][n*K_PAD2 + k], &g_WTl[l][n*K_PAD2 + k]);
}

// ---------------------------------------------------------------------------
// K0: vocab-level GEMMs.
// ---------------------------------------------------------------------------
#define PROJ_SMEM ((64*101 + 400*100)*4)
__global__ void __launch_bounds__(256,1) proj_kernel(int phase,
    const float* __restrict__ ent,  const float* __restrict__ rel,
    const float* __restrict__ ent1, const float* __restrict__ rel1,
    const float* __restrict__ Wf,   const float* __restrict__ Wb,
    const float* __restrict__ Wp,
    const float* __restrict__ Whf,  const float* __restrict__ Whb,
    const float* __restrict__ Whp)
{
    const float* X; const float* W; float* P; int nrows; int xs;
    if (phase == 0){
        xs = 100;
        switch (blockIdx.y){
          case 0:  X=ent;  W=Wf; P=g_Pe[0]; nrows=NENT;  break;
          case 1:  X=rel;  W=Wf; P=g_Pr[0]; nrows=NRELS; break;
          case 2:  X=ent;  W=Wb; P=g_Pe[1]; nrows=NENT;  break;
          case 3:  X=rel;  W=Wb; P=g_Pr[1]; nrows=NRELS; break;
          case 4:  X=ent1; W=Wp; P=g_Pe[2]; nrows=NENT;  break;
          default: X=rel1; W=Wp; P=g_Pr[2]; nrows=NRELS; break;
        }
    } else {
        xs = 200; nrows = NENT;
        switch (blockIdx.y){
          case 0:  X=g_h1c1[0]; W=Whf; P=g_R1[0]; break;
          case 1:  X=g_h1c1[1]; W=Whb; P=g_R1[1]; break;
          default: X=g_h1c1[2]; W=Whp; P=g_R1[2]; break;
        }
    }
    int r0 = blockIdx.x*64;
    if (r0 >= nrows) return;
    extern __shared__ float sm[];
    float* esm = sm;            // 64 x 101
    float* wsm = sm + 64*101;   // 400 x 100
    int tid = threadIdx.x;
    for (int i=tid;i<40000;i+=256) wsm[i]=W[i];
    for (int i=tid;i<6400;i+=256){
        int r=i/100, k=i-r*100;
        esm[r*101+k] = (r0+r < nrows) ? X[(size_t)(r0+r)*xs+k] : 0.f;
    }
    __syncthreads();
    int warp=tid>>5, lane=tid&31;
    int gb = warp*50;
    float acc0[50], acc1[50];
    #pragma unroll
    for (int g=0;g<50;g++){ acc0[g]=0.f; acc1[g]=0.f; }
    #pragma unroll 1
    for (int k=0;k<100;k++){
        float x0 = esm[lane*101+k];
        float x1 = esm[(lane+32)*101+k];
        const float* wp = wsm + gb*100 + k;
        #pragma unroll
        for (int g=0;g<50;g++){
            float w = wp[g*100];
            acc0[g]=fmaf(w,x0,acc0[g]);
            acc1[g]=fmaf(w,x1,acc1[g]);
        }
    }
    int e0=r0+lane, e1=e0+32;
    if (e0<nrows){
        float* p=P+(size_t)e0*400+gb;
        #pragma unroll
        for (int g=0;g<50;g++) p[g]=acc0[g];
    }
    if (e1<nrows){
        float* p=P+(size_t)e1*400+gb;
        #pragma unroll
        for (int g=0;g<50;g++) p[g]=acc1[g];
    }
}

// ---------------------------------------------------------------------------
__global__ void step1_kernel(const float* __restrict__ b_f,
                             const float* __restrict__ b_b,
                             const float* __restrict__ b_p)
{
    int idx = blockIdx.x*256 + threadIdx.x;
    if (idx >= 3*NENT*100) return;
    int l   = idx / (NENT*100);
    int rem = idx - l*(NENT*100);
    int e = rem/100, j = rem - e*100;
    const float* P = g_Pe[l] + (size_t)e*400;
    const float* b = (l==0)? b_f : (l==1)? b_b : b_p;
    float iv = P[j]     + b[j];
    float gv = P[200+j] + b[200+j];
    float ov = P[300+j] + b[300+j];
    float c1 = sigmoidf_(iv) * tanhf_(gv);
    float h1 = sigmoidf_(ov) * tanhf_(c1);
    g_h1c1[l][(size_t)e*200 + j]       = h1;
    g_h1c1[l][(size_t)e*200 + 100 + j] = c1;
}

// ---------------------------------------------------------------------------
__global__ void __launch_bounds__(256,4) step12_kernel(
    const int* __restrict__ bh, const int* __restrict__ br, const int* __restrict__ bt,
    const float* __restrict__ b_f, const float* __restrict__ b_b, const float* __restrict__ b_p)
{
    __shared__ int ih[64], ir[64], it[64];
    int tid=threadIdx.x; int row0=blockIdx.x*64;
    if (tid<64)        ih[tid]     = bh[row0+tid];
    else if (tid<128)  ir[tid-64]  = br[row0+tid-64];
    else if (tid<192)  it[tid-128] = bt[row0+tid-128];
    __syncthreads();
    for (int l=0;l<3;l++){
        const float* Pr  = g_Pr[l];
        const float* R1  = g_R1[l];
        const float* HC  = g_h1c1[l];
        const float* bias= (l==0)?b_f:(l==1)?b_b:b_p;
        #pragma unroll
        for (int i=0;i<25;i++){
            int e=tid+i*256; int row=e/100, j=e-row*100;
            int fi = (l==1)? it[row] : ih[row];
            size_t grow=(size_t)(row0+row);
            float h1 = HC[(size_t)fi*200 + j];
            float c1 = HC[(size_t)fi*200 + 100 + j];
            if (l==0){      g_out[grow*600 + j]       = h1; store_splitA(grow, j, h1); }
            else if (l==1){ g_out[grow*600 + 500 + j] = h1; store_splitA(grow, 500+j, h1); }
            const float* pr = Pr + (size_t)ir[row]*400;
            const float* r1 = R1 + (size_t)fi*400;
            float iv = pr[j]     + r1[j]     + bias[j];
            float fv = pr[100+j] + r1[100+j] + bias[100+j];
            float gv = pr[200+j] + r1[200+j] + bias[200+j];
            float ov = pr[300+j] + r1[300+j] + bias[300+j];
            float c2 = sigmoidf_(fv)*c1 + sigmoidf_(iv)*tanhf_(gv);
            float h2 = sigmoidf_(ov)*tanhf_(c2);
            size_t hidx = (size_t)l*M_TOTAL*K_PAD2 + grow*K_PAD2 + j;
            split2(h2, &g_h2h[hidx], &g_h2l[hidx]);
            g_c2[(size_t)l*M_TOTAL*100 + grow*100 + j] = c2;
            if (l==0){      g_out[grow*600 + 200 + j] = h2; store_splitA(grow, 200+j, h2); }
            else if (l==1){ g_out[grow*600 + 300 + j] = h2; store_splitA(grow, 300+j, h2); }
        }
    }
}

// ---------------------------------------------------------------------------
__global__ void __launch_bounds__(256,4) step3_kernel(
    const int* __restrict__ bh, const int* __restrict__ bt,
    const float* __restrict__ b_f, const float* __restrict__ b_b, const float* __restrict__ b_p)
{
    __shared__ int ih[64], it[64];
    int tid=threadIdx.x; int row0=blockIdx.x*64;
    if (tid<64)        ih[tid]    = bh[row0+tid];
    else if (tid<128)  it[tid-64] = bt[row0+tid-64];
    __syncthreads();
    for (int l=0;l<3;l++){
        const float* Pe  = g_Pe[l];
        const float* R2  = g_R2 + (size_t)l*M_TOTAL*400;
        const float* C2  = g_c2 + (size_t)l*M_TOTAL*100;
        const float* bias= (l==0)?b_f:(l==1)?b_b:b_p;
        #pragma unroll
        for (int i=0;i<25;i++){
            int e=tid+i*256; int row=e/100, j=e-row*100;
            int li = (l==1)? ih[row] : it[row];
            size_t grow=(size_t)(row0+row);
            const float* pe = Pe + (size_t)li*400;
            const float* r2 = R2 + grow*400;
            float iv = pe[j]     + r2[j]     + bias[j];
            float fv = pe[100+j] + r2[100+j] + bias[100+j];
            float gv = pe[200+j] + r2[200+j] + bias[200+j];
            float ov = pe[300+j] + r2[300+j] + bias[300+j];
            float c3 = sigmoidf_(fv)*C2[grow*100+j] + sigmoidf_(iv)*tanhf_(gv);
            float h3 = sigmoidf_(ov)*tanhf_(c3);
            if (l==0){      g_out[grow*600 + 400 + j]=h3; store_splitA(grow, 400+j, h3); }
            else if (l==1){ g_out[grow*600 + 100 + j]=h3; store_splitA(grow, 100+j, h3); }
            else            g_op [grow*100 + j]      =h3;
        }
    }
}

// ---------------------------------------------------------------------------
__global__ void __launch_bounds__(256,1) gat1_att(
    const float* __restrict__ a1, float* __restrict__ out_att, float* __restrict__ out2)
{
    __shared__ __align__(16) float a1s[1200];
    __shared__ float ebuf[41];
    __shared__ float att[40];
    __shared__ float red[2];
    int b=blockIdx.x, tid=threadIdx.x, warp=tid>>5, lane=tid&31;
    for (int i=tid;i<1200;i+=256) a1s[i]=a1[i];
    __syncthreads();
    const float* base = g_hG + (size_t)b*24000;
    for (int t=warp;t<41;t+=8){
        const float* rowp = (t<40)? base + t*600 : base;
        const float* av   = (t<40)? a1s         : a1s+600;
        float s=0.f;
        for (int kk=lane;kk<150;kk+=32){
            float4 r4 = *(const float4*)(rowp + kk*4);
            float4 a4 = *(const float4*)(av   + kk*4);
            s += r4.x*a4.x + r4.y*a4.y + r4.z*a4.z + r4.w*a4.w;
        }
        #pragma unroll
        for (int o=16;o;o>>=1) s += __shfl_xor_sync(0xffffffffu, s, o);
        if (lane==0) ebuf[t]=s;
    }
    __syncthreads();
    if (tid<40){
        float x = ebuf[tid] + ebuf[40];
        ebuf[tid] = (x>0.f)? x : 0.2f*x;
    }
    __syncthreads();
    if (tid<32){
        float v = ebuf[tid];
        if (tid<8) v = fmaxf(v, ebuf[tid+32]);
        #pragma unroll
        for (int o=16;o;o>>=1) v = fmaxf(v, __shfl_xor_sync(0xffffffffu, v, o));
        if (tid==0) red[0]=v;
    }
    __syncthreads();
    if (tid<40) att[tid]=__expf(ebuf[tid]-red[0]);
    __syncthreads();
    if (tid<32){
        float v = att[tid] + ((tid<8)? att[tid+32] : 0.f);
        #pragma unroll
        for (int o=16;o;o>>=1) v += __shfl_xor_sync(0xffffffffu, v, o);
        if (tid==0) red[1]=1.f/v;
    }
    __syncthreads();
    if (tid<40) att[tid]=fmaxf(att[tid]*red[1]-0.001f, 0.f);
    __syncthreads();
    for (int f=tid; f<600; f+=256){
        float acc=0.f;
        #pragma unroll 8
        for (int n=0;n<40;n++) acc += att[n]*base[n*600+f];
        out_att[(size_t)b*600+f]=acc;
    }
    if ((b&1)==0){
        const float* srow = g_out + (size_t)b*40*600;
        float* drow = out2 + (size_t)(b>>1)*600;
        for (int f=tid;f<600;f+=256) drow[f]=srow[f];
    }
}

// ---------------------------------------------------------------------------
#define GAT2_SMEM ((4000 + 10000 + 4000)*4)
__global__ void __launch_bounds__(256,1) gat2_kernel(
    const float* __restrict__ W2, const float* __restrict__ a2,
    float* __restrict__ output_att, float* __restrict__ op2)
{
    extern __shared__ float sm[];
    float* ops = sm;
    float* Ws  = ops + 4000;
    float* hg  = Ws  + 10000;
    __shared__ float a2s[200];
    __shared__ float ebuf[41];
    __shared__ float att[40];
    __shared__ float red[2];
    int b=blockIdx.x, tid=threadIdx.x, warp=tid>>5, lane=tid&31;
    const float* src = g_op + (size_t)b*4000;
    for (int i=tid;i<4000;i+=256)  ops[i]=src[i];
    for (int i=tid;i<10000;i+=256) Ws[i]=W2[i];
    if (tid<200) a2s[tid]=a2[tid];
    __syncthreads();
    for (int i=tid;i<4000;i+=256){
        int n=i/100, o=i-n*100;
        float acc=0.f;
        #pragma unroll 4
        for (int k=0;k<100;k++) acc=fmaf(ops[n*100+k], Ws[k*100+o], acc);
        hg[i]=acc;
    }
    __syncthreads();
    for (int t=warp;t<41;t+=8){
        const float* rowp = (t<40)? hg + t*100 : hg;
        const float* av   = (t<40)? a2s        : a2s+100;
        float s=0.f;
        for (int k=lane;k<100;k+=32) s += rowp[k]*av[k];
        #pragma unroll
        for (int o=16;o;o>>=1) s += __shfl_xor_sync(0xffffffffu, s, o);
        if (lane==0) ebuf[t]=s;
    }
    __syncthreads();
    if (tid<40){
        float x = ebuf[tid] + ebuf[40];
        ebuf[tid] = (x>0.f)? x : 0.2f*x;
    }
    __syncthreads();
    if (tid<32){
        float v = ebuf[tid];
        if (tid<8) v = fmaxf(v, ebuf[tid+32]);
        #pragma unroll
        for (int o=16;o;o>>=1) v = fmaxf(v, __shfl_xor_sync(0xffffffffu, v, o));
        if (tid==0) red[0]=v;
    }
    __syncthreads();
    if (tid<40) att[tid]=__expf(ebuf[tid]-red[0]);
    __syncthreads();
    if (tid<32){
        float v = att[tid] + ((tid<8)? att[tid+32] : 0.f);
        #pragma unroll
        for (int o=16;o;o>>=1) v += __shfl_xor_sync(0xffffffffu, v, o);
        if (tid==0) red[1]=1.f/v;
    }
    __syncthreads();
    if (tid<40) att[tid]=fmaxf(att[tid]*red[1]-0.001f, 0.f);
    __syncthreads();
    if (tid<100){
        float acc=0.f;
        #pragma unroll 8
        for (int n=0;n<40;n++) acc += att[n]*hg[n*100+tid];
        output_att[(size_t)b*100+tid]=acc;
    }
    if ((b&1)==0){
        const float* srow = g_op + (size_t)b*40*100;
        float* drow = op2 + (size_t)(b>>1)*100;
        if (tid<100) drow[tid]=srow[tid];
    }
}

// ---------------------------------------------------------------------------
extern "C" void kernel_launch(void* const* d_in, const int* in_sizes, int n_in,
                              void* d_out, int out_size)
{
    const int*   bh    = (const int*)  d_in[0];
    const int*   br    = (const int*)  d_in[1];
    const int*   bt    = (const int*)  d_in[2];
    const float* ent   = (const float*)d_in[3];
    const float* rel   = (const float*)d_in[4];
    const float* ent1  = (const float*)d_in[5];
    const float* rel1  = (const float*)d_in[6];
    const float* Wih_f = (const float*)d_in[7];
    const float* Whh_f = (const float*)d_in[8];
    const float* b_f   = (const float*)d_in[9];
    const float* Wih_b = (const float*)d_in[10];
    const float* Whh_b = (const float*)d_in[11];
    const float* b_b   = (const float*)d_in[12];
    const float* Wih_p = (const float*)d_in[13];
    const float* Whh_p = (const float*)d_in[14];
    const float* b_p   = (const float*)d_in[15];
    const float* W1    = (const float*)d_in[16];
    const float* a1    = (const float*)d_in[17];
    const float* W2    = (const float*)d_in[18];
    const float* a2    = (const float*)d_in[19];

    float* out        = (float*)d_out;
    float* out2       = out;                          // [1024,600]
    float* out_att    = out + 1024*600;               // [2048,600]
    float* op2        = out + 1024*600 + 2048*600;    // [1024,100]
    float* output_att = op2 + 1024*100;               // [2048,100]

    cudaFuncSetAttribute(proj_kernel, cudaFuncAttributeMaxDynamicSharedMemorySize, PROJ_SMEM);
    cudaFuncSetAttribute(gat2_kernel, cudaFuncAttributeMaxDynamicSharedMemorySize, GAT2_SMEM);
    cudaFuncSetAttribute(mma_gemm,    cudaFuncAttributeMaxDynamicSharedMemorySize, MM_SMEM);

    convB_kernel<<<(600*600 + 255)/256, 256>>>(W1);
    convW_kernel<<<(3*400*100 + 255)/256, 256>>>(Whh_f, Whh_b, Whh_p);

    dim3 pg0((NENT+63)/64, 6);
    proj_kernel<<<pg0, 256, PROJ_SMEM>>>(0, ent, rel, ent1, rel1,
                                         Wih_f, Wih_b, Wih_p, Whh_f, Whh_b, Whh_p);

    int s1blocks = (3*NENT*100 + 255)/256;
    step1_kernel<<<s1blocks, 256>>>(b_f, b_b, b_p);

    dim3 pg1((NENT+63)/64, 3);
    proj_kernel<<<pg1, 256, PROJ_SMEM>>>(1, ent, rel, ent1, rel1,
                                         Wih_f, Wih_b, Wih_p, Whh_f, Whh_b, Whh_p);

    step12_kernel<<<M_TOTAL/64, 256>>>(bh, br, bt, b_f, b_b, b_p);

    dim3 rg(4, M_TOTAL/128, 3);
    mma_gemm<<<rg, 256, MM_SMEM>>>(1);

    step3_kernel<<<M_TOTAL/64, 256>>>(bh, bt, b_f, b_b, b_p);

    dim3 gg(5, M_TOTAL/128, 1);
    mma_gemm<<<gg, 256, MM_SMEM>>>(0);

    gat1_att<<<NGROUP, 256>>>(a1, out_att, out2);

    gat2_kernel<<<NGROUP, 256, GAT2_SMEM>>>(W2, a2, output_att, op2);

    (void)in_sizes; (void)n_in; (void)out_size;
}

// round 6
// speedup vs baseline: 6.2155x; 1.4324x over previous
#include <cuda_runtime.h>
#include <cuda_bf16.h>
#include <math.h>
#include <cstdint>

#define M_TOTAL 81920
#define NGROUP  2048
#define NENT    14541
#define NRELS   237
#define NENT_P  14592   // NENT padded to 128
#define K_PAD   640     // padded K for the 600-wide GEMM
#define K_PAD2  128     // padded K for 100-wide GEMMs

// ---------------- scratch (device globals: no allocation allowed) ----------
__device__ float g_Pe[3][NENT*400];
__device__ float g_Pr[3][NRELS*400];
__device__ float g_h1c1[3][NENT*200];
__device__ float g_R1[3][NENT*400];
__device__ float g_c2[(size_t)3*M_TOTAL*100];
__device__ float g_R2[(size_t)3*M_TOTAL*400];
__device__ float g_out[(size_t)M_TOTAL*600];
__device__ float g_hG [(size_t)M_TOTAL*600];
__device__ float g_op [(size_t)M_TOTAL*100];
// bf16 hi/lo splits (pad regions stay zero from static init; never written)
__device__ __align__(16) __nv_bfloat16 g_Ah[(size_t)M_TOTAL*K_PAD];
__device__ __align__(16) __nv_bfloat16 g_Al[(size_t)M_TOTAL*K_PAD];
__device__ __align__(16) __nv_bfloat16 g_BTh[640*K_PAD];
__device__ __align__(16) __nv_bfloat16 g_BTl[640*K_PAD];
__device__ __align__(16) __nv_bfloat16 g_h2h[(size_t)3*M_TOTAL*K_PAD2];
__device__ __align__(16) __nv_bfloat16 g_h2l[(size_t)3*M_TOTAL*K_PAD2];
// weights: idx 0..2 = Whh f/b/p ; 3..5 = Wih f/b/p  (each [512,128] B^T layout)
__device__ __align__(16) __nv_bfloat16 g_WTh[6][512*K_PAD2];
__device__ __align__(16) __nv_bfloat16 g_WTl[6][512*K_PAD2];
// embedding splits: 0=ent,1=ent1 ; rel: 0=rel,1=rel1
__device__ __align__(16) __nv_bfloat16 g_Eh[2][NENT_P*K_PAD2];
__device__ __align__(16) __nv_bfloat16 g_El[2][NENT_P*K_PAD2];
__device__ __align__(16) __nv_bfloat16 g_Rh[2][256*K_PAD2];
__device__ __align__(16) __nv_bfloat16 g_Rl[2][256*K_PAD2];
// step-1 hidden splits
__device__ __align__(16) __nv_bfloat16 g_h1h[3][NENT_P*K_PAD2];
__device__ __align__(16) __nv_bfloat16 g_h1l[3][NENT_P*K_PAD2];

__device__ __forceinline__ float sigmoidf_(float x){
    return __fdividef(1.f, 1.f + __expf(-x));
}
__device__ __forceinline__ float tanhf_(float x){
    float xc = fminf(fmaxf(x,-15.f),15.f);
    float e = __expf(2.f*xc);
    return __fdividef(e-1.f, e+1.f);
}
__device__ __forceinline__ void split2(float v, __nv_bfloat16* ph, __nv_bfloat16* pl){
    __nv_bfloat16 h = __float2bfloat16(v);
    *ph = h;
    *pl = __float2bfloat16(v - __bfloat162float(h));
}
// split a float4 into two packed 4xbf16 (8B) stores
__device__ __forceinline__ void split4(float4 v, __nv_bfloat16* ph, __nv_bfloat16* pl){
    __nv_bfloat16 h0=__float2bfloat16(v.x), h1=__float2bfloat16(v.y);
    __nv_bfloat16 h2=__float2bfloat16(v.z), h3=__float2bfloat16(v.w);
    __nv_bfloat162 a = {h0,h1}, b = {h2,h3};
    __nv_bfloat162 c = {__float2bfloat16(v.x-__bfloat162float(h0)), __float2bfloat16(v.y-__bfloat162float(h1))};
    __nv_bfloat162 d = {__float2bfloat16(v.z-__bfloat162float(h2)), __float2bfloat16(v.w-__bfloat162float(h3))};
    ((__nv_bfloat162*)ph)[0]=a; ((__nv_bfloat162*)ph)[1]=b;
    ((__nv_bfloat162*)pl)[0]=c; ((__nv_bfloat162*)pl)[1]=d;
}

// ======================= HMMA GEMM plumbing =================================
__device__ __forceinline__ void cp16(unsigned saddr, const void* g){
    asm volatile("cp.async.cg.shared.global [%0], [%1], 16;" :: "r"(saddr), "l"(g));
}
__device__ __forceinline__ void cp_commit(){
    asm volatile("cp.async.commit_group;" ::: "memory");
}
template<int N> __device__ __forceinline__ void cp_wait(){
    asm volatile("cp.async.wait_group %0;" :: "n"(N) : "memory");
}
__device__ __forceinline__ void ldm4(uint32_t* r, unsigned addr){
    asm volatile("ldmatrix.sync.aligned.m8n8.x4.shared.b16 {%0,%1,%2,%3}, [%4];"
        : "=r"(r[0]), "=r"(r[1]), "=r"(r[2]), "=r"(r[3]) : "r"(addr));
}
__device__ __forceinline__ void mma16816(float* d, const uint32_t* a, uint32_t b0, uint32_t b1){
    asm volatile("mma.sync.aligned.m16n8k16.row.col.f32.bf16.bf16.f32 "
        "{%0,%1,%2,%3},{%4,%5,%6,%7},{%8,%9},{%0,%1,%2,%3};"
        : "+f"(d[0]), "+f"(d[1]), "+f"(d[2]), "+f"(d[3])
        : "r"(a[0]), "r"(a[1]), "r"(a[2]), "r"(a[3]), "r"(b0), "r"(b1));
}

#define STG_BYTES 65536                 // Ah 16K | Al 16K | Bh 16K | Bl 16K
#define MM_SMEM   (2*STG_BYTES)

__device__ __forceinline__ void stageG(unsigned sb,
    const __nv_bfloat16* Ah, const __nv_bfloat16* Al, size_t lda, int mrow0, int Mv,
    const __nv_bfloat16* Bh, const __nv_bfloat16* Bl, size_t ldb, int ncol0,
    int kcol, int tid)
{
    for (int i=tid;i<1024;i+=256){
        int r=i>>3, c=i&7;
        unsigned off = (unsigned)((r*128 + c*16) ^ ((r&7)<<4));
        int ra = mrow0 + r; if (ra >= Mv) ra = Mv-1;
        cp16(sb + off,          Ah + (size_t)ra*lda + kcol + c*8);
        cp16(sb + 16384 + off,  Al + (size_t)ra*lda + kcol + c*8);
        cp16(sb + 32768 + off,  Bh + (size_t)(ncol0+r)*ldb + kcol + c*8);
        cp16(sb + 49152 + off,  Bl + (size_t)(ncol0+r)*ldb + kcol + c*8);
    }
}

// ---------------------------------------------------------------------------
// mma_gemm: C = A @ B^T with 3-term bf16 split, m16n8k16 HMMA.
// which 0: g_hG = out @ W1        1: R2[z] = h2[z] @ Whh_z^T
// which 2: Pe[z] = ent/ent1 @ Wih_z^T   3: Pr[z] = rel/rel1 @ Wih_z^T
// which 4: R1[z] = h1[z] @ Whh_z^T
// ---------------------------------------------------------------------------
__global__ void __launch_bounds__(256,1) mma_gemm(int which)
{
    extern __shared__ char smraw[];
    unsigned sbase;
    asm("{ .reg .u64 t; cvta.to.shared.u64 t, %1; cvt.u32.u64 %0, t; }" : "=r"(sbase) : "l"(smraw));

    const __nv_bfloat16 *Ah,*Al,*Bh,*Bl; float* C;
    int Mv, Nv, ldc, nch; size_t lda, ldb;
    int z = blockIdx.z;
    switch (which){
      case 0:
        Ah=g_Ah; Al=g_Al; Bh=g_BTh; Bl=g_BTl; C=g_hG;
        Mv=M_TOTAL; Nv=600; ldc=600; nch=10; lda=K_PAD; ldb=K_PAD; break;
      case 1:
        Ah=g_h2h+(size_t)z*M_TOTAL*K_PAD2; Al=g_h2l+(size_t)z*M_TOTAL*K_PAD2;
        Bh=g_WTh[z]; Bl=g_WTl[z]; C=g_R2+(size_t)z*M_TOTAL*400;
        Mv=M_TOTAL; Nv=400; ldc=400; nch=2; lda=K_PAD2; ldb=K_PAD2; break;
      case 2: {
        int e = (z==2)? 1 : 0;
        Ah=g_Eh[e]; Al=g_El[e]; Bh=g_WTh[3+z]; Bl=g_WTl[3+z]; C=g_Pe[z];
        Mv=NENT; Nv=400; ldc=400; nch=2; lda=K_PAD2; ldb=K_PAD2; break; }
      case 3: {
        int e = (z==2)? 1 : 0;
        Ah=g_Rh[e]; Al=g_Rl[e]; Bh=g_WTh[3+z]; Bl=g_WTl[3+z]; C=g_Pr[z];
        Mv=NRELS; Nv=400; ldc=400; nch=2; lda=K_PAD2; ldb=K_PAD2; break; }
      default:
        Ah=g_h1h[z]; Al=g_h1l[z]; Bh=g_WTh[z]; Bl=g_WTl[z]; C=g_R1[z];
        Mv=NENT; Nv=400; ldc=400; nch=2; lda=K_PAD2; ldb=K_PAD2; break;
    }
    int tid=threadIdx.x, wid=tid>>5, lane=tid&31;
    int wm = wid & 1, wn = wid >> 1;
    int ncol0 = blockIdx.x*128, mrow0 = blockIdx.y*128;

    float acc[4][4][4];
    #pragma unroll
    for (int i=0;i<4;i++)
        #pragma unroll
        for (int j=0;j<4;j++)
            #pragma unroll
            for (int q=0;q<4;q++) acc[i][j][q]=0.f;

    stageG(sbase,             Ah,Al,lda,mrow0,Mv, Bh,Bl,ldb,ncol0, 0,  tid); cp_commit();
    stageG(sbase + STG_BYTES, Ah,Al,lda,mrow0,Mv, Bh,Bl,ldb,ncol0, 64, tid); cp_commit();

    int lr  = lane & 15;
    int lhb = (lane >> 4) << 4;

    for (int k=0;k<nch;k++){
        if (k < nch-1) cp_wait<1>(); else cp_wait<0>();
        __syncthreads();
        unsigned st = sbase + (unsigned)(k&1)*STG_BYTES;
        unsigned sAh = st, sAl = st+16384, sBh = st+32768, sBl = st+49152;

        #pragma unroll
        for (int kk=0;kk<4;kk++){
            int cb = kk*32 + lhb;
            uint32_t ah[4][4], al[4][4], bh[2][4], bl[2][4];
            #pragma unroll
            for (int mt=0;mt<4;mt++){
                int r = wm*64 + mt*16 + lr;
                unsigned off = (unsigned)((r*128 + cb) ^ ((r&7)<<4));
                ldm4(ah[mt], sAh + off);
                ldm4(al[mt], sAl + off);
            }
            #pragma unroll
            for (int ng=0;ng<2;ng++){
                int n = wn*32 + ng*16 + lr;
                unsigned off = (unsigned)((n*128 + cb) ^ ((n&7)<<4));
                ldm4(bh[ng], sBh + off);
                ldm4(bl[ng], sBl + off);
            }
            #pragma unroll
            for (int mt=0;mt<4;mt++){
                #pragma unroll
                for (int nt=0;nt<4;nt++){
                    int ng = nt>>1, s = nt&1;
                    mma16816(acc[mt][nt], ah[mt], bh[ng][s], bh[ng][s+2]);
                    mma16816(acc[mt][nt], ah[mt], bl[ng][s], bl[ng][s+2]);
                    mma16816(acc[mt][nt], al[mt], bh[ng][s], bh[ng][s+2]);
                }
            }
        }
        __syncthreads();
        if (k+2 < nch){
            stageG(st, Ah,Al,lda,mrow0,Mv, Bh,Bl,ldb,ncol0, (k+2)*64, tid);
            cp_commit();
        }
    }

    #pragma unroll
    for (int mt=0;mt<4;mt++){
        int rbase = mrow0 + wm*64 + mt*16 + (lane>>2);
        #pragma unroll
        for (int nt=0;nt<4;nt++){
            int col = ncol0 + wn*32 + nt*8 + (lane&3)*2;
            if (col < Nv){
                if (rbase < Mv)
                    *(float2*)(C + (size_t)rbase*ldc + col)     = make_float2(acc[mt][nt][0], acc[mt][nt][1]);
                if (rbase+8 < Mv)
                    *(float2*)(C + (size_t)(rbase+8)*ldc + col) = make_float2(acc[mt][nt][2], acc[mt][nt][3]);
            }
        }
    }
}

// ---------------------------------------------------------------------------
// conversions
// ---------------------------------------------------------------------------
__global__ void convB_kernel(const float* __restrict__ W1)
{
    int i = blockIdx.x*256 + threadIdx.x;
    if (i >= 600*600) return;
    int n = i / 600, k = i - n*600;
    split2(W1[(size_t)k*600 + n], &g_BTh[(size_t)n*K_PAD + k], &g_BTl[(size_t)n*K_PAD + k]);
}
__global__ void convW6_kernel(const float* __restrict__ Whf, const float* __restrict__ Whb,
                              const float* __restrict__ Whp, const float* __restrict__ Wif,
                              const float* __restrict__ Wib, const float* __restrict__ Wip)
{
    int i = blockIdx.x*256 + threadIdx.x;
    if (i >= 6*400*100) return;
    int m = i / 40000; int rem = i - m*40000;
    int n = rem/100, k = rem - n*100;
    const float* W;
    switch(m){ case 0:W=Whf;break; case 1:W=Whb;break; case 2:W=Whp;break;
               case 3:W=Wif;break; case 4:W=Wib;break; default:W=Wip;break; }
    split2(W[n*100+k], &g_WTh[m][n*K_PAD2 + k], &g_WTl[m][n*K_PAD2 + k]);
}
__global__ void convE_kernel(const float* __restrict__ ent, const float* __restrict__ ent1,
                             const float* __restrict__ rel, const float* __restrict__ rel1)
{
    int i = blockIdx.x*256 + threadIdx.x;
    if (i < 2*NENT*100){
        int e = i / (NENT*100); int rem = i - e*(NENT*100);
        int r = rem/100, k = rem - r*100;
        const float* src = e ? ent1 : ent;
        split2(src[(size_t)r*100+k], &g_Eh[e][(size_t)r*K_PAD2+k], &g_El[e][(size_t)r*K_PAD2+k]);
    } else {
        int j = i - 2*NENT*100;
        if (j >= 2*NRELS*100) return;
        int e = j / (NRELS*100); int rem = j - e*(NRELS*100);
        int r = rem/100, k = rem - r*100;
        const float* src = e ? rel1 : rel;
        split2(src[(size_t)r*100+k], &g_Rh[e][(size_t)r*K_PAD2+k], &g_Rl[e][(size_t)r*K_PAD2+k]);
    }
}

// ---------------------------------------------------------------------------
// step1: per-entity first LSTM cell; also emits h1 bf16 splits for the GEMM.
// ---------------------------------------------------------------------------
__global__ void step1_kernel(const float* __restrict__ b_f,
                             const float* __restrict__ b_b,
                             const float* __restrict__ b_p)
{
    int idx = blockIdx.x*256 + threadIdx.x;
    if (idx >= 3*NENT*100) return;
    int l   = idx / (NENT*100);
    int rem = idx - l*(NENT*100);
    int e = rem/100, j = rem - e*100;
    const float* P = g_Pe[l] + (size_t)e*400;
    const float* b = (l==0)? b_f : (l==1)? b_b : b_p;
    float iv = P[j]     + b[j];
    float gv = P[200+j] + b[200+j];
    float ov = P[300+j] + b[300+j];
    float c1 = sigmoidf_(iv) * tanhf_(gv);
    float h1 = sigmoidf_(ov) * tanhf_(c1);
    g_h1c1[l][(size_t)e*200 + j]       = h1;
    g_h1c1[l][(size_t)e*200 + 100 + j] = c1;
    split2(h1, &g_h1h[l][(size_t)e*K_PAD2 + j], &g_h1l[l][(size_t)e*K_PAD2 + j]);
}

// ---------------------------------------------------------------------------
// step12: gather + step2 cell, float4-vectorized. g_out stored only for rows%80==0.
// ---------------------------------------------------------------------------
__global__ void __launch_bounds__(256) step12_kernel(
    const int* __restrict__ bh, const int* __restrict__ br, const int* __restrict__ bt,
    const float* __restrict__ b_f, const float* __restrict__ b_b, const float* __restrict__ b_p)
{
    __shared__ int ih[64], ir[64], it[64];
    int tid=threadIdx.x; int row0=blockIdx.x*64;
    if (tid<64)        ih[tid]     = bh[row0+tid];
    else if (tid<128)  ir[tid-64]  = br[row0+tid-64];
    else if (tid<192)  it[tid-128] = bt[row0+tid-128];
    __syncthreads();
    for (int l=0;l<3;l++){
        const float* Pr  = g_Pr[l];
        const float* R1  = g_R1[l];
        const float* HC  = g_h1c1[l];
        const float* bias= (l==0)?b_f:(l==1)?b_b:b_p;
        for (int t=tid;t<1600;t+=256){
            int row=t/25, q=t-row*25; int j=q*4;
            int fi = (l==1)? it[row] : ih[row];
            size_t grow=(size_t)(row0+row);
            bool emit_out = ((grow % 80u)==0u) && (l<2);
            float4 h1v = *(const float4*)&HC[(size_t)fi*200 + j];
            float4 c1v = *(const float4*)&HC[(size_t)fi*200 + 100 + j];
            if (l==0){
                if (emit_out) *(float4*)&g_out[grow*600 + j] = h1v;
                split4(h1v, &g_Ah[grow*K_PAD + j], &g_Al[grow*K_PAD + j]);
            } else if (l==1){
                if (emit_out) *(float4*)&g_out[grow*600 + 500 + j] = h1v;
                split4(h1v, &g_Ah[grow*K_PAD + 500 + j], &g_Al[grow*K_PAD + 500 + j]);
            }
            const float* pr = Pr + (size_t)ir[row]*400;
            const float* r1 = R1 + (size_t)fi*400;
            float4 pi = *(const float4*)&pr[j],      ri = *(const float4*)&r1[j];
            float4 pf = *(const float4*)&pr[100+j],  rf = *(const float4*)&r1[100+j];
            float4 pg = *(const float4*)&pr[200+j],  rg = *(const float4*)&r1[200+j];
            float4 po = *(const float4*)&pr[300+j],  ro = *(const float4*)&r1[300+j];
            float4 bi = *(const float4*)&bias[j],    bf4= *(const float4*)&bias[100+j];
            float4 bg = *(const float4*)&bias[200+j],bo = *(const float4*)&bias[300+j];
            float4 c2v, h2v;
            {
                float c,h;
                c = sigmoidf_(pf.x+rf.x+bf4.x)*c1v.x + sigmoidf_(pi.x+ri.x+bi.x)*tanhf_(pg.x+rg.x+bg.x);
                h = sigmoidf_(po.x+ro.x+bo.x)*tanhf_(c); c2v.x=c; h2v.x=h;
                c = sigmoidf_(pf.y+rf.y+bf4.y)*c1v.y + sigmoidf_(pi.y+ri.y+bi.y)*tanhf_(pg.y+rg.y+bg.y);
                h = sigmoidf_(po.y+ro.y+bo.y)*tanhf_(c); c2v.y=c; h2v.y=h;
                c = sigmoidf_(pf.z+rf.z+bf4.z)*c1v.z + sigmoidf_(pi.z+ri.z+bi.z)*tanhf_(pg.z+rg.z+bg.z);
                h = sigmoidf_(po.z+ro.z+bo.z)*tanhf_(c); c2v.z=c; h2v.z=h;
                c = sigmoidf_(pf.w+rf.w+bf4.w)*c1v.w + sigmoidf_(pi.w+ri.w+bi.w)*tanhf_(pg.w+rg.w+bg.w);
                h = sigmoidf_(po.w+ro.w+bo.w)*tanhf_(c); c2v.w=c; h2v.w=h;
            }
            size_t hidx = (size_t)l*M_TOTAL*K_PAD2 + grow*K_PAD2 + j;
            split4(h2v, &g_h2h[hidx], &g_h2l[hidx]);
            *(float4*)&g_c2[(size_t)l*M_TOTAL*100 + grow*100 + j] = c2v;
            if (l==0){
                if (emit_out) *(float4*)&g_out[grow*600 + 200 + j] = h2v;
                split4(h2v, &g_Ah[grow*K_PAD + 200 + j], &g_Al[grow*K_PAD + 200 + j]);
            } else if (l==1){
                if (emit_out) *(float4*)&g_out[grow*600 + 300 + j] = h2v;
                split4(h2v, &g_Ah[grow*K_PAD + 300 + j], &g_Al[grow*K_PAD + 300 + j]);
            }
        }
    }
}

// ---------------------------------------------------------------------------
// step3: final cell, float4-vectorized.
// ---------------------------------------------------------------------------
__global__ void __launch_bounds__(256) step3_kernel(
    const int* __restrict__ bh, const int* __restrict__ bt,
    const float* __restrict__ b_f, const float* __restrict__ b_b, const float* __restrict__ b_p)
{
    __shared__ int ih[64], it[64];
    int tid=threadIdx.x; int row0=blockIdx.x*64;
    if (tid<64)        ih[tid]    = bh[row0+tid];
    else if (tid<128)  it[tid-64] = bt[row0+tid-64];
    __syncthreads();
    for (int l=0;l<3;l++){
        const float* Pe  = g_Pe[l];
        const float* R2  = g_R2 + (size_t)l*M_TOTAL*400;
        const float* C2  = g_c2 + (size_t)l*M_TOTAL*100;
        const float* bias= (l==0)?b_f:(l==1)?b_b:b_p;
        for (int t=tid;t<1600;t+=256){
            int row=t/25, q=t-row*25; int j=q*4;
            int li = (l==1)? ih[row] : it[row];
            size_t grow=(size_t)(row0+row);
            const float* pe = Pe + (size_t)li*400;
            const float* r2 = R2 + grow*400;
            float4 pi = *(const float4*)&pe[j],      ri = *(const float4*)&r2[j];
            float4 pf = *(const float4*)&pe[100+j],  rf = *(const float4*)&r2[100+j];
            float4 pg = *(const float4*)&pe[200+j],  rg = *(const float4*)&r2[200+j];
            float4 po = *(const float4*)&pe[300+j],  ro = *(const float4*)&r2[300+j];
            float4 bi = *(const float4*)&bias[j],    bf4= *(const float4*)&bias[100+j];
            float4 bg = *(const float4*)&bias[200+j],bo = *(const float4*)&bias[300+j];
            float4 c2v = *(const float4*)&C2[grow*100 + j];
            float4 h3v;
            {
                float c;
                c = sigmoidf_(pf.x+rf.x+bf4.x)*c2v.x + sigmoidf_(pi.x+ri.x+bi.x)*tanhf_(pg.x+rg.x+bg.x);
                h3v.x = sigmoidf_(po.x+ro.x+bo.x)*tanhf_(c);
                c = sigmoidf_(pf.y+rf.y+bf4.y)*c2v.y + sigmoidf_(pi.y+ri.y+bi.y)*tanhf_(pg.y+rg.y+bg.y);
                h3v.y = sigmoidf_(po.y+ro.y+bo.y)*tanhf_(c);
                c = sigmoidf_(pf.z+rf.z+bf4.z)*c2v.z + sigmoidf_(pi.z+ri.z+bi.z)*tanhf_(pg.z+rg.z+bg.z);
                h3v.z = sigmoidf_(po.z+ro.z+bo.z)*tanhf_(c);
                c = sigmoidf_(pf.w+rf.w+bf4.w)*c2v.w + sigmoidf_(pi.w+ri.w+bi.w)*tanhf_(pg.w+rg.w+bg.w);
                h3v.w = sigmoidf_(po.w+ro.w+bo.w)*tanhf_(c);
            }
            bool emit_out = ((grow % 80u)==0u);
            if (l==0){
                if (emit_out) *(float4*)&g_out[grow*600 + 400 + j] = h3v;
                split4(h3v, &g_Ah[grow*K_PAD + 400 + j], &g_Al[grow*K_PAD + 400 + j]);
            } else if (l==1){
                if (emit_out) *(float4*)&g_out[grow*600 + 100 + j] = h3v;
                split4(h3v, &g_Ah[grow*K_PAD + 100 + j], &g_Al[grow*K_PAD + 100 + j]);
            } else {
                *(float4*)&g_op[grow*100 + j] = h3v;
            }
        }
    }
}

// ---------------------------------------------------------------------------
__global__ void __launch_bounds__(256,1) gat1_att(
    const float* __restrict__ a1, float* __restrict__ out_att, float* __restrict__ out2)
{
    __shared__ __align__(16) float a1s[1200];
    __shared__ float ebuf[41];
    __shared__ float att[40];
    __shared__ float red[2];
    int b=blockIdx.x, tid=threadIdx.x, warp=tid>>5, lane=tid&31;
    for (int i=tid;i<1200;i+=256) a1s[i]=a1[i];
    __syncthreads();
    const float* base = g_hG + (size_t)b*24000;
    for (int t=warp;t<41;t+=8){
        const float* rowp = (t<40)? base + t*600 : base;
        const float* av   = (t<40)? a1s         : a1s+600;
        float s=0.f;
        for (int kk=lane;kk<150;kk+=32){
            float4 r4 = *(const float4*)(rowp + kk*4);
            float4 a4 = *(const float4*)(av   + kk*4);
            s += r4.x*a4.x + r4.y*a4.y + r4.z*a4.z + r4.w*a4.w;
        }
        #pragma unroll
        for (int o=16;o;o>>=1) s += __shfl_xor_sync(0xffffffffu, s, o);
        if (lane==0) ebuf[t]=s;
    }
    __syncthreads();
    if (tid<40){
        float x = ebuf[tid] + ebuf[40];
        ebuf[tid] = (x>0.f)? x : 0.2f*x;
    }
    __syncthreads();
    if (tid<32){
        float v = ebuf[tid];
        if (tid<8) v = fmaxf(v, ebuf[tid+32]);
        #pragma unroll
        for (int o=16;o;o>>=1) v = fmaxf(v, __shfl_xor_sync(0xffffffffu, v, o));
        if (tid==0) red[0]=v;
    }
    __syncthreads();
    if (tid<40) att[tid]=__expf(ebuf[tid]-red[0]);
    __syncthreads();
    if (tid<32){
        float v = att[tid] + ((tid<8)? att[tid+32] : 0.f);
        #pragma unroll
        for (int o=16;o;o>>=1) v += __shfl_xor_sync(0xffffffffu, v, o);
        if (tid==0) red[1]=1.f/v;
    }
    __syncthreads();
    if (tid<40) att[tid]=fmaxf(att[tid]*red[1]-0.001f, 0.f);
    __syncthreads();
    for (int f=tid; f<600; f+=256){
        float acc=0.f;
        #pragma unroll 8
        for (int n=0;n<40;n++) acc += att[n]*base[n*600+f];
        out_att[(size_t)b*600+f]=acc;
    }
    if ((b&1)==0){
        const float* srow = g_out + (size_t)b*40*600;
        float* drow = out2 + (size_t)(b>>1)*600;
        for (int f=tid;f<600;f+=256) drow[f]=srow[f];
    }
}

// ---------------------------------------------------------------------------
#define GAT2_SMEM ((4000 + 10000 + 4000)*4)
__global__ void __launch_bounds__(256,1) gat2_kernel(
    const float* __restrict__ W2, const float* __restrict__ a2,
    float* __restrict__ output_att, float* __restrict__ op2)
{
    extern __shared__ float sm[];
    float* ops = sm;
    float* Ws  = ops + 4000;
    float* hg  = Ws  + 10000;
    __shared__ float a2s[200];
    __shared__ float ebuf[41];
    __shared__ float att[40];
    __shared__ float red[2];
    int b=blockIdx.x, tid=threadIdx.x, warp=tid>>5, lane=tid&31;
    const float* src = g_op + (size_t)b*4000;
    for (int i=tid;i<4000;i+=256)  ops[i]=src[i];
    for (int i=tid;i<10000;i+=256) Ws[i]=W2[i];
    if (tid<200) a2s[tid]=a2[tid];
    __syncthreads();
    for (int i=tid;i<4000;i+=256){
        int n=i/100, o=i-n*100;
        float acc=0.f;
        #pragma unroll 4
        for (int k=0;k<100;k++) acc=fmaf(ops[n*100+k], Ws[k*100+o], acc);
        hg[i]=acc;
    }
    __syncthreads();
    for (int t=warp;t<41;t+=8){
        const float* rowp = (t<40)? hg + t*100 : hg;
        const float* av   = (t<40)? a2s        : a2s+100;
        float s=0.f;
        for (int k=lane;k<100;k+=32) s += rowp[k]*av[k];
        #pragma unroll
        for (int o=16;o;o>>=1) s += __shfl_xor_sync(0xffffffffu, s, o);
        if (lane==0) ebuf[t]=s;
    }
    __syncthreads();
    if (tid<40){
        float x = ebuf[tid] + ebuf[40];
        ebuf[tid] = (x>0.f)? x : 0.2f*x;
    }
    __syncthreads();
    if (tid<32){
        float v = ebuf[tid];
        if (tid<8) v = fmaxf(v, ebuf[tid+32]);
        #pragma unroll
        for (int o=16;o;o>>=1) v = fmaxf(v, __shfl_xor_sync(0xffffffffu, v, o));
        if (tid==0) red[0]=v;
    }
    __syncthreads();
    if (tid<40) att[tid]=__expf(ebuf[tid]-red[0]);
    __syncthreads();
    if (tid<32){
        float v = att[tid] + ((tid<8)? att[tid+32] : 0.f);
        #pragma unroll
        for (int o=16;o;o>>=1) v += __shfl_xor_sync(0xffffffffu, v, o);
        if (tid==0) red[1]=1.f/v;
    }
    __syncthreads();
    if (tid<40) att[tid]=fmaxf(att[tid]*red[1]-0.001f, 0.f);
    __syncthreads();
    if (tid<100){
        float acc=0.f;
        #pragma unroll 8
        for (int n=0;n<40;n++) acc += att[n]*hg[n*100+tid];
        output_att[(size_t)b*100+tid]=acc;
    }
    if ((b&1)==0){
        const float* srow = g_op + (size_t)b*40*100;
        float* drow = op2 + (size_t)(b>>1)*100;
        if (tid<100) drow[tid]=srow[tid];
    }
}

// ---------------------------------------------------------------------------
extern "C" void kernel_launch(void* const* d_in, const int* in_sizes, int n_in,
                              void* d_out, int out_size)
{
    const int*   bh    = (const int*)  d_in[0];
    const int*   br    = (const int*)  d_in[1];
    const int*   bt    = (const int*)  d_in[2];
    const float* ent   = (const float*)d_in[3];
    const float* rel   = (const float*)d_in[4];
    const float* ent1  = (const float*)d_in[5];
    const float* rel1  = (const float*)d_in[6];
    const float* Wih_f = (const float*)d_in[7];
    const float* Whh_f = (const float*)d_in[8];
    const float* b_f   = (const float*)d_in[9];
    const float* Wih_b = (const float*)d_in[10];
    const float* Whh_b = (const float*)d_in[11];
    const float* b_b   = (const float*)d_in[12];
    const float* Wih_p = (const float*)d_in[13];
    const float* Whh_p = (const float*)d_in[14];
    const float* b_p   = (const float*)d_in[15];
    const float* W1    = (const float*)d_in[16];
    const float* a1    = (const float*)d_in[17];
    const float* W2    = (const float*)d_in[18];
    const float* a2    = (const float*)d_in[19];

    float* out        = (float*)d_out;
    float* out2       = out;                          // [1024,600]
    float* out_att    = out + 1024*600;               // [2048,600]
    float* op2        = out + 1024*600 + 2048*600;    // [1024,100]
    float* output_att = op2 + 1024*100;               // [2048,100]

    cudaFuncSetAttribute(gat2_kernel, cudaFuncAttributeMaxDynamicSharedMemorySize, GAT2_SMEM);
    cudaFuncSetAttribute(mma_gemm,    cudaFuncAttributeMaxDynamicSharedMemorySize, MM_SMEM);

    convB_kernel<<<(600*600 + 255)/256, 256>>>(W1);
    convW6_kernel<<<(6*400*100 + 255)/256, 256>>>(Whh_f, Whh_b, Whh_p, Wih_f, Wih_b, Wih_p);
    convE_kernel<<<(2*(NENT+NRELS)*100 + 255)/256, 256>>>(ent, ent1, rel, rel1);

    dim3 pe(4, NENT_P/128, 3);
    mma_gemm<<<pe, 256, MM_SMEM>>>(2);
    dim3 pr(4, 2, 3);
    mma_gemm<<<pr, 256, MM_SMEM>>>(3);

    step1_kernel<<<(3*NENT*100 + 255)/256, 256>>>(b_f, b_b, b_p);

    mma_gemm<<<pe, 256, MM_SMEM>>>(4);

    step12_kernel<<<M_TOTAL/64, 256>>>(bh, br, bt, b_f, b_b, b_p);

    dim3 rg(4, M_TOTAL/128, 3);
    mma_gemm<<<rg, 256, MM_SMEM>>>(1);

    step3_kernel<<<M_TOTAL/64, 256>>>(bh, bt, b_f, b_b, b_p);

    dim3 gg(5, M_TOTAL/128, 1);
    mma_gemm<<<gg, 256, MM_SMEM>>>(0);

    gat1_att<<<NGROUP, 256>>>(a1, out_att, out2);

    gat2_kernel<<<NGROUP, 256, GAT2_SMEM>>>(W2, a2, output_att, op2);

    (void)in_sizes; (void)n_in; (void)out_size;
}

// round 7
// speedup vs baseline: 6.7668x; 1.0887x over previous
#include <cuda_runtime.h>
#include <cuda_bf16.h>
#include <math.h>
#include <cstdint>

#define M_TOTAL 81920
#define NGROUP  2048
#define NENT    14541
#define NRELS   237
#define NENT_P  14592   // NENT padded to 128
#define K_PAD   640     // padded K for the 600-wide GEMM
#define K_PAD2  128     // padded K for 100-wide GEMMs

// ---------------- scratch (device globals: no allocation allowed) ----------
__device__ float g_Pe[3][NENT*400];
__device__ float g_Pr[3][NRELS*400];
__device__ float g_h1c1[3][NENT*200];
__device__ float g_R1[3][NENT*400];
__device__ float g_c2[(size_t)3*M_TOTAL*100];
__device__ float g_R2[(size_t)3*M_TOTAL*400];
__device__ float g_out[(size_t)M_TOTAL*600];
__device__ float g_hG [(size_t)M_TOTAL*600];
__device__ float g_op [(size_t)M_TOTAL*100];
// bf16 hi/lo splits (pad regions stay zero from static init; never written)
__device__ __align__(16) __nv_bfloat16 g_Ah[(size_t)M_TOTAL*K_PAD];
__device__ __align__(16) __nv_bfloat16 g_Al[(size_t)M_TOTAL*K_PAD];
__device__ __align__(16) __nv_bfloat16 g_BTh[640*K_PAD];
__device__ __align__(16) __nv_bfloat16 g_BTl[640*K_PAD];
__device__ __align__(16) __nv_bfloat16 g_h2h[(size_t)3*M_TOTAL*K_PAD2];
__device__ __align__(16) __nv_bfloat16 g_h2l[(size_t)3*M_TOTAL*K_PAD2];
// weights: idx 0..2 = Whh f/b/p ; 3..5 = Wih f/b/p  (each [512,128] B^T layout)
__device__ __align__(16) __nv_bfloat16 g_WTh[6][512*K_PAD2];
__device__ __align__(16) __nv_bfloat16 g_WTl[6][512*K_PAD2];
// embedding splits: 0=ent,1=ent1 ; rel: 0=rel,1=rel1
__device__ __align__(16) __nv_bfloat16 g_Eh[2][NENT_P*K_PAD2];
__device__ __align__(16) __nv_bfloat16 g_El[2][NENT_P*K_PAD2];
__device__ __align__(16) __nv_bfloat16 g_Rh[2][256*K_PAD2];
__device__ __align__(16) __nv_bfloat16 g_Rl[2][256*K_PAD2];
// step-1 hidden splits
__device__ __align__(16) __nv_bfloat16 g_h1h[3][NENT_P*K_PAD2];
__device__ __align__(16) __nv_bfloat16 g_h1l[3][NENT_P*K_PAD2];

__device__ __forceinline__ float sigmoidf_(float x){
    return __fdividef(1.f, 1.f + __expf(-x));
}
__device__ __forceinline__ float tanhf_(float x){
    float xc = fminf(fmaxf(x,-15.f),15.f);
    float e = __expf(2.f*xc);
    return __fdividef(e-1.f, e+1.f);
}
__device__ __forceinline__ void split2(float v, __nv_bfloat16* ph, __nv_bfloat16* pl){
    __nv_bfloat16 h = __float2bfloat16(v);
    *ph = h;
    *pl = __float2bfloat16(v - __bfloat162float(h));
}
__device__ __forceinline__ void split4(float4 v, __nv_bfloat16* ph, __nv_bfloat16* pl){
    __nv_bfloat16 h0=__float2bfloat16(v.x), h1=__float2bfloat16(v.y);
    __nv_bfloat16 h2=__float2bfloat16(v.z), h3=__float2bfloat16(v.w);
    __nv_bfloat162 a = {h0,h1}, b = {h2,h3};
    __nv_bfloat162 c = {__float2bfloat16(v.x-__bfloat162float(h0)), __float2bfloat16(v.y-__bfloat162float(h1))};
    __nv_bfloat162 d = {__float2bfloat16(v.z-__bfloat162float(h2)), __float2bfloat16(v.w-__bfloat162float(h3))};
    ((__nv_bfloat162*)ph)[0]=a; ((__nv_bfloat162*)ph)[1]=b;
    ((__nv_bfloat162*)pl)[0]=c; ((__nv_bfloat162*)pl)[1]=d;
}

// ======================= HMMA GEMM plumbing =================================
__device__ __forceinline__ void cp16(unsigned saddr, const void* g){
    asm volatile("cp.async.cg.shared.global [%0], [%1], 16;" :: "r"(saddr), "l"(g));
}
__device__ __forceinline__ void cp_commit(){
    asm volatile("cp.async.commit_group;" ::: "memory");
}
template<int N> __device__ __forceinline__ void cp_wait(){
    asm volatile("cp.async.wait_group %0;" :: "n"(N) : "memory");
}
__device__ __forceinline__ void ldm4(uint32_t* r, unsigned addr){
    asm volatile("ldmatrix.sync.aligned.m8n8.x4.shared.b16 {%0,%1,%2,%3}, [%4];"
        : "=r"(r[0]), "=r"(r[1]), "=r"(r[2]), "=r"(r[3]) : "r"(addr));
}
__device__ __forceinline__ void mma16816(float* d, const uint32_t* a, uint32_t b0, uint32_t b1){
    asm volatile("mma.sync.aligned.m16n8k16.row.col.f32.bf16.bf16.f32 "
        "{%0,%1,%2,%3},{%4,%5,%6,%7},{%8,%9},{%0,%1,%2,%3};"
        : "+f"(d[0]), "+f"(d[1]), "+f"(d[2]), "+f"(d[3])
        : "r"(a[0]), "r"(a[1]), "r"(a[2]), "r"(a[3]), "r"(b0), "r"(b1));
}

// stage layout (48KB): Ah 8K | Al 8K | Bh 16K | Bl 16K
#define STG_BYTES 49152
#define MM_SMEM   (2*STG_BYTES)

__device__ __forceinline__ void stageG(unsigned sb,
    const __nv_bfloat16* Ah, const __nv_bfloat16* Al, size_t lda, int mrow0, int Mv,
    const __nv_bfloat16* Bh, const __nv_bfloat16* Bl, size_t ldb, int ncol0,
    int kcol, int tid)
{
    // A: 64 rows x 64 k
    for (int i=tid;i<512;i+=256){
        int r=i>>3, c=i&7;
        unsigned off = (unsigned)((r*128 + c*16) ^ ((r&7)<<4));
        int ra = mrow0 + r; if (ra >= Mv) ra = Mv-1;
        cp16(sb + off,         Ah + (size_t)ra*lda + kcol + c*8);
        cp16(sb + 8192 + off,  Al + (size_t)ra*lda + kcol + c*8);
    }
    // B: 128 rows x 64 k
    for (int i=tid;i<1024;i+=256){
        int r=i>>3, c=i&7;
        unsigned off = (unsigned)((r*128 + c*16) ^ ((r&7)<<4));
        cp16(sb + 16384 + off,  Bh + (size_t)(ncol0+r)*ldb + kcol + c*8);
        cp16(sb + 32768 + off,  Bl + (size_t)(ncol0+r)*ldb + kcol + c*8);
    }
}

// ---------------------------------------------------------------------------
// mma_gemm: C = A @ B^T with 3-term bf16 split, m16n8k16 HMMA.
// CTA tile 64(M) x 128(N); 2 CTAs/SM.
// which 0: g_hG = out @ W1        1: R2[z] = h2[z] @ Whh_z^T
// which 2: Pe[z] = ent/ent1 @ Wih_z^T   3: Pr[z] = rel/rel1 @ Wih_z^T
// which 4: R1[z] = h1[z] @ Whh_z^T
// ---------------------------------------------------------------------------
__global__ void __launch_bounds__(256,2) mma_gemm(int which)
{
    extern __shared__ char smraw[];
    unsigned sbase;
    asm("{ .reg .u64 t; cvta.to.shared.u64 t, %1; cvt.u32.u64 %0, t; }" : "=r"(sbase) : "l"(smraw));

    const __nv_bfloat16 *Ah,*Al,*Bh,*Bl; float* C;
    int Mv, Nv, ldc, nch; size_t lda, ldb;
    int z = blockIdx.z;
    switch (which){
      case 0:
        Ah=g_Ah; Al=g_Al; Bh=g_BTh; Bl=g_BTl; C=g_hG;
        Mv=M_TOTAL; Nv=600; ldc=600; nch=10; lda=K_PAD; ldb=K_PAD; break;
      case 1:
        Ah=g_h2h+(size_t)z*M_TOTAL*K_PAD2; Al=g_h2l+(size_t)z*M_TOTAL*K_PAD2;
        Bh=g_WTh[z]; Bl=g_WTl[z]; C=g_R2+(size_t)z*M_TOTAL*400;
        Mv=M_TOTAL; Nv=400; ldc=400; nch=2; lda=K_PAD2; ldb=K_PAD2; break;
      case 2: {
        int e = (z==2)? 1 : 0;
        Ah=g_Eh[e]; Al=g_El[e]; Bh=g_WTh[3+z]; Bl=g_WTl[3+z]; C=g_Pe[z];
        Mv=NENT; Nv=400; ldc=400; nch=2; lda=K_PAD2; ldb=K_PAD2; break; }
      case 3: {
        int e = (z==2)? 1 : 0;
        Ah=g_Rh[e]; Al=g_Rl[e]; Bh=g_WTh[3+z]; Bl=g_WTl[3+z]; C=g_Pr[z];
        Mv=NRELS; Nv=400; ldc=400; nch=2; lda=K_PAD2; ldb=K_PAD2; break; }
      default:
        Ah=g_h1h[z]; Al=g_h1l[z]; Bh=g_WTh[z]; Bl=g_WTl[z]; C=g_R1[z];
        Mv=NENT; Nv=400; ldc=400; nch=2; lda=K_PAD2; ldb=K_PAD2; break;
    }
    int tid=threadIdx.x, wid=tid>>5, lane=tid&31;
    int wm = wid & 1, wn = wid >> 1;            // warps: 2(M) x 4(N)
    int ncol0 = blockIdx.x*128, mrow0 = blockIdx.y*64;

    float acc[2][4][4];
    #pragma unroll
    for (int i=0;i<2;i++)
        #pragma unroll
        for (int j=0;j<4;j++)
            #pragma unroll
            for (int q=0;q<4;q++) acc[i][j][q]=0.f;

    stageG(sbase,             Ah,Al,lda,mrow0,Mv, Bh,Bl,ldb,ncol0, 0,  tid); cp_commit();
    stageG(sbase + STG_BYTES, Ah,Al,lda,mrow0,Mv, Bh,Bl,ldb,ncol0, 64, tid); cp_commit();

    int lr  = lane & 15;
    int lhb = (lane >> 4) << 4;

    for (int k=0;k<nch;k++){
        if (k < nch-1) cp_wait<1>(); else cp_wait<0>();
        __syncthreads();
        unsigned st = sbase + (unsigned)(k&1)*STG_BYTES;
        unsigned sAh = st, sAl = st+8192, sBh = st+16384, sBl = st+32768;

        #pragma unroll
        for (int kk=0;kk<4;kk++){
            int cb = kk*32 + lhb;
            uint32_t ah[2][4], al[2][4], bh[2][4], bl[2][4];
            #pragma unroll
            for (int mt=0;mt<2;mt++){
                int r = wm*32 + mt*16 + lr;
                unsigned off = (unsigned)((r*128 + cb) ^ ((r&7)<<4));
                ldm4(ah[mt], sAh + off);
                ldm4(al[mt], sAl + off);
            }
            #pragma unroll
            for (int ng=0;ng<2;ng++){
                int n = wn*32 + ng*16 + lr;
                unsigned off = (unsigned)((n*128 + cb) ^ ((n&7)<<4));
                ldm4(bh[ng], sBh + off);
                ldm4(bl[ng], sBl + off);
            }
            #pragma unroll
            for (int mt=0;mt<2;mt++){
                #pragma unroll
                for (int nt=0;nt<4;nt++){
                    int ng = nt>>1, s = nt&1;
                    mma16816(acc[mt][nt], ah[mt], bh[ng][s], bh[ng][s+2]);
                    mma16816(acc[mt][nt], ah[mt], bl[ng][s], bl[ng][s+2]);
                    mma16816(acc[mt][nt], al[mt], bh[ng][s], bh[ng][s+2]);
                }
            }
        }
        __syncthreads();
        if (k+2 < nch){
            stageG(st, Ah,Al,lda,mrow0,Mv, Bh,Bl,ldb,ncol0, (k+2)*64, tid);
            cp_commit();
        }
    }

    #pragma unroll
    for (int mt=0;mt<2;mt++){
        int rbase = mrow0 + wm*32 + mt*16 + (lane>>2);
        #pragma unroll
        for (int nt=0;nt<4;nt++){
            int col = ncol0 + wn*32 + nt*8 + (lane&3)*2;
            if (col < Nv){
                if (rbase < Mv)
                    *(float2*)(C + (size_t)rbase*ldc + col)     = make_float2(acc[mt][nt][0], acc[mt][nt][1]);
                if (rbase+8 < Mv)
                    *(float2*)(C + (size_t)(rbase+8)*ldc + col) = make_float2(acc[mt][nt][2], acc[mt][nt][3]);
            }
        }
    }
}

// ---------------------------------------------------------------------------
// conversions
// ---------------------------------------------------------------------------
__global__ void convB_kernel(const float* __restrict__ W1)
{
    int i = blockIdx.x*256 + threadIdx.x;
    if (i >= 600*600) return;
    int n = i / 600, k = i - n*600;
    split2(W1[(size_t)k*600 + n], &g_BTh[(size_t)n*K_PAD + k], &g_BTl[(size_t)n*K_PAD + k]);
}
__global__ void convW6_kernel(const float* __restrict__ Whf, const float* __restrict__ Whb,
                              const float* __restrict__ Whp, const float* __restrict__ Wif,
                              const float* __restrict__ Wib, const float* __restrict__ Wip)
{
    int i = blockIdx.x*256 + threadIdx.x;
    if (i >= 6*400*100) return;
    int m = i / 40000; int rem = i - m*40000;
    int n = rem/100, k = rem - n*100;
    const float* W;
    switch(m){ case 0:W=Whf;break; case 1:W=Whb;break; case 2:W=Whp;break;
               case 3:W=Wif;break; case 4:W=Wib;break; default:W=Wip;break; }
    split2(W[n*100+k], &g_WTh[m][n*K_PAD2 + k], &g_WTl[m][n*K_PAD2 + k]);
}
__global__ void convE_kernel(const float* __restrict__ ent, const float* __restrict__ ent1,
                             const float* __restrict__ rel, const float* __restrict__ rel1)
{
    int i = blockIdx.x*256 + threadIdx.x;
    if (i < 2*NENT*100){
        int e = i / (NENT*100); int rem = i - e*(NENT*100);
        int r = rem/100, k = rem - r*100;
        const float* src = e ? ent1 : ent;
        split2(src[(size_t)r*100+k], &g_Eh[e][(size_t)r*K_PAD2+k], &g_El[e][(size_t)r*K_PAD2+k]);
    } else {
        int j = i - 2*NENT*100;
        if (j >= 2*NRELS*100) return;
        int e = j / (NRELS*100); int rem = j - e*(NRELS*100);
        int r = rem/100, k = rem - r*100;
        const float* src = e ? rel1 : rel;
        split2(src[(size_t)r*100+k], &g_Rh[e][(size_t)r*K_PAD2+k], &g_Rl[e][(size_t)r*K_PAD2+k]);
    }
}

// ---------------------------------------------------------------------------
__global__ void step1_kernel(const float* __restrict__ b_f,
                             const float* __restrict__ b_b,
                             const float* __restrict__ b_p)
{
    int idx = blockIdx.x*256 + threadIdx.x;
    if (idx >= 3*NENT*100) return;
    int l   = idx / (NENT*100);
    int rem = idx - l*(NENT*100);
    int e = rem/100, j = rem - e*100;
    const float* P = g_Pe[l] + (size_t)e*400;
    const float* b = (l==0)? b_f : (l==1)? b_b : b_p;
    float iv = P[j]     + b[j];
    float gv = P[200+j] + b[200+j];
    float ov = P[300+j] + b[300+j];
    float c1 = sigmoidf_(iv) * tanhf_(gv);
    float h1 = sigmoidf_(ov) * tanhf_(c1);
    g_h1c1[l][(size_t)e*200 + j]       = h1;
    g_h1c1[l][(size_t)e*200 + 100 + j] = c1;
    split2(h1, &g_h1h[l][(size_t)e*K_PAD2 + j], &g_h1l[l][(size_t)e*K_PAD2 + j]);
}

// ---------------------------------------------------------------------------
__global__ void __launch_bounds__(256) step12_kernel(
    const int* __restrict__ bh, const int* __restrict__ br, const int* __restrict__ bt,
    const float* __restrict__ b_f, const float* __restrict__ b_b, const float* __restrict__ b_p)
{
    __shared__ int ih[64], ir[64], it[64];
    int tid=threadIdx.x; int row0=blockIdx.x*64;
    if (tid<64)        ih[tid]     = bh[row0+tid];
    else if (tid<128)  ir[tid-64]  = br[row0+tid-64];
    else if (tid<192)  it[tid-128] = bt[row0+tid-128];
    __syncthreads();
    for (int l=0;l<3;l++){
        const float* Pr  = g_Pr[l];
        const float* R1  = g_R1[l];
        const float* HC  = g_h1c1[l];
        const float* bias= (l==0)?b_f:(l==1)?b_b:b_p;
        for (int t=tid;t<1600;t+=256){
            int row=t/25, q=t-row*25; int j=q*4;
            int fi = (l==1)? it[row] : ih[row];
            size_t grow=(size_t)(row0+row);
            bool emit_out = ((grow % 80u)==0u) && (l<2);
            float4 h1v = *(const float4*)&HC[(size_t)fi*200 + j];
            float4 c1v = *(const float4*)&HC[(size_t)fi*200 + 100 + j];
            if (l==0){
                if (emit_out) *(float4*)&g_out[grow*600 + j] = h1v;
                split4(h1v, &g_Ah[grow*K_PAD + j], &g_Al[grow*K_PAD + j]);
            } else if (l==1){
                if (emit_out) *(float4*)&g_out[grow*600 + 500 + j] = h1v;
                split4(h1v, &g_Ah[grow*K_PAD + 500 + j], &g_Al[grow*K_PAD + 500 + j]);
            }
            const float* pr = Pr + (size_t)ir[row]*400;
            const float* r1 = R1 + (size_t)fi*400;
            float4 pi = *(const float4*)&pr[j],      ri = *(const float4*)&r1[j];
            float4 pf = *(const float4*)&pr[100+j],  rf = *(const float4*)&r1[100+j];
            float4 pg = *(const float4*)&pr[200+j],  rg = *(const float4*)&r1[200+j];
            float4 po = *(const float4*)&pr[300+j],  ro = *(const float4*)&r1[300+j];
            float4 bi = *(const float4*)&bias[j],    bf4= *(const float4*)&bias[100+j];
            float4 bg = *(const float4*)&bias[200+j],bo = *(const float4*)&bias[300+j];
            float4 c2v, h2v;
            {
                float c,h;
                c = sigmoidf_(pf.x+rf.x+bf4.x)*c1v.x + sigmoidf_(pi.x+ri.x+bi.x)*tanhf_(pg.x+rg.x+bg.x);
                h = sigmoidf_(po.x+ro.x+bo.x)*tanhf_(c); c2v.x=c; h2v.x=h;
                c = sigmoidf_(pf.y+rf.y+bf4.y)*c1v.y + sigmoidf_(pi.y+ri.y+bi.y)*tanhf_(pg.y+rg.y+bg.y);
                h = sigmoidf_(po.y+ro.y+bo.y)*tanhf_(c); c2v.y=c; h2v.y=h;
                c = sigmoidf_(pf.z+rf.z+bf4.z)*c1v.z + sigmoidf_(pi.z+ri.z+bi.z)*tanhf_(pg.z+rg.z+bg.z);
                h = sigmoidf_(po.z+ro.z+bo.z)*tanhf_(c); c2v.z=c; h2v.z=h;
                c = sigmoidf_(pf.w+rf.w+bf4.w)*c1v.w + sigmoidf_(pi.w+ri.w+bi.w)*tanhf_(pg.w+rg.w+bg.w);
                h = sigmoidf_(po.w+ro.w+bo.w)*tanhf_(c); c2v.w=c; h2v.w=h;
            }
            size_t hidx = (size_t)l*M_TOTAL*K_PAD2 + grow*K_PAD2 + j;
            split4(h2v, &g_h2h[hidx], &g_h2l[hidx]);
            *(float4*)&g_c2[(size_t)l*M_TOTAL*100 + grow*100 + j] = c2v;
            if (l==0){
                if (emit_out) *(float4*)&g_out[grow*600 + 200 + j] = h2v;
                split4(h2v, &g_Ah[grow*K_PAD + 200 + j], &g_Al[grow*K_PAD + 200 + j]);
            } else if (l==1){
                if (emit_out) *(float4*)&g_out[grow*600 + 300 + j] = h2v;
                split4(h2v, &g_Ah[grow*K_PAD + 300 + j], &g_Al[grow*K_PAD + 300 + j]);
            }
        }
    }
}

// ---------------------------------------------------------------------------
__global__ void __launch_bounds__(256) step3_kernel(
    const int* __restrict__ bh, const int* __restrict__ bt,
    const float* __restrict__ b_f, const float* __restrict__ b_b, const float* __restrict__ b_p)
{
    __shared__ int ih[64], it[64];
    int tid=threadIdx.x; int row0=blockIdx.x*64;
    if (tid<64)        ih[tid]    = bh[row0+tid];
    else if (tid<128)  it[tid-64] = bt[row0+tid-64];
    __syncthreads();
    for (int l=0;l<3;l++){
        const float* Pe  = g_Pe[l];
        const float* R2  = g_R2 + (size_t)l*M_TOTAL*400;
        const float* C2  = g_c2 + (size_t)l*M_TOTAL*100;
        const float* bias= (l==0)?b_f:(l==1)?b_b:b_p;
        for (int t=tid;t<1600;t+=256){
            int row=t/25, q=t-row*25; int j=q*4;
            int li = (l==1)? ih[row] : it[row];
            size_t grow=(size_t)(row0+row);
            const float* pe = Pe + (size_t)li*400;
            const float* r2 = R2 + grow*400;
            float4 pi = *(const float4*)&pe[j],      ri = *(const float4*)&r2[j];
            float4 pf = *(const float4*)&pe[100+j],  rf = *(const float4*)&r2[100+j];
            float4 pg = *(const float4*)&pe[200+j],  rg = *(const float4*)&r2[200+j];
            float4 po = *(const float4*)&pe[300+j],  ro = *(const float4*)&r2[300+j];
            float4 bi = *(const float4*)&bias[j],    bf4= *(const float4*)&bias[100+j];
            float4 bg = *(const float4*)&bias[200+j],bo = *(const float4*)&bias[300+j];
            float4 c2v = *(const float4*)&C2[grow*100 + j];
            float4 h3v;
            {
                float c;
                c = sigmoidf_(pf.x+rf.x+bf4.x)*c2v.x + sigmoidf_(pi.x+ri.x+bi.x)*tanhf_(pg.x+rg.x+bg.x);
                h3v.x = sigmoidf_(po.x+ro.x+bo.x)*tanhf_(c);
                c = sigmoidf_(pf.y+rf.y+bf4.y)*c2v.y + sigmoidf_(pi.y+ri.y+bi.y)*tanhf_(pg.y+rg.y+bg.y);
                h3v.y = sigmoidf_(po.y+ro.y+bo.y)*tanhf_(c);
                c = sigmoidf_(pf.z+rf.z+bf4.z)*c2v.z + sigmoidf_(pi.z+ri.z+bi.z)*tanhf_(pg.z+rg.z+bg.z);
                h3v.z = sigmoidf_(po.z+ro.z+bo.z)*tanhf_(c);
                c = sigmoidf_(pf.w+rf.w+bf4.w)*c2v.w + sigmoidf_(pi.w+ri.w+bi.w)*tanhf_(pg.w+rg.w+bg.w);
                h3v.w = sigmoidf_(po.w+ro.w+bo.w)*tanhf_(c);
            }
            bool emit_out = ((grow % 80u)==0u);
            if (l==0){
                if (emit_out) *(float4*)&g_out[grow*600 + 400 + j] = h3v;
                split4(h3v, &g_Ah[grow*K_PAD + 400 + j], &g_Al[grow*K_PAD + 400 + j]);
            } else if (l==1){
                if (emit_out) *(float4*)&g_out[grow*600 + 100 + j] = h3v;
                split4(h3v, &g_Ah[grow*K_PAD + 100 + j], &g_Al[grow*K_PAD + 100 + j]);
            } else {
                *(float4*)&g_op[grow*100 + j] = h3v;
            }
        }
    }
}

// ---------------------------------------------------------------------------
__global__ void __launch_bounds__(256,1) gat1_att(
    const float* __restrict__ a1, float* __restrict__ out_att, float* __restrict__ out2)
{
    __shared__ __align__(16) float a1s[1200];
    __shared__ float ebuf[41];
    __shared__ float att[40];
    __shared__ float red[2];
    int b=blockIdx.x, tid=threadIdx.x, warp=tid>>5, lane=tid&31;
    for (int i=tid;i<1200;i+=256) a1s[i]=a1[i];
    __syncthreads();
    const float* base = g_hG + (size_t)b*24000;
    for (int t=warp;t<41;t+=8){
        const float* rowp = (t<40)? base + t*600 : base;
        const float* av   = (t<40)? a1s         : a1s+600;
        float s=0.f;
        for (int kk=lane;kk<150;kk+=32){
            float4 r4 = *(const float4*)(rowp + kk*4);
            float4 a4 = *(const float4*)(av   + kk*4);
            s += r4.x*a4.x + r4.y*a4.y + r4.z*a4.z + r4.w*a4.w;
        }
        #pragma unroll
        for (int o=16;o;o>>=1) s += __shfl_xor_sync(0xffffffffu, s, o);
        if (lane==0) ebuf[t]=s;
    }
    __syncthreads();
    if (tid<40){
        float x = ebuf[tid] + ebuf[40];
        ebuf[tid] = (x>0.f)? x : 0.2f*x;
    }
    __syncthreads();
    if (tid<32){
        float v = ebuf[tid];
        if (tid<8) v = fmaxf(v, ebuf[tid+32]);
        #pragma unroll
        for (int o=16;o;o>>=1) v = fmaxf(v, __shfl_xor_sync(0xffffffffu, v, o));
        if (tid==0) red[0]=v;
    }
    __syncthreads();
    if (tid<40) att[tid]=__expf(ebuf[tid]-red[0]);
    __syncthreads();
    if (tid<32){
        float v = att[tid] + ((tid<8)? att[tid+32] : 0.f);
        #pragma unroll
        for (int o=16;o;o>>=1) v += __shfl_xor_sync(0xffffffffu, v, o);
        if (tid==0) red[1]=1.f/v;
    }
    __syncthreads();
    if (tid<40) att[tid]=fmaxf(att[tid]*red[1]-0.001f, 0.f);
    __syncthreads();
    for (int f=tid; f<600; f+=256){
        float acc=0.f;
        #pragma unroll 8
        for (int n=0;n<40;n++) acc += att[n]*base[n*600+f];
        out_att[(size_t)b*600+f]=acc;
    }
    if ((b&1)==0){
        const float* srow = g_out + (size_t)b*40*600;
        float* drow = out2 + (size_t)(b>>1)*600;
        for (int f=tid;f<600;f+=256) drow[f]=srow[f];
    }
}

// ---------------------------------------------------------------------------
#define GAT2_SMEM ((4000 + 10000 + 4000)*4)
__global__ void __launch_bounds__(256,1) gat2_kernel(
    const float* __restrict__ W2, const float* __restrict__ a2,
    float* __restrict__ output_att, float* __restrict__ op2)
{
    extern __shared__ float sm[];
    float* ops = sm;
    float* Ws  = ops + 4000;
    float* hg  = Ws  + 10000;
    __shared__ float a2s[200];
    __shared__ float ebuf[41];
    __shared__ float att[40];
    __shared__ float red[2];
    int b=blockIdx.x, tid=threadIdx.x, warp=tid>>5, lane=tid&31;
    const float* src = g_op + (size_t)b*4000;
    for (int i=tid;i<4000;i+=256)  ops[i]=src[i];
    for (int i=tid;i<10000;i+=256) Ws[i]=W2[i];
    if (tid<200) a2s[tid]=a2[tid];
    __syncthreads();
    for (int i=tid;i<4000;i+=256){
        int n=i/100, o=i-n*100;
        float acc=0.f;
        #pragma unroll 4
        for (int k=0;k<100;k++) acc=fmaf(ops[n*100+k], Ws[k*100+o], acc);
        hg[i]=acc;
    }
    __syncthreads();
    for (int t=warp;t<41;t+=8){
        const float* rowp = (t<40)? hg + t*100 : hg;
        const float* av   = (t<40)? a2s        : a2s+100;
        float s=0.f;
        for (int k=lane;k<100;k+=32) s += rowp[k]*av[k];
        #pragma unroll
        for (int o=16;o;o>>=1) s += __shfl_xor_sync(0xffffffffu, s, o);
        if (lane==0) ebuf[t]=s;
    }
    __syncthreads();
    if (tid<40){
        float x = ebuf[tid] + ebuf[40];
        ebuf[tid] = (x>0.f)? x : 0.2f*x;
    }
    __syncthreads();
    if (tid<32){
        float v = ebuf[tid];
        if (tid<8) v = fmaxf(v, ebuf[tid+32]);
        #pragma unroll
        for (int o=16;o;o>>=1) v = fmaxf(v, __shfl_xor_sync(0xffffffffu, v, o));
        if (tid==0) red[0]=v;
    }
    __syncthreads();
    if (tid<40) att[tid]=__expf(ebuf[tid]-red[0]);
    __syncthreads();
    if (tid<32){
        float v = att[tid] + ((tid<8)? att[tid+32] : 0.f);
        #pragma unroll
        for (int o=16;o;o>>=1) v += __shfl_xor_sync(0xffffffffu, v, o);
        if (tid==0) red[1]=1.f/v;
    }
    __syncthreads();
    if (tid<40) att[tid]=fmaxf(att[tid]*red[1]-0.001f, 0.f);
    __syncthreads();
    if (tid<100){
        float acc=0.f;
        #pragma unroll 8
        for (int n=0;n<40;n++) acc += att[n]*hg[n*100+tid];
        output_att[(size_t)b*100+tid]=acc;
    }
    if ((b&1)==0){
        const float* srow = g_op + (size_t)b*40*100;
        float* drow = op2 + (size_t)(b>>1)*100;
        if (tid<100) drow[tid]=srow[tid];
    }
}

// ---------------------------------------------------------------------------
extern "C" void kernel_launch(void* const* d_in, const int* in_sizes, int n_in,
                              void* d_out, int out_size)
{
    const int*   bh    = (const int*)  d_in[0];
    const int*   br    = (const int*)  d_in[1];
    const int*   bt    = (const int*)  d_in[2];
    const float* ent   = (const float*)d_in[3];
    const float* rel   = (const float*)d_in[4];
    const float* ent1  = (const float*)d_in[5];
    const float* rel1  = (const float*)d_in[6];
    const float* Wih_f = (const float*)d_in[7];
    const float* Whh_f = (const float*)d_in[8];
    const float* b_f   = (const float*)d_in[9];
    const float* Wih_b = (const float*)d_in[10];
    const float* Whh_b = (const float*)d_in[11];
    const float* b_b   = (const float*)d_in[12];
    const float* Wih_p = (const float*)d_in[13];
    const float* Whh_p = (const float*)d_in[14];
    const float* b_p   = (const float*)d_in[15];
    const float* W1    = (const float*)d_in[16];
    const float* a1    = (const float*)d_in[17];
    const float* W2    = (const float*)d_in[18];
    const float* a2    = (const float*)d_in[19];

    float* out        = (float*)d_out;
    float* out2       = out;                          // [1024,600]
    float* out_att    = out + 1024*600;               // [2048,600]
    float* op2        = out + 1024*600 + 2048*600;    // [1024,100]
    float* output_att = op2 + 1024*100;               // [2048,100]

    cudaFuncSetAttribute(gat2_kernel, cudaFuncAttributeMaxDynamicSharedMemorySize, GAT2_SMEM);
    cudaFuncSetAttribute(mma_gemm,    cudaFuncAttributeMaxDynamicSharedMemorySize, MM_SMEM);

    convB_kernel<<<(600*600 + 255)/256, 256>>>(W1);
    convW6_kernel<<<(6*400*100 + 255)/256, 256>>>(Whh_f, Whh_b, Whh_p, Wih_f, Wih_b, Wih_p);
    convE_kernel<<<(2*(NENT+NRELS)*100 + 255)/256, 256>>>(ent, ent1, rel, rel1);

    dim3 pe(4, NENT_P/64, 3);
    mma_gemm<<<pe, 256, MM_SMEM>>>(2);
    dim3 pr(4, 4, 3);
    mma_gemm<<<pr, 256, MM_SMEM>>>(3);

    step1_kernel<<<(3*NENT*100 + 255)/256, 256>>>(b_f, b_b, b_p);

    mma_gemm<<<pe, 256, MM_SMEM>>>(4);

    step12_kernel<<<M_TOTAL/64, 256>>>(bh, br, bt, b_f, b_b, b_p);

    dim3 rg(4, M_TOTAL/64, 3);
    mma_gemm<<<rg, 256, MM_SMEM>>>(1);

    step3_kernel<<<M_TOTAL/64, 256>>>(bh, bt, b_f, b_b, b_p);

    dim3 gg(5, M_TOTAL/64, 1);
    mma_gemm<<<gg, 256, MM_SMEM>>>(0);

    gat1_att<<<NGROUP, 256>>>(a1, out_att, out2);

    gat2_kernel<<<NGROUP, 256, GAT2_SMEM>>>(W2, a2, output_att, op2);

    (void)in_sizes; (void)n_in; (void)out_size;
}

// round 8
// speedup vs baseline: 8.9417x; 1.3214x over previous
#include <cuda_runtime.h>
#include <cuda_bf16.h>
#include <cuda_fp16.h>
#include <math.h>
#include <cstdint>

#define M_TOTAL 81920
#define NGROUP  2048
#define NENT    14541
#define NRELS   237
#define NENT_P  14592   // NENT padded to 128
#define K_PAD   640     // padded K for the 600-wide GEMM
#define K_PAD2  128     // padded K for 100-wide GEMMs

// ---------------- scratch (device globals: no allocation allowed) ----------
__device__ float g_Pe[3][NENT*400];
__device__ float g_Pr[3][NRELS*400];
__device__ float g_h1c1[3][NENT*200];
__device__ float g_R1[3][NENT*400];
__device__ float g_c2[(size_t)3*M_TOTAL*100];
__device__ float g_R2[(size_t)3*M_TOTAL*400];
__device__ float g_out[(size_t)M_TOTAL*600];
__device__ float g_hG [(size_t)M_TOTAL*600];
__device__ float g_op [(size_t)M_TOTAL*100];
// fp16 operands for the big GEMM (pads stay zero)
__device__ __align__(16) __half g_Af[(size_t)M_TOTAL*K_PAD];
__device__ __align__(16) __half g_BTf[640*K_PAD];
// bf16 hi/lo splits for the precise small GEMMs
__device__ __align__(16) __nv_bfloat16 g_h2h[(size_t)3*M_TOTAL*K_PAD2];
__device__ __align__(16) __nv_bfloat16 g_h2l[(size_t)3*M_TOTAL*K_PAD2];
__device__ __align__(16) __nv_bfloat16 g_WTh[6][512*K_PAD2];
__device__ __align__(16) __nv_bfloat16 g_WTl[6][512*K_PAD2];
__device__ __align__(16) __nv_bfloat16 g_Eh[2][NENT_P*K_PAD2];
__device__ __align__(16) __nv_bfloat16 g_El[2][NENT_P*K_PAD2];
__device__ __align__(16) __nv_bfloat16 g_Rh[2][256*K_PAD2];
__device__ __align__(16) __nv_bfloat16 g_Rl[2][256*K_PAD2];
__device__ __align__(16) __nv_bfloat16 g_h1h[3][NENT_P*K_PAD2];
__device__ __align__(16) __nv_bfloat16 g_h1l[3][NENT_P*K_PAD2];

__device__ __forceinline__ float sigmoidf_(float x){
    return __fdividef(1.f, 1.f + __expf(-x));
}
__device__ __forceinline__ float tanhf_(float x){
    float xc = fminf(fmaxf(x,-15.f),15.f);
    float e = __expf(2.f*xc);
    return __fdividef(e-1.f, e+1.f);
}
__device__ __forceinline__ void split2(float v, __nv_bfloat16* ph, __nv_bfloat16* pl){
    __nv_bfloat16 h = __float2bfloat16(v);
    *ph = h;
    *pl = __float2bfloat16(v - __bfloat162float(h));
}
__device__ __forceinline__ void split4(float4 v, __nv_bfloat16* ph, __nv_bfloat16* pl){
    __nv_bfloat16 h0=__float2bfloat16(v.x), h1=__float2bfloat16(v.y);
    __nv_bfloat16 h2=__float2bfloat16(v.z), h3=__float2bfloat16(v.w);
    __nv_bfloat162 a = {h0,h1}, b = {h2,h3};
    __nv_bfloat162 c = {__float2bfloat16(v.x-__bfloat162float(h0)), __float2bfloat16(v.y-__bfloat162float(h1))};
    __nv_bfloat162 d = {__float2bfloat16(v.z-__bfloat162float(h2)), __float2bfloat16(v.w-__bfloat162float(h3))};
    ((__nv_bfloat162*)ph)[0]=a; ((__nv_bfloat162*)ph)[1]=b;
    ((__nv_bfloat162*)pl)[0]=c; ((__nv_bfloat162*)pl)[1]=d;
}
__device__ __forceinline__ void storeh4(float4 v, __half* p){
    __half2 a = __floats2half2_rn(v.x, v.y);
    __half2 b = __floats2half2_rn(v.z, v.w);
    ((__half2*)p)[0]=a; ((__half2*)p)[1]=b;
}

// ======================= MMA plumbing =======================================
__device__ __forceinline__ void cp16(unsigned saddr, const void* g){
    asm volatile("cp.async.cg.shared.global [%0], [%1], 16;" :: "r"(saddr), "l"(g));
}
__device__ __forceinline__ void cp_commit(){
    asm volatile("cp.async.commit_group;" ::: "memory");
}
template<int N> __device__ __forceinline__ void cp_wait(){
    asm volatile("cp.async.wait_group %0;" :: "n"(N) : "memory");
}
__device__ __forceinline__ void ldm4(uint32_t* r, unsigned addr){
    asm volatile("ldmatrix.sync.aligned.m8n8.x4.shared.b16 {%0,%1,%2,%3}, [%4];"
        : "=r"(r[0]), "=r"(r[1]), "=r"(r[2]), "=r"(r[3]) : "r"(addr));
}
__device__ __forceinline__ void mma16816(float* d, const uint32_t* a, uint32_t b0, uint32_t b1){
    asm volatile("mma.sync.aligned.m16n8k16.row.col.f32.bf16.bf16.f32 "
        "{%0,%1,%2,%3},{%4,%5,%6,%7},{%8,%9},{%0,%1,%2,%3};"
        : "+f"(d[0]), "+f"(d[1]), "+f"(d[2]), "+f"(d[3])
        : "r"(a[0]), "r"(a[1]), "r"(a[2]), "r"(a[3]), "r"(b0), "r"(b1));
}
__device__ __forceinline__ void mma16816h(float* d, const uint32_t* a, uint32_t b0, uint32_t b1){
    asm volatile("mma.sync.aligned.m16n8k16.row.col.f32.f16.f16.f32 "
        "{%0,%1,%2,%3},{%4,%5,%6,%7},{%8,%9},{%0,%1,%2,%3};"
        : "+f"(d[0]), "+f"(d[1]), "+f"(d[2]), "+f"(d[3])
        : "r"(a[0]), "r"(a[1]), "r"(a[2]), "r"(a[3]), "r"(b0), "r"(b1));
}

// ======================= fp16 single-pass GEMM (g_hG) =======================
// tile 64(M) x 128(N), stage 24KB (A 8K | B 16K), 2 stages, 3 CTAs/SM.
#define STG_F16 24576
#define MMF_SMEM (2*STG_F16)

__device__ __forceinline__ void stageF(unsigned sb, int mrow0, int ncol0, int kcol, int tid){
    const __half* A = g_Af + (size_t)mrow0*K_PAD + kcol;
    const __half* B = g_BTf + (size_t)ncol0*K_PAD + kcol;
    for (int i=tid;i<512;i+=256){
        int r=i>>3, c=i&7;
        unsigned off = (unsigned)((r*128 + c*16) ^ ((r&7)<<4));
        cp16(sb + off, A + (size_t)r*K_PAD + c*8);
    }
    for (int i=tid;i<1024;i+=256){
        int r=i>>3, c=i&7;
        unsigned off = (unsigned)((r*128 + c*16) ^ ((r&7)<<4));
        cp16(sb + 8192 + off, B + (size_t)r*K_PAD + c*8);
    }
}

__global__ void __launch_bounds__(256,3) mma_f16()
{
    extern __shared__ char smraw[];
    unsigned sbase;
    asm("{ .reg .u64 t; cvta.to.shared.u64 t, %1; cvt.u32.u64 %0, t; }" : "=r"(sbase) : "l"(smraw));
    int tid=threadIdx.x, wid=tid>>5, lane=tid&31;
    int wm = wid & 1, wn = wid >> 1;
    int ncol0 = blockIdx.x*128, mrow0 = blockIdx.y*64;

    float acc[2][4][4];
    #pragma unroll
    for (int i=0;i<2;i++)
        #pragma unroll
        for (int j=0;j<4;j++)
            #pragma unroll
            for (int q=0;q<4;q++) acc[i][j][q]=0.f;

    stageF(sbase,           mrow0, ncol0, 0,  tid); cp_commit();
    stageF(sbase + STG_F16, mrow0, ncol0, 64, tid); cp_commit();

    int lr  = lane & 15;
    int lhb = (lane >> 4) << 4;

    for (int k=0;k<10;k++){
        if (k < 9) cp_wait<1>(); else cp_wait<0>();
        __syncthreads();
        unsigned st = sbase + (unsigned)(k&1)*STG_F16;
        unsigned sA = st, sB = st+8192;
        #pragma unroll
        for (int kk=0;kk<4;kk++){
            int cb = kk*32 + lhb;
            uint32_t ah[2][4], bb[2][4];
            #pragma unroll
            for (int mt=0;mt<2;mt++){
                int r = wm*32 + mt*16 + lr;
                unsigned off = (unsigned)((r*128 + cb) ^ ((r&7)<<4));
                ldm4(ah[mt], sA + off);
            }
            #pragma unroll
            for (int ng=0;ng<2;ng++){
                int n = wn*32 + ng*16 + lr;
                unsigned off = (unsigned)((n*128 + cb) ^ ((n&7)<<4));
                ldm4(bb[ng], sB + off);
            }
            #pragma unroll
            for (int mt=0;mt<2;mt++){
                #pragma unroll
                for (int nt=0;nt<4;nt++){
                    int ng = nt>>1, s = nt&1;
                    mma16816h(acc[mt][nt], ah[mt], bb[ng][s], bb[ng][s+2]);
                }
            }
        }
        __syncthreads();
        if (k+2 < 10){
            stageF(st, mrow0, ncol0, (k+2)*64, tid);
            cp_commit();
        }
    }
    #pragma unroll
    for (int mt=0;mt<2;mt++){
        int rbase = mrow0 + wm*32 + mt*16 + (lane>>2);
        #pragma unroll
        for (int nt=0;nt<4;nt++){
            int col = ncol0 + wn*32 + nt*8 + (lane&3)*2;
            if (col < 600){
                *(float2*)(g_hG + (size_t)rbase*600 + col)     = make_float2(acc[mt][nt][0], acc[mt][nt][1]);
                *(float2*)(g_hG + (size_t)(rbase+8)*600 + col) = make_float2(acc[mt][nt][2], acc[mt][nt][3]);
            }
        }
    }
}

// ======================= bf16 3-term GEMM (small/precise) ===================
// stage layout (48KB): Ah 8K | Al 8K | Bh 16K | Bl 16K ; tile 64x128, 2 CTAs/SM
#define STG_BYTES 49152
#define MM_SMEM   (2*STG_BYTES)

__device__ __forceinline__ void stageG(unsigned sb,
    const __nv_bfloat16* Ah, const __nv_bfloat16* Al, size_t lda, int mrow0, int Mv,
    const __nv_bfloat16* Bh, const __nv_bfloat16* Bl, size_t ldb, int ncol0,
    int kcol, int tid)
{
    for (int i=tid;i<512;i+=256){
        int r=i>>3, c=i&7;
        unsigned off = (unsigned)((r*128 + c*16) ^ ((r&7)<<4));
        int ra = mrow0 + r; if (ra >= Mv) ra = Mv-1;
        cp16(sb + off,         Ah + (size_t)ra*lda + kcol + c*8);
        cp16(sb + 8192 + off,  Al + (size_t)ra*lda + kcol + c*8);
    }
    for (int i=tid;i<1024;i+=256){
        int r=i>>3, c=i&7;
        unsigned off = (unsigned)((r*128 + c*16) ^ ((r&7)<<4));
        cp16(sb + 16384 + off,  Bh + (size_t)(ncol0+r)*ldb + kcol + c*8);
        cp16(sb + 32768 + off,  Bl + (size_t)(ncol0+r)*ldb + kcol + c*8);
    }
}

// which 1: R2[z] = h2[z] @ Whh_z^T   2: Pe[z] = ent/ent1 @ Wih_z^T
// which 3: Pr[z] = rel/rel1 @ Wih_z^T  4: R1[z] = h1[z] @ Whh_z^T
__global__ void __launch_bounds__(256,2) mma_gemm(int which)
{
    extern __shared__ char smraw[];
    unsigned sbase;
    asm("{ .reg .u64 t; cvta.to.shared.u64 t, %1; cvt.u32.u64 %0, t; }" : "=r"(sbase) : "l"(smraw));

    const __nv_bfloat16 *Ah,*Al,*Bh,*Bl; float* C;
    int Mv;
    int z = blockIdx.z;
    switch (which){
      case 1:
        Ah=g_h2h+(size_t)z*M_TOTAL*K_PAD2; Al=g_h2l+(size_t)z*M_TOTAL*K_PAD2;
        Bh=g_WTh[z]; Bl=g_WTl[z]; C=g_R2+(size_t)z*M_TOTAL*400; Mv=M_TOTAL; break;
      case 2: {
        int e = (z==2)? 1 : 0;
        Ah=g_Eh[e]; Al=g_El[e]; Bh=g_WTh[3+z]; Bl=g_WTl[3+z]; C=g_Pe[z]; Mv=NENT; break; }
      case 3: {
        int e = (z==2)? 1 : 0;
        Ah=g_Rh[e]; Al=g_Rl[e]; Bh=g_WTh[3+z]; Bl=g_WTl[3+z]; C=g_Pr[z]; Mv=NRELS; break; }
      default:
        Ah=g_h1h[z]; Al=g_h1l[z]; Bh=g_WTh[z]; Bl=g_WTl[z]; C=g_R1[z]; Mv=NENT; break;
    }
    const int Nv=400, ldc=400, nch=2;
    const size_t lda=K_PAD2, ldb=K_PAD2;

    int tid=threadIdx.x, wid=tid>>5, lane=tid&31;
    int wm = wid & 1, wn = wid >> 1;
    int ncol0 = blockIdx.x*128, mrow0 = blockIdx.y*64;

    float acc[2][4][4];
    #pragma unroll
    for (int i=0;i<2;i++)
        #pragma unroll
        for (int j=0;j<4;j++)
            #pragma unroll
            for (int q=0;q<4;q++) acc[i][j][q]=0.f;

    stageG(sbase,             Ah,Al,lda,mrow0,Mv, Bh,Bl,ldb,ncol0, 0,  tid); cp_commit();
    stageG(sbase + STG_BYTES, Ah,Al,lda,mrow0,Mv, Bh,Bl,ldb,ncol0, 64, tid); cp_commit();

    int lr  = lane & 15;
    int lhb = (lane >> 4) << 4;

    for (int k=0;k<nch;k++){
        if (k < nch-1) cp_wait<1>(); else cp_wait<0>();
        __syncthreads();
        unsigned st = sbase + (unsigned)(k&1)*STG_BYTES;
        unsigned sAh = st, sAl = st+8192, sBh = st+16384, sBl = st+32768;

        #pragma unroll
        for (int kk=0;kk<4;kk++){
            int cb = kk*32 + lhb;
            uint32_t ah[2][4], al[2][4], bh[2][4], bl[2][4];
            #pragma unroll
            for (int mt=0;mt<2;mt++){
                int r = wm*32 + mt*16 + lr;
                unsigned off = (unsigned)((r*128 + cb) ^ ((r&7)<<4));
                ldm4(ah[mt], sAh + off);
                ldm4(al[mt], sAl + off);
            }
            #pragma unroll
            for (int ng=0;ng<2;ng++){
                int n = wn*32 + ng*16 + lr;
                unsigned off = (unsigned)((n*128 + cb) ^ ((n&7)<<4));
                ldm4(bh[ng], sBh + off);
                ldm4(bl[ng], sBl + off);
            }
            #pragma unroll
            for (int mt=0;mt<2;mt++){
                #pragma unroll
                for (int nt=0;nt<4;nt++){
                    int ng = nt>>1, s = nt&1;
                    mma16816(acc[mt][nt], ah[mt], bh[ng][s], bh[ng][s+2]);
                    mma16816(acc[mt][nt], ah[mt], bl[ng][s], bl[ng][s+2]);
                    mma16816(acc[mt][nt], al[mt], bh[ng][s], bh[ng][s+2]);
                }
            }
        }
        __syncthreads();
        if (k+2 < nch){
            stageG(st, Ah,Al,lda,mrow0,Mv, Bh,Bl,ldb,ncol0, (k+2)*64, tid);
            cp_commit();
        }
    }

    #pragma unroll
    for (int mt=0;mt<2;mt++){
        int rbase = mrow0 + wm*32 + mt*16 + (lane>>2);
        #pragma unroll
        for (int nt=0;nt<4;nt++){
            int col = ncol0 + wn*32 + nt*8 + (lane&3)*2;
            if (col < Nv){
                if (rbase < Mv)
                    *(float2*)(C + (size_t)rbase*ldc + col)     = make_float2(acc[mt][nt][0], acc[mt][nt][1]);
                if (rbase+8 < Mv)
                    *(float2*)(C + (size_t)(rbase+8)*ldc + col) = make_float2(acc[mt][nt][2], acc[mt][nt][3]);
            }
        }
    }
}

// ---------------------------------------------------------------------------
// conversions
// ---------------------------------------------------------------------------
__global__ void convB_kernel(const float* __restrict__ W1)
{
    int i = blockIdx.x*256 + threadIdx.x;
    if (i >= 600*600) return;
    int n = i / 600, k = i - n*600;
    g_BTf[(size_t)n*K_PAD + k] = __float2half(W1[(size_t)k*600 + n]);
}
__global__ void convW6_kernel(const float* __restrict__ Whf, const float* __restrict__ Whb,
                              const float* __restrict__ Whp, const float* __restrict__ Wif,
                              const float* __restrict__ Wib, const float* __restrict__ Wip)
{
    int i = blockIdx.x*256 + threadIdx.x;
    if (i >= 6*400*100) return;
    int m = i / 40000; int rem = i - m*40000;
    int n = rem/100, k = rem - n*100;
    const float* W;
    switch(m){ case 0:W=Whf;break; case 1:W=Whb;break; case 2:W=Whp;break;
               case 3:W=Wif;break; case 4:W=Wib;break; default:W=Wip;break; }
    split2(W[n*100+k], &g_WTh[m][n*K_PAD2 + k], &g_WTl[m][n*K_PAD2 + k]);
}
__global__ void convE_kernel(const float* __restrict__ ent, const float* __restrict__ ent1,
                             const float* __restrict__ rel, const float* __restrict__ rel1)
{
    int i = blockIdx.x*256 + threadIdx.x;
    if (i < 2*NENT*100){
        int e = i / (NENT*100); int rem = i - e*(NENT*100);
        int r = rem/100, k = rem - r*100;
        const float* src = e ? ent1 : ent;
        split2(src[(size_t)r*100+k], &g_Eh[e][(size_t)r*K_PAD2+k], &g_El[e][(size_t)r*K_PAD2+k]);
    } else {
        int j = i - 2*NENT*100;
        if (j >= 2*NRELS*100) return;
        int e = j / (NRELS*100); int rem = j - e*(NRELS*100);
        int r = rem/100, k = rem - r*100;
        const float* src = e ? rel1 : rel;
        split2(src[(size_t)r*100+k], &g_Rh[e][(size_t)r*K_PAD2+k], &g_Rl[e][(size_t)r*K_PAD2+k]);
    }
}

// ---------------------------------------------------------------------------
__global__ void step1_kernel(const float* __restrict__ b_f,
                             const float* __restrict__ b_b,
                             const float* __restrict__ b_p)
{
    int idx = blockIdx.x*256 + threadIdx.x;
    if (idx >= 3*NENT*100) return;
    int l   = idx / (NENT*100);
    int rem = idx - l*(NENT*100);
    int e = rem/100, j = rem - e*100;
    const float* P = g_Pe[l] + (size_t)e*400;
    const float* b = (l==0)? b_f : (l==1)? b_b : b_p;
    float iv = P[j]     + b[j];
    float gv = P[200+j] + b[200+j];
    float ov = P[300+j] + b[300+j];
    float c1 = sigmoidf_(iv) * tanhf_(gv);
    float h1 = sigmoidf_(ov) * tanhf_(c1);
    g_h1c1[l][(size_t)e*200 + j]       = h1;
    g_h1c1[l][(size_t)e*200 + 100 + j] = c1;
    split2(h1, &g_h1h[l][(size_t)e*K_PAD2 + j], &g_h1l[l][(size_t)e*K_PAD2 + j]);
}

// ---------------------------------------------------------------------------
__global__ void __launch_bounds__(256) step12_kernel(
    const int* __restrict__ bh, const int* __restrict__ br, const int* __restrict__ bt,
    const float* __restrict__ b_f, const float* __restrict__ b_b, const float* __restrict__ b_p)
{
    __shared__ int ih[64], ir[64], it[64];
    int tid=threadIdx.x; int row0=blockIdx.x*64;
    if (tid<64)        ih[tid]     = bh[row0+tid];
    else if (tid<128)  ir[tid-64]  = br[row0+tid-64];
    else if (tid<192)  it[tid-128] = bt[row0+tid-128];
    __syncthreads();
    for (int l=0;l<3;l++){
        const float* Pr  = g_Pr[l];
        const float* R1  = g_R1[l];
        const float* HC  = g_h1c1[l];
        const float* bias= (l==0)?b_f:(l==1)?b_b:b_p;
        for (int t=tid;t<1600;t+=256){
            int row=t/25, q=t-row*25; int j=q*4;
            int fi = (l==1)? it[row] : ih[row];
            size_t grow=(size_t)(row0+row);
            bool emit_out = ((grow % 80u)==0u) && (l<2);
            float4 h1v = *(const float4*)&HC[(size_t)fi*200 + j];
            float4 c1v = *(const float4*)&HC[(size_t)fi*200 + 100 + j];
            if (l==0){
                if (emit_out) *(float4*)&g_out[grow*600 + j] = h1v;
                storeh4(h1v, &g_Af[grow*K_PAD + j]);
            } else if (l==1){
                if (emit_out) *(float4*)&g_out[grow*600 + 500 + j] = h1v;
                storeh4(h1v, &g_Af[grow*K_PAD + 500 + j]);
            }
            const float* pr = Pr + (size_t)ir[row]*400;
            const float* r1 = R1 + (size_t)fi*400;
            float4 pi = *(const float4*)&pr[j],      ri = *(const float4*)&r1[j];
            float4 pf = *(const float4*)&pr[100+j],  rf = *(const float4*)&r1[100+j];
            float4 pg = *(const float4*)&pr[200+j],  rg = *(const float4*)&r1[200+j];
            float4 po = *(const float4*)&pr[300+j],  ro = *(const float4*)&r1[300+j];
            float4 bi = *(const float4*)&bias[j],    bf4= *(const float4*)&bias[100+j];
            float4 bg = *(const float4*)&bias[200+j],bo = *(const float4*)&bias[300+j];
            float4 c2v, h2v;
            {
                float c,h;
                c = sigmoidf_(pf.x+rf.x+bf4.x)*c1v.x + sigmoidf_(pi.x+ri.x+bi.x)*tanhf_(pg.x+rg.x+bg.x);
                h = sigmoidf_(po.x+ro.x+bo.x)*tanhf_(c); c2v.x=c; h2v.x=h;
                c = sigmoidf_(pf.y+rf.y+bf4.y)*c1v.y + sigmoidf_(pi.y+ri.y+bi.y)*tanhf_(pg.y+rg.y+bg.y);
                h = sigmoidf_(po.y+ro.y+bo.y)*tanhf_(c); c2v.y=c; h2v.y=h;
                c = sigmoidf_(pf.z+rf.z+bf4.z)*c1v.z + sigmoidf_(pi.z+ri.z+bi.z)*tanhf_(pg.z+rg.z+bg.z);
                h = sigmoidf_(po.z+ro.z+bo.z)*tanhf_(c); c2v.z=c; h2v.z=h;
                c = sigmoidf_(pf.w+rf.w+bf4.w)*c1v.w + sigmoidf_(pi.w+ri.w+bi.w)*tanhf_(pg.w+rg.w+bg.w);
                h = sigmoidf_(po.w+ro.w+bo.w)*tanhf_(c); c2v.w=c; h2v.w=h;
            }
            size_t hidx = (size_t)l*M_TOTAL*K_PAD2 + grow*K_PAD2 + j;
            split4(h2v, &g_h2h[hidx], &g_h2l[hidx]);
            *(float4*)&g_c2[(size_t)l*M_TOTAL*100 + grow*100 + j] = c2v;
            if (l==0){
                if (emit_out) *(float4*)&g_out[grow*600 + 200 + j] = h2v;
                storeh4(h2v, &g_Af[grow*K_PAD + 200 + j]);
            } else if (l==1){
                if (emit_out) *(float4*)&g_out[grow*600 + 300 + j] = h2v;
                storeh4(h2v, &g_Af[grow*K_PAD + 300 + j]);
            }
        }
    }
}

// ---------------------------------------------------------------------------
__global__ void __launch_bounds__(256) step3_kernel(
    const int* __restrict__ bh, const int* __restrict__ bt,
    const float* __restrict__ b_f, const float* __restrict__ b_b, const float* __restrict__ b_p)
{
    __shared__ int ih[64], it[64];
    int tid=threadIdx.x; int row0=blockIdx.x*64;
    if (tid<64)        ih[tid]    = bh[row0+tid];
    else if (tid<128)  it[tid-64] = bt[row0+tid-64];
    __syncthreads();
    for (int l=0;l<3;l++){
        const float* Pe  = g_Pe[l];
        const float* R2  = g_R2 + (size_t)l*M_TOTAL*400;
        const float* C2  = g_c2 + (size_t)l*M_TOTAL*100;
        const float* bias= (l==0)?b_f:(l==1)?b_b:b_p;
        for (int t=tid;t<1600;t+=256){
            int row=t/25, q=t-row*25; int j=q*4;
            int li = (l==1)? ih[row] : it[row];
            size_t grow=(size_t)(row0+row);
            const float* pe = Pe + (size_t)li*400;
            const float* r2 = R2 + grow*400;
            float4 pi = *(const float4*)&pe[j],      ri = *(const float4*)&r2[j];
            float4 pf = *(const float4*)&pe[100+j],  rf = *(const float4*)&r2[100+j];
            float4 pg = *(const float4*)&pe[200+j],  rg = *(const float4*)&r2[200+j];
            float4 po = *(const float4*)&pe[300+j],  ro = *(const float4*)&r2[300+j];
            float4 bi = *(const float4*)&bias[j],    bf4= *(const float4*)&bias[100+j];
            float4 bg = *(const float4*)&bias[200+j],bo = *(const float4*)&bias[300+j];
            float4 c2v = *(const float4*)&C2[grow*100 + j];
            float4 h3v;
            {
                float c;
                c = sigmoidf_(pf.x+rf.x+bf4.x)*c2v.x + sigmoidf_(pi.x+ri.x+bi.x)*tanhf_(pg.x+rg.x+bg.x);
                h3v.x = sigmoidf_(po.x+ro.x+bo.x)*tanhf_(c);
                c = sigmoidf_(pf.y+rf.y+bf4.y)*c2v.y + sigmoidf_(pi.y+ri.y+bi.y)*tanhf_(pg.y+rg.y+bg.y);
                h3v.y = sigmoidf_(po.y+ro.y+bo.y)*tanhf_(c);
                c = sigmoidf_(pf.z+rf.z+bf4.z)*c2v.z + sigmoidf_(pi.z+ri.z+bi.z)*tanhf_(pg.z+rg.z+bg.z);
                h3v.z = sigmoidf_(po.z+ro.z+bo.z)*tanhf_(c);
                c = sigmoidf_(pf.w+rf.w+bf4.w)*c2v.w + sigmoidf_(pi.w+ri.w+bi.w)*tanhf_(pg.w+rg.w+bg.w);
                h3v.w = sigmoidf_(po.w+ro.w+bo.w)*tanhf_(c);
            }
            bool emit_out = ((grow % 80u)==0u);
            if (l==0){
                if (emit_out) *(float4*)&g_out[grow*600 + 400 + j] = h3v;
                storeh4(h3v, &g_Af[grow*K_PAD + 400 + j]);
            } else if (l==1){
                if (emit_out) *(float4*)&g_out[grow*600 + 100 + j] = h3v;
                storeh4(h3v, &g_Af[grow*K_PAD + 100 + j]);
            } else {
                *(float4*)&g_op[grow*100 + j] = h3v;
            }
        }
    }
}

// ---------------------------------------------------------------------------
__global__ void __launch_bounds__(256,1) gat1_att(
    const float* __restrict__ a1, float* __restrict__ out_att, float* __restrict__ out2)
{
    __shared__ __align__(16) float a1s[1200];
    __shared__ float ebuf[41];
    __shared__ float att[40];
    __shared__ float red[2];
    int b=blockIdx.x, tid=threadIdx.x, warp=tid>>5, lane=tid&31;
    for (int i=tid;i<1200;i+=256) a1s[i]=a1[i];
    __syncthreads();
    const float* base = g_hG + (size_t)b*24000;
    for (int t=warp;t<41;t+=8){
        const float* rowp = (t<40)? base + t*600 : base;
        const float* av   = (t<40)? a1s         : a1s+600;
        float s=0.f;
        for (int kk=lane;kk<150;kk+=32){
            float4 r4 = *(const float4*)(rowp + kk*4);
            float4 a4 = *(const float4*)(av   + kk*4);
            s += r4.x*a4.x + r4.y*a4.y + r4.z*a4.z + r4.w*a4.w;
        }
        #pragma unroll
        for (int o=16;o;o>>=1) s += __shfl_xor_sync(0xffffffffu, s, o);
        if (lane==0) ebuf[t]=s;
    }
    __syncthreads();
    if (tid<40){
        float x = ebuf[tid] + ebuf[40];
        ebuf[tid] = (x>0.f)? x : 0.2f*x;
    }
    __syncthreads();
    if (tid<32){
        float v = ebuf[tid];
        if (tid<8) v = fmaxf(v, ebuf[tid+32]);
        #pragma unroll
        for (int o=16;o;o>>=1) v = fmaxf(v, __shfl_xor_sync(0xffffffffu, v, o));
        if (tid==0) red[0]=v;
    }
    __syncthreads();
    if (tid<40) att[tid]=__expf(ebuf[tid]-red[0]);
    __syncthreads();
    if (tid<32){
        float v = att[tid] + ((tid<8)? att[tid+32] : 0.f);
        #pragma unroll
        for (int o=16;o;o>>=1) v += __shfl_xor_sync(0xffffffffu, v, o);
        if (tid==0) red[1]=1.f/v;
    }
    __syncthreads();
    if (tid<40) att[tid]=fmaxf(att[tid]*red[1]-0.001f, 0.f);
    __syncthreads();
    for (int f=tid; f<600; f+=256){
        float acc=0.f;
        #pragma unroll 8
        for (int n=0;n<40;n++) acc += att[n]*base[n*600+f];
        out_att[(size_t)b*600+f]=acc;
    }
    if ((b&1)==0){
        const float* srow = g_out + (size_t)b*40*600;
        float* drow = out2 + (size_t)(b>>1)*600;
        for (int f=tid;f<600;f+=256) drow[f]=srow[f];
    }
}

// ---------------------------------------------------------------------------
#define GAT2_SMEM ((4000 + 10000 + 4000)*4)
__global__ void __launch_bounds__(256,1) gat2_kernel(
    const float* __restrict__ W2, const float* __restrict__ a2,
    float* __restrict__ output_att, float* __restrict__ op2)
{
    extern __shared__ float sm[];
    float* ops = sm;
    float* Ws  = ops + 4000;
    float* hg  = Ws  + 10000;
    __shared__ float a2s[200];
    __shared__ float ebuf[41];
    __shared__ float att[40];
    __shared__ float red[2];
    int b=blockIdx.x, tid=threadIdx.x, warp=tid>>5, lane=tid&31;
    const float* src = g_op + (size_t)b*4000;
    for (int i=tid;i<4000;i+=256)  ops[i]=src[i];
    for (int i=tid;i<10000;i+=256) Ws[i]=W2[i];
    if (tid<200) a2s[tid]=a2[tid];
    __syncthreads();
    for (int i=tid;i<4000;i+=256){
        int n=i/100, o=i-n*100;
        float acc=0.f;
        #pragma unroll 4
        for (int k=0;k<100;k++) acc=fmaf(ops[n*100+k], Ws[k*100+o], acc);
        hg[i]=acc;
    }
    __syncthreads();
    for (int t=warp;t<41;t+=8){
        const float* rowp = (t<40)? hg + t*100 : hg;
        const float* av   = (t<40)? a2s        : a2s+100;
        float s=0.f;
        for (int k=lane;k<100;k+=32) s += rowp[k]*av[k];
        #pragma unroll
        for (int o=16;o;o>>=1) s += __shfl_xor_sync(0xffffffffu, s, o);
        if (lane==0) ebuf[t]=s;
    }
    __syncthreads();
    if (tid<40){
        float x = ebuf[tid] + ebuf[40];
        ebuf[tid] = (x>0.f)? x : 0.2f*x;
    }
    __syncthreads();
    if (tid<32){
        float v = ebuf[tid];
        if (tid<8) v = fmaxf(v, ebuf[tid+32]);
        #pragma unroll
        for (int o=16;o;o>>=1) v = fmaxf(v, __shfl_xor_sync(0xffffffffu, v, o));
        if (tid==0) red[0]=v;
    }
    __syncthreads();
    if (tid<40) att[tid]=__expf(ebuf[tid]-red[0]);
    __syncthreads();
    if (tid<32){
        float v = att[tid] + ((tid<8)? att[tid+32] : 0.f);
        #pragma unroll
        for (int o=16;o;o>>=1) v += __shfl_xor_sync(0xffffffffu, v, o);
        if (tid==0) red[1]=1.f/v;
    }
    __syncthreads();
    if (tid<40) att[tid]=fmaxf(att[tid]*red[1]-0.001f, 0.f);
    __syncthreads();
    if (tid<100){
        float acc=0.f;
        #pragma unroll 8
        for (int n=0;n<40;n++) acc += att[n]*hg[n*100+tid];
        output_att[(size_t)b*100+tid]=acc;
    }
    if ((b&1)==0){
        const float* srow = g_op + (size_t)b*40*100;
        float* drow = op2 + (size_t)(b>>1)*100;
        if (tid<100) drow[tid]=srow[tid];
    }
}

// ---------------------------------------------------------------------------
extern "C" void kernel_launch(void* const* d_in, const int* in_sizes, int n_in,
                              void* d_out, int out_size)
{
    const int*   bh    = (const int*)  d_in[0];
    const int*   br    = (const int*)  d_in[1];
    const int*   bt    = (const int*)  d_in[2];
    const float* ent   = (const float*)d_in[3];
    const float* rel   = (const float*)d_in[4];
    const float* ent1  = (const float*)d_in[5];
    const float* rel1  = (const float*)d_in[6];
    const float* Wih_f = (const float*)d_in[7];
    const float* Whh_f = (const float*)d_in[8];
    const float* b_f   = (const float*)d_in[9];
    const float* Wih_b = (const float*)d_in[10];
    const float* Whh_b = (const float*)d_in[11];
    const float* b_b   = (const float*)d_in[12];
    const float* Wih_p = (const float*)d_in[13];
    const float* Whh_p = (const float*)d_in[14];
    const float* b_p   = (const float*)d_in[15];
    const float* W1    = (const float*)d_in[16];
    const float* a1    = (const float*)d_in[17];
    const float* W2    = (const float*)d_in[18];
    const float* a2    = (const float*)d_in[19];

    float* out        = (float*)d_out;
    float* out2       = out;                          // [1024,600]
    float* out_att    = out + 1024*600;               // [2048,600]
    float* op2        = out + 1024*600 + 2048*600;    // [1024,100]
    float* output_att = op2 + 1024*100;               // [2048,100]

    cudaFuncSetAttribute(gat2_kernel, cudaFuncAttributeMaxDynamicSharedMemorySize, GAT2_SMEM);
    cudaFuncSetAttribute(mma_gemm,    cudaFuncAttributeMaxDynamicSharedMemorySize, MM_SMEM);
    cudaFuncSetAttribute(mma_f16,     cudaFuncAttributeMaxDynamicSharedMemorySize, MMF_SMEM);

    convB_kernel<<<(600*600 + 255)/256, 256>>>(W1);
    convW6_kernel<<<(6*400*100 + 255)/256, 256>>>(Whh_f, Whh_b, Whh_p, Wih_f, Wih_b, Wih_p);
    convE_kernel<<<(2*(NENT+NRELS)*100 + 255)/256, 256>>>(ent, ent1, rel, rel1);

    dim3 pe(4, NENT_P/64, 3);
    mma_gemm<<<pe, 256, MM_SMEM>>>(2);
    dim3 pr(4, 4, 3);
    mma_gemm<<<pr, 256, MM_SMEM>>>(3);

    step1_kernel<<<(3*NENT*100 + 255)/256, 256>>>(b_f, b_b, b_p);

    mma_gemm<<<pe, 256, MM_SMEM>>>(4);

    step12_kernel<<<M_TOTAL/64, 256>>>(bh, br, bt, b_f, b_b, b_p);

    dim3 rg(4, M_TOTAL/64, 3);
    mma_gemm<<<rg, 256, MM_SMEM>>>(1);

    step3_kernel<<<M_TOTAL/64, 256>>>(bh, bt, b_f, b_b, b_p);

    dim3 gg(5, M_TOTAL/64, 1);
    mma_f16<<<gg, 256, MMF_SMEM>>>();

    gat1_att<<<NGROUP, 256>>>(a1, out_att, out2);

    gat2_kernel<<<NGROUP, 256, GAT2_SMEM>>>(W2, a2, output_att, op2);

    (void)in_sizes; (void)n_in; (void)out_size;
}

// round 9
// speedup vs baseline: 11.3713x; 1.2717x over previous
#include <cuda_runtime.h>
#include <cuda_bf16.h>
#include <cuda_fp16.h>
#include <math.h>
#include <cstdint>

#define M_TOTAL 81920
#define NGROUP  2048
#define NENT    14541
#define NRELS   237
#define NENT_P  14592
#define K_PAD   640
#define K_PAD2  128

// ---------------- scratch (device globals) ----------------------------------
__device__ __half g_Pe[3][NENT*400];        // fp16 tables
__device__ __half g_Pr[3][NRELS*400];
__device__ __half g_R1[3][NENT*400];
__device__ float  g_h1c1[3][NENT*200];
__device__ float  g_c2[(size_t)3*M_TOTAL*100];
__device__ __align__(16) __half g_R2f[(size_t)3*M_TOTAL*400];
__device__ float  g_out[(size_t)M_TOTAL*600];
__device__ __align__(16) __half g_hGf[(size_t)M_TOTAL*600];
__device__ float  g_op [(size_t)M_TOTAL*100];
// fp16 GEMM operands (pads stay zero)
__device__ __align__(16) __half g_Af[(size_t)M_TOTAL*K_PAD];
__device__ __align__(16) __half g_BTf[640*K_PAD];
__device__ __align__(16) __half g_h2f[(size_t)3*M_TOTAL*K_PAD2];
__device__ __align__(16) __half g_Wf[3][512*K_PAD2];
// bf16 hi/lo splits for the accurate vocab-level GEMMs
__device__ __align__(16) __nv_bfloat16 g_WTh[6][512*K_PAD2];
__device__ __align__(16) __nv_bfloat16 g_WTl[6][512*K_PAD2];
__device__ __align__(16) __nv_bfloat16 g_Eh[2][NENT_P*K_PAD2];
__device__ __align__(16) __nv_bfloat16 g_El[2][NENT_P*K_PAD2];
__device__ __align__(16) __nv_bfloat16 g_Rh[2][256*K_PAD2];
__device__ __align__(16) __nv_bfloat16 g_Rl[2][256*K_PAD2];
__device__ __align__(16) __nv_bfloat16 g_h1h[3][NENT_P*K_PAD2];
__device__ __align__(16) __nv_bfloat16 g_h1l[3][NENT_P*K_PAD2];

__device__ __forceinline__ float sigmoidf_(float x){
    return __fdividef(1.f, 1.f + __expf(-x));
}
__device__ __forceinline__ float tanhf_(float x){
    float xc = fminf(fmaxf(x,-15.f),15.f);
    float e = __expf(2.f*xc);
    return __fdividef(e-1.f, e+1.f);
}
__device__ __forceinline__ void split2(float v, __nv_bfloat16* ph, __nv_bfloat16* pl){
    __nv_bfloat16 h = __float2bfloat16(v);
    *ph = h;
    *pl = __float2bfloat16(v - __bfloat162float(h));
}
__device__ __forceinline__ void storeh4(float4 v, __half* p){
    ((__half2*)p)[0] = __floats2half2_rn(v.x, v.y);
    ((__half2*)p)[1] = __floats2half2_rn(v.z, v.w);
}
__device__ __forceinline__ float4 loadh4(const __half* p){
    __half2 a = ((const __half2*)p)[0], b = ((const __half2*)p)[1];
    float2 fa=__half22float2(a), fb=__half22float2(b);
    return make_float4(fa.x,fa.y,fb.x,fb.y);
}

// ======================= MMA plumbing =======================================
__device__ __forceinline__ void cp16(unsigned saddr, const void* g){
    asm volatile("cp.async.cg.shared.global [%0], [%1], 16;" :: "r"(saddr), "l"(g));
}
__device__ __forceinline__ void cp_commit(){
    asm volatile("cp.async.commit_group;" ::: "memory");
}
template<int N> __device__ __forceinline__ void cp_wait(){
    asm volatile("cp.async.wait_group %0;" :: "n"(N) : "memory");
}
__device__ __forceinline__ void ldm4(uint32_t* r, unsigned addr){
    asm volatile("ldmatrix.sync.aligned.m8n8.x4.shared.b16 {%0,%1,%2,%3}, [%4];"
        : "=r"(r[0]), "=r"(r[1]), "=r"(r[2]), "=r"(r[3]) : "r"(addr));
}
__device__ __forceinline__ void mma16816(float* d, const uint32_t* a, uint32_t b0, uint32_t b1){
    asm volatile("mma.sync.aligned.m16n8k16.row.col.f32.bf16.bf16.f32 "
        "{%0,%1,%2,%3},{%4,%5,%6,%7},{%8,%9},{%0,%1,%2,%3};"
        : "+f"(d[0]), "+f"(d[1]), "+f"(d[2]), "+f"(d[3])
        : "r"(a[0]), "r"(a[1]), "r"(a[2]), "r"(a[3]), "r"(b0), "r"(b1));
}
__device__ __forceinline__ void mma16816h(float* d, const uint32_t* a, uint32_t b0, uint32_t b1){
    asm volatile("mma.sync.aligned.m16n8k16.row.col.f32.f16.f16.f32 "
        "{%0,%1,%2,%3},{%4,%5,%6,%7},{%8,%9},{%0,%1,%2,%3};"
        : "+f"(d[0]), "+f"(d[1]), "+f"(d[2]), "+f"(d[3])
        : "r"(a[0]), "r"(a[1]), "r"(a[2]), "r"(a[3]), "r"(b0), "r"(b1));
}

// ======================= fp16 single-pass GEMM ==============================
// tile 64(M) x 128(N); stage 24KB (A 8K | B 16K), 2 stages, 3 CTAs/SM.
// which 0: g_hGf = Af @ BTf^T (nch=10)   which 1: g_R2f[z] = h2f[z] @ Wf[z]^T (nch=2)
#define STG_F16 24576
#define MMF_SMEM (2*STG_F16)

__device__ __forceinline__ void stageF(unsigned sb,
    const __half* A, size_t lda, const __half* B, size_t ldb, int kcol, int tid)
{
    for (int i=tid;i<512;i+=256){
        int r=i>>3, c=i&7;
        unsigned off = (unsigned)((r*128 + c*16) ^ ((r&7)<<4));
        cp16(sb + off, A + (size_t)r*lda + kcol + c*8);
    }
    for (int i=tid;i<1024;i+=256){
        int r=i>>3, c=i&7;
        unsigned off = (unsigned)((r*128 + c*16) ^ ((r&7)<<4));
        cp16(sb + 8192 + off, B + (size_t)r*ldb + kcol + c*8);
    }
}

__global__ void __launch_bounds__(256,3) mma_f16(int which)
{
    extern __shared__ char smraw[];
    unsigned sbase;
    asm("{ .reg .u64 t; cvta.to.shared.u64 t, %1; cvt.u32.u64 %0, t; }" : "=r"(sbase) : "l"(smraw));
    int tid=threadIdx.x, wid=tid>>5, lane=tid&31;
    int wm = wid & 1, wn = wid >> 1;
    int ncol0 = blockIdx.x*128, mrow0 = blockIdx.y*64;
    int z = blockIdx.z;

    const __half *A, *B; __half* C; int Nv, ldc, nch; size_t lda, ldb;
    if (which==0){
        A = g_Af + (size_t)mrow0*K_PAD; B = g_BTf + (size_t)ncol0*K_PAD;
        C = g_hGf; Nv=600; ldc=600; nch=10; lda=K_PAD; ldb=K_PAD;
    } else {
        A = g_h2f + (size_t)z*M_TOTAL*K_PAD2 + (size_t)mrow0*K_PAD2;
        B = g_Wf[z] + (size_t)ncol0*K_PAD2;
        C = g_R2f + (size_t)z*M_TOTAL*400; Nv=400; ldc=400; nch=2; lda=K_PAD2; ldb=K_PAD2;
    }

    float acc[2][4][4];
    #pragma unroll
    for (int i=0;i<2;i++)
        #pragma unroll
        for (int j=0;j<4;j++)
            #pragma unroll
            for (int q=0;q<4;q++) acc[i][j][q]=0.f;

    stageF(sbase,           A,lda,B,ldb, 0,  tid); cp_commit();
    stageF(sbase + STG_F16, A,lda,B,ldb, 64, tid); cp_commit();

    int lr  = lane & 15;
    int lhb = (lane >> 4) << 4;

    for (int k=0;k<nch;k++){
        if (k < nch-1) cp_wait<1>(); else cp_wait<0>();
        __syncthreads();
        unsigned st = sbase + (unsigned)(k&1)*STG_F16;
        unsigned sA = st, sB = st+8192;
        #pragma unroll
        for (int kk=0;kk<4;kk++){
            int cb = kk*32 + lhb;
            uint32_t ah[2][4], bb[2][4];
            #pragma unroll
            for (int mt=0;mt<2;mt++){
                int r = wm*32 + mt*16 + lr;
                unsigned off = (unsigned)((r*128 + cb) ^ ((r&7)<<4));
                ldm4(ah[mt], sA + off);
            }
            #pragma unroll
            for (int ng=0;ng<2;ng++){
                int n = wn*32 + ng*16 + lr;
                unsigned off = (unsigned)((n*128 + cb) ^ ((n&7)<<4));
                ldm4(bb[ng], sB + off);
            }
            #pragma unroll
            for (int mt=0;mt<2;mt++){
                #pragma unroll
                for (int nt=0;nt<4;nt++){
                    int ng = nt>>1, s = nt&1;
                    mma16816h(acc[mt][nt], ah[mt], bb[ng][s], bb[ng][s+2]);
                }
            }
        }
        __syncthreads();
        if (k+2 < nch){
            stageF(st, A,lda,B,ldb, (k+2)*64, tid);
            cp_commit();
        }
    }
    #pragma unroll
    for (int mt=0;mt<2;mt++){
        int rbase = mrow0 + wm*32 + mt*16 + (lane>>2);
        #pragma unroll
        for (int nt=0;nt<4;nt++){
            int col = ncol0 + wn*32 + nt*8 + (lane&3)*2;
            if (col < Nv){
                *(__half2*)(C + (size_t)rbase*ldc + col)     = __floats2half2_rn(acc[mt][nt][0], acc[mt][nt][1]);
                *(__half2*)(C + (size_t)(rbase+8)*ldc + col) = __floats2half2_rn(acc[mt][nt][2], acc[mt][nt][3]);
            }
        }
    }
}

// ======================= bf16 3-term GEMM (vocab-level, fp16 out) ===========
#define STG_BYTES 49152
#define MM_SMEM   (2*STG_BYTES)

__device__ __forceinline__ void stageG(unsigned sb,
    const __nv_bfloat16* Ah, const __nv_bfloat16* Al, size_t lda, int mrow0, int Mv,
    const __nv_bfloat16* Bh, const __nv_bfloat16* Bl, size_t ldb, int ncol0,
    int kcol, int tid)
{
    for (int i=tid;i<512;i+=256){
        int r=i>>3, c=i&7;
        unsigned off = (unsigned)((r*128 + c*16) ^ ((r&7)<<4));
        int ra = mrow0 + r; if (ra >= Mv) ra = Mv-1;
        cp16(sb + off,         Ah + (size_t)ra*lda + kcol + c*8);
        cp16(sb + 8192 + off,  Al + (size_t)ra*lda + kcol + c*8);
    }
    for (int i=tid;i<1024;i+=256){
        int r=i>>3, c=i&7;
        unsigned off = (unsigned)((r*128 + c*16) ^ ((r&7)<<4));
        cp16(sb + 16384 + off,  Bh + (size_t)(ncol0+r)*ldb + kcol + c*8);
        cp16(sb + 32768 + off,  Bl + (size_t)(ncol0+r)*ldb + kcol + c*8);
    }
}

// which 2: Pe[z]  3: Pr[z]  4: R1[z]
__global__ void __launch_bounds__(256,2) mma_gemm(int which)
{
    extern __shared__ char smraw[];
    unsigned sbase;
    asm("{ .reg .u64 t; cvta.to.shared.u64 t, %1; cvt.u32.u64 %0, t; }" : "=r"(sbase) : "l"(smraw));

    const __nv_bfloat16 *Ah,*Al,*Bh,*Bl; __half* C;
    int Mv;
    int z = blockIdx.z;
    switch (which){
      case 2: {
        int e = (z==2)? 1 : 0;
        Ah=g_Eh[e]; Al=g_El[e]; Bh=g_WTh[3+z]; Bl=g_WTl[3+z]; C=g_Pe[z]; Mv=NENT; break; }
      case 3: {
        int e = (z==2)? 1 : 0;
        Ah=g_Rh[e]; Al=g_Rl[e]; Bh=g_WTh[3+z]; Bl=g_WTl[3+z]; C=g_Pr[z]; Mv=NRELS; break; }
      default:
        Ah=g_h1h[z]; Al=g_h1l[z]; Bh=g_WTh[z]; Bl=g_WTl[z]; C=g_R1[z]; Mv=NENT; break;
    }
    const int Nv=400, ldc=400, nch=2;
    const size_t lda=K_PAD2, ldb=K_PAD2;

    int tid=threadIdx.x, wid=tid>>5, lane=tid&31;
    int wm = wid & 1, wn = wid >> 1;
    int ncol0 = blockIdx.x*128, mrow0 = blockIdx.y*64;

    float acc[2][4][4];
    #pragma unroll
    for (int i=0;i<2;i++)
        #pragma unroll
        for (int j=0;j<4;j++)
            #pragma unroll
            for (int q=0;q<4;q++) acc[i][j][q]=0.f;

    stageG(sbase,             Ah,Al,lda,mrow0,Mv, Bh,Bl,ldb,ncol0, 0,  tid); cp_commit();
    stageG(sbase + STG_BYTES, Ah,Al,lda,mrow0,Mv, Bh,Bl,ldb,ncol0, 64, tid); cp_commit();

    int lr  = lane & 15;
    int lhb = (lane >> 4) << 4;

    for (int k=0;k<nch;k++){
        if (k < nch-1) cp_wait<1>(); else cp_wait<0>();
        __syncthreads();
        unsigned st = sbase + (unsigned)(k&1)*STG_BYTES;
        unsigned sAh = st, sAl = st+8192, sBh = st+16384, sBl = st+32768;

        #pragma unroll
        for (int kk=0;kk<4;kk++){
            int cb = kk*32 + lhb;
            uint32_t ah[2][4], al[2][4], bh[2][4], bl[2][4];
            #pragma unroll
            for (int mt=0;mt<2;mt++){
                int r = wm*32 + mt*16 + lr;
                unsigned off = (unsigned)((r*128 + cb) ^ ((r&7)<<4));
                ldm4(ah[mt], sAh + off);
                ldm4(al[mt], sAl + off);
            }
            #pragma unroll
            for (int ng=0;ng<2;ng++){
                int n = wn*32 + ng*16 + lr;
                unsigned off = (unsigned)((n*128 + cb) ^ ((n&7)<<4));
                ldm4(bh[ng], sBh + off);
                ldm4(bl[ng], sBl + off);
            }
            #pragma unroll
            for (int mt=0;mt<2;mt++){
                #pragma unroll
                for (int nt=0;nt<4;nt++){
                    int ng = nt>>1, s = nt&1;
                    mma16816(acc[mt][nt], ah[mt], bh[ng][s], bh[ng][s+2]);
                    mma16816(acc[mt][nt], ah[mt], bl[ng][s], bl[ng][s+2]);
                    mma16816(acc[mt][nt], al[mt], bh[ng][s], bh[ng][s+2]);
                }
            }
        }
        __syncthreads();
        if (k+2 < nch){
            stageG(st, Ah,Al,lda,mrow0,Mv, Bh,Bl,ldb,ncol0, (k+2)*64, tid);
            cp_commit();
        }
    }

    #pragma unroll
    for (int mt=0;mt<2;mt++){
        int rbase = mrow0 + wm*32 + mt*16 + (lane>>2);
        #pragma unroll
        for (int nt=0;nt<4;nt++){
            int col = ncol0 + wn*32 + nt*8 + (lane&3)*2;
            if (col < Nv){
                if (rbase < Mv)
                    *(__half2*)(C + (size_t)rbase*ldc + col)     = __floats2half2_rn(acc[mt][nt][0], acc[mt][nt][1]);
                if (rbase+8 < Mv)
                    *(__half2*)(C + (size_t)(rbase+8)*ldc + col) = __floats2half2_rn(acc[mt][nt][2], acc[mt][nt][3]);
            }
        }
    }
}

// ---------------------------------------------------------------------------
// conversions
// ---------------------------------------------------------------------------
__global__ void convB_kernel(const float* __restrict__ W1)
{
    int i = blockIdx.x*256 + threadIdx.x;
    if (i >= 600*600) return;
    int n = i / 600, k = i - n*600;
    g_BTf[(size_t)n*K_PAD + k] = __float2half(W1[(size_t)k*600 + n]);
}
__global__ void convW6_kernel(const float* __restrict__ Whf, const float* __restrict__ Whb,
                              const float* __restrict__ Whp, const float* __restrict__ Wif,
                              const float* __restrict__ Wib, const float* __restrict__ Wip)
{
    int i = blockIdx.x*256 + threadIdx.x;
    if (i >= 6*400*100) return;
    int m = i / 40000; int rem = i - m*40000;
    int n = rem/100, k = rem - n*100;
    const float* W;
    switch(m){ case 0:W=Whf;break; case 1:W=Whb;break; case 2:W=Whp;break;
               case 3:W=Wif;break; case 4:W=Wib;break; default:W=Wip;break; }
    float v = W[n*100+k];
    split2(v, &g_WTh[m][n*K_PAD2 + k], &g_WTl[m][n*K_PAD2 + k]);
    if (m < 3) g_Wf[m][n*K_PAD2 + k] = __float2half(v);
}
__global__ void convE_kernel(const float* __restrict__ ent, const float* __restrict__ ent1,
                             const float* __restrict__ rel, const float* __restrict__ rel1)
{
    int i = blockIdx.x*256 + threadIdx.x;
    if (i < 2*NENT*100){
        int e = i / (NENT*100); int rem = i - e*(NENT*100);
        int r = rem/100, k = rem - r*100;
        const float* src = e ? ent1 : ent;
        split2(src[(size_t)r*100+k], &g_Eh[e][(size_t)r*K_PAD2+k], &g_El[e][(size_t)r*K_PAD2+k]);
    } else {
        int j = i - 2*NENT*100;
        if (j >= 2*NRELS*100) return;
        int e = j / (NRELS*100); int rem = j - e*(NRELS*100);
        int r = rem/100, k = rem - r*100;
        const float* src = e ? rel1 : rel;
        split2(src[(size_t)r*100+k], &g_Rh[e][(size_t)r*K_PAD2+k], &g_Rl[e][(size_t)r*K_PAD2+k]);
    }
}

// ---------------------------------------------------------------------------
__global__ void step1_kernel(const float* __restrict__ b_f,
                             const float* __restrict__ b_b,
                             const float* __restrict__ b_p)
{
    int idx = blockIdx.x*256 + threadIdx.x;
    if (idx >= 3*NENT*100) return;
    int l   = idx / (NENT*100);
    int rem = idx - l*(NENT*100);
    int e = rem/100, j = rem - e*100;
    const __half* P = g_Pe[l] + (size_t)e*400;
    const float* b = (l==0)? b_f : (l==1)? b_b : b_p;
    float iv = __half2float(P[j])     + b[j];
    float gv = __half2float(P[200+j]) + b[200+j];
    float ov = __half2float(P[300+j]) + b[300+j];
    float c1 = sigmoidf_(iv) * tanhf_(gv);
    float h1 = sigmoidf_(ov) * tanhf_(c1);
    g_h1c1[l][(size_t)e*200 + j]       = h1;
    g_h1c1[l][(size_t)e*200 + 100 + j] = c1;
    split2(h1, &g_h1h[l][(size_t)e*K_PAD2 + j], &g_h1l[l][(size_t)e*K_PAD2 + j]);
}

// ---------------------------------------------------------------------------
__global__ void __launch_bounds__(256) step12_kernel(
    const int* __restrict__ bh, const int* __restrict__ br, const int* __restrict__ bt,
    const float* __restrict__ b_f, const float* __restrict__ b_b, const float* __restrict__ b_p)
{
    __shared__ int ih[64], ir[64], it[64];
    int tid=threadIdx.x; int row0=blockIdx.x*64;
    if (tid<64)        ih[tid]     = bh[row0+tid];
    else if (tid<128)  ir[tid-64]  = br[row0+tid-64];
    else if (tid<192)  it[tid-128] = bt[row0+tid-128];
    __syncthreads();
    for (int l=0;l<3;l++){
        const __half* Pr = g_Pr[l];
        const __half* R1 = g_R1[l];
        const float*  HC = g_h1c1[l];
        const float* bias= (l==0)?b_f:(l==1)?b_b:b_p;
        for (int t=tid;t<1600;t+=256){
            int row=t/25, q=t-row*25; int j=q*4;
            int fi = (l==1)? it[row] : ih[row];
            size_t grow=(size_t)(row0+row);
            bool emit_out = ((grow % 80u)==0u) && (l<2);
            float4 h1v = *(const float4*)&HC[(size_t)fi*200 + j];
            float4 c1v = *(const float4*)&HC[(size_t)fi*200 + 100 + j];
            if (l==0){
                if (emit_out) *(float4*)&g_out[grow*600 + j] = h1v;
                storeh4(h1v, &g_Af[grow*K_PAD + j]);
            } else if (l==1){
                if (emit_out) *(float4*)&g_out[grow*600 + 500 + j] = h1v;
                storeh4(h1v, &g_Af[grow*K_PAD + 500 + j]);
            }
            const __half* pr = Pr + (size_t)ir[row]*400;
            const __half* r1 = R1 + (size_t)fi*400;
            float4 pi = loadh4(pr+j),      ri = loadh4(r1+j);
            float4 pf = loadh4(pr+100+j),  rf = loadh4(r1+100+j);
            float4 pg = loadh4(pr+200+j),  rg = loadh4(r1+200+j);
            float4 po = loadh4(pr+300+j),  ro = loadh4(r1+300+j);
            float4 bi = *(const float4*)&bias[j],    bf4= *(const float4*)&bias[100+j];
            float4 bg = *(const float4*)&bias[200+j],bo = *(const float4*)&bias[300+j];
            float4 c2v, h2v;
            {
                float c,h;
                c = sigmoidf_(pf.x+rf.x+bf4.x)*c1v.x + sigmoidf_(pi.x+ri.x+bi.x)*tanhf_(pg.x+rg.x+bg.x);
                h = sigmoidf_(po.x+ro.x+bo.x)*tanhf_(c); c2v.x=c; h2v.x=h;
                c = sigmoidf_(pf.y+rf.y+bf4.y)*c1v.y + sigmoidf_(pi.y+ri.y+bi.y)*tanhf_(pg.y+rg.y+bg.y);
                h = sigmoidf_(po.y+ro.y+bo.y)*tanhf_(c); c2v.y=c; h2v.y=h;
                c = sigmoidf_(pf.z+rf.z+bf4.z)*c1v.z + sigmoidf_(pi.z+ri.z+bi.z)*tanhf_(pg.z+rg.z+bg.z);
                h = sigmoidf_(po.z+ro.z+bo.z)*tanhf_(c); c2v.z=c; h2v.z=h;
                c = sigmoidf_(pf.w+rf.w+bf4.w)*c1v.w + sigmoidf_(pi.w+ri.w+bi.w)*tanhf_(pg.w+rg.w+bg.w);
                h = sigmoidf_(po.w+ro.w+bo.w)*tanhf_(c); c2v.w=c; h2v.w=h;
            }
            storeh4(h2v, &g_h2f[(size_t)l*M_TOTAL*K_PAD2 + grow*K_PAD2 + j]);
            *(float4*)&g_c2[(size_t)l*M_TOTAL*100 + grow*100 + j] = c2v;
            if (l==0){
                if (emit_out) *(float4*)&g_out[grow*600 + 200 + j] = h2v;
                storeh4(h2v, &g_Af[grow*K_PAD + 200 + j]);
            } else if (l==1){
                if (emit_out) *(float4*)&g_out[grow*600 + 300 + j] = h2v;
                storeh4(h2v, &g_Af[grow*K_PAD + 300 + j]);
            }
        }
    }
}

// ---------------------------------------------------------------------------
__global__ void __launch_bounds__(256) step3_kernel(
    const int* __restrict__ bh, const int* __restrict__ bt,
    const float* __restrict__ b_f, const float* __restrict__ b_b, const float* __restrict__ b_p)
{
    __shared__ int ih[64], it[64];
    int tid=threadIdx.x; int row0=blockIdx.x*64;
    if (tid<64)        ih[tid]    = bh[row0+tid];
    else if (tid<128)  it[tid-64] = bt[row0+tid-64];
    __syncthreads();
    for (int l=0;l<3;l++){
        const __half* Pe = g_Pe[l];
        const __half* R2 = g_R2f + (size_t)l*M_TOTAL*400;
        const float*  C2 = g_c2 + (size_t)l*M_TOTAL*100;
        const float* bias= (l==0)?b_f:(l==1)?b_b:b_p;
        for (int t=tid;t<1600;t+=256){
            int row=t/25, q=t-row*25; int j=q*4;
            int li = (l==1)? ih[row] : it[row];
            size_t grow=(size_t)(row0+row);
            const __half* pe = Pe + (size_t)li*400;
            const __half* r2 = R2 + grow*400;
            float4 pi = loadh4(pe+j),      ri = loadh4(r2+j);
            float4 pf = loadh4(pe+100+j),  rf = loadh4(r2+100+j);
            float4 pg = loadh4(pe+200+j),  rg = loadh4(r2+200+j);
            float4 po = loadh4(pe+300+j),  ro = loadh4(r2+300+j);
            float4 bi = *(const float4*)&bias[j],    bf4= *(const float4*)&bias[100+j];
            float4 bg = *(const float4*)&bias[200+j],bo = *(const float4*)&bias[300+j];
            float4 c2v = *(const float4*)&C2[grow*100 + j];
            float4 h3v;
            {
                float c;
                c = sigmoidf_(pf.x+rf.x+bf4.x)*c2v.x + sigmoidf_(pi.x+ri.x+bi.x)*tanhf_(pg.x+rg.x+bg.x);
                h3v.x = sigmoidf_(po.x+ro.x+bo.x)*tanhf_(c);
                c = sigmoidf_(pf.y+rf.y+bf4.y)*c2v.y + sigmoidf_(pi.y+ri.y+bi.y)*tanhf_(pg.y+rg.y+bg.y);
                h3v.y = sigmoidf_(po.y+ro.y+bo.y)*tanhf_(c);
                c = sigmoidf_(pf.z+rf.z+bf4.z)*c2v.z + sigmoidf_(pi.z+ri.z+bi.z)*tanhf_(pg.z+rg.z+bg.z);
                h3v.z = sigmoidf_(po.z+ro.z+bo.z)*tanhf_(c);
                c = sigmoidf_(pf.w+rf.w+bf4.w)*c2v.w + sigmoidf_(pi.w+ri.w+bi.w)*tanhf_(pg.w+rg.w+bg.w);
                h3v.w = sigmoidf_(po.w+ro.w+bo.w)*tanhf_(c);
            }
            bool emit_out = ((grow % 80u)==0u);
            if (l==0){
                if (emit_out) *(float4*)&g_out[grow*600 + 400 + j] = h3v;
                storeh4(h3v, &g_Af[grow*K_PAD + 400 + j]);
            } else if (l==1){
                if (emit_out) *(float4*)&g_out[grow*600 + 100 + j] = h3v;
                storeh4(h3v, &g_Af[grow*K_PAD + 100 + j]);
            } else {
                *(float4*)&g_op[grow*100 + j] = h3v;
            }
        }
    }
}

// ---------------------------------------------------------------------------
__global__ void __launch_bounds__(256,1) gat1_att(
    const float* __restrict__ a1, float* __restrict__ out_att, float* __restrict__ out2)
{
    __shared__ __align__(16) float a1s[1200];
    __shared__ float ebuf[41];
    __shared__ float att[40];
    __shared__ float red[2];
    int b=blockIdx.x, tid=threadIdx.x, warp=tid>>5, lane=tid&31;
    for (int i=tid;i<1200;i+=256) a1s[i]=a1[i];
    __syncthreads();
    const __half* base = g_hGf + (size_t)b*24000;
    for (int t=warp;t<41;t+=8){
        const __half* rowp = (t<40)? base + t*600 : base;
        const float* av    = (t<40)? a1s          : a1s+600;
        float s=0.f;
        for (int kk=lane;kk<75;kk+=32){
            uint4 raw = *(const uint4*)(rowp + kk*8);
            __half2* hv = (__half2*)&raw;
            const float* ap = av + kk*8;
            float2 f0=__half22float2(hv[0]), f1=__half22float2(hv[1]);
            float2 f2=__half22float2(hv[2]), f3=__half22float2(hv[3]);
            s += f0.x*ap[0]+f0.y*ap[1]+f1.x*ap[2]+f1.y*ap[3]
               + f2.x*ap[4]+f2.y*ap[5]+f3.x*ap[6]+f3.y*ap[7];
        }
        #pragma unroll
        for (int o=16;o;o>>=1) s += __shfl_xor_sync(0xffffffffu, s, o);
        if (lane==0) ebuf[t]=s;
    }
    __syncthreads();
    if (tid<40){
        float x = ebuf[tid] + ebuf[40];
        ebuf[tid] = (x>0.f)? x : 0.2f*x;
    }
    __syncthreads();
    if (tid<32){
        float v = ebuf[tid];
        if (tid<8) v = fmaxf(v, ebuf[tid+32]);
        #pragma unroll
        for (int o=16;o;o>>=1) v = fmaxf(v, __shfl_xor_sync(0xffffffffu, v, o));
        if (tid==0) red[0]=v;
    }
    __syncthreads();
    if (tid<40) att[tid]=__expf(ebuf[tid]-red[0]);
    __syncthreads();
    if (tid<32){
        float v = att[tid] + ((tid<8)? att[tid+32] : 0.f);
        #pragma unroll
        for (int o=16;o;o>>=1) v += __shfl_xor_sync(0xffffffffu, v, o);
        if (tid==0) red[1]=1.f/v;
    }
    __syncthreads();
    if (tid<40) att[tid]=fmaxf(att[tid]*red[1]-0.001f, 0.f);
    __syncthreads();
    for (int f2=tid; f2<300; f2+=256){
        float ax=0.f, ay=0.f;
        const __half2* col = (const __half2*)base + f2;
        #pragma unroll 8
        for (int n=0;n<40;n++){
            float2 v = __half22float2(col[n*300]);
            ax += att[n]*v.x; ay += att[n]*v.y;
        }
        out_att[(size_t)b*600 + f2*2]     = ax;
        out_att[(size_t)b*600 + f2*2 + 1] = ay;
    }
    if ((b&1)==0){
        const float* srow = g_out + (size_t)b*40*600;
        float* drow = out2 + (size_t)(b>>1)*600;
        for (int f=tid;f<600;f+=256) drow[f]=srow[f];
    }
}

// ---------------------------------------------------------------------------
#define GAT2_SMEM ((4000 + 10000 + 4000)*4)
__global__ void __launch_bounds__(256,1) gat2_kernel(
    const float* __restrict__ W2, const float* __restrict__ a2,
    float* __restrict__ output_att, float* __restrict__ op2)
{
    extern __shared__ float sm[];
    float* ops = sm;
    float* Ws  = ops + 4000;
    float* hg  = Ws  + 10000;
    __shared__ float a2s[200];
    __shared__ float ebuf[41];
    __shared__ float att[40];
    __shared__ float red[2];
    int b=blockIdx.x, tid=threadIdx.x, warp=tid>>5, lane=tid&31;
    const float* src = g_op + (size_t)b*4000;
    for (int i=tid;i<4000;i+=256)  ops[i]=src[i];
    for (int i=tid;i<10000;i+=256) Ws[i]=W2[i];
    if (tid<200) a2s[tid]=a2[tid];
    __syncthreads();
    for (int i=tid;i<4000;i+=256){
        int n=i/100, o=i-n*100;
        float acc=0.f;
        #pragma unroll 4
        for (int k=0;k<100;k++) acc=fmaf(ops[n*100+k], Ws[k*100+o], acc);
        hg[i]=acc;
    }
    __syncthreads();
    for (int t=warp;t<41;t+=8){
        const float* rowp = (t<40)? hg + t*100 : hg;
        const float* av   = (t<40)? a2s        : a2s+100;
        float s=0.f;
        for (int k=lane;k<100;k+=32) s += rowp[k]*av[k];
        #pragma unroll
        for (int o=16;o;o>>=1) s += __shfl_xor_sync(0xffffffffu, s, o);
        if (lane==0) ebuf[t]=s;
    }
    __syncthreads();
    if (tid<40){
        float x = ebuf[tid] + ebuf[40];
        ebuf[tid] = (x>0.f)? x : 0.2f*x;
    }
    __syncthreads();
    if (tid<32){
        float v = ebuf[tid];
        if (tid<8) v = fmaxf(v, ebuf[tid+32]);
        #pragma unroll
        for (int o=16;o;o>>=1) v = fmaxf(v, __shfl_xor_sync(0xffffffffu, v, o));
        if (tid==0) red[0]=v;
    }
    __syncthreads();
    if (tid<40) att[tid]=__expf(ebuf[tid]-red[0]);
    __syncthreads();
    if (tid<32){
        float v = att[tid] + ((tid<8)? att[tid+32] : 0.f);
        #pragma unroll
        for (int o=16;o;o>>=1) v += __shfl_xor_sync(0xffffffffu, v, o);
        if (tid==0) red[1]=1.f/v;
    }
    __syncthreads();
    if (tid<40) att[tid]=fmaxf(att[tid]*red[1]-0.001f, 0.f);
    __syncthreads();
    if (tid<100){
        float acc=0.f;
        #pragma unroll 8
        for (int n=0;n<40;n++) acc += att[n]*hg[n*100+tid];
        output_att[(size_t)b*100+tid]=acc;
    }
    if ((b&1)==0){
        const float* srow = g_op + (size_t)b*40*100;
        float* drow = op2 + (size_t)(b>>1)*100;
        if (tid<100) drow[tid]=srow[tid];
    }
}

// ---------------------------------------------------------------------------
extern "C" void kernel_launch(void* const* d_in, const int* in_sizes, int n_in,
                              void* d_out, int out_size)
{
    const int*   bh    = (const int*)  d_in[0];
    const int*   br    = (const int*)  d_in[1];
    const int*   bt    = (const int*)  d_in[2];
    const float* ent   = (const float*)d_in[3];
    const float* rel   = (const float*)d_in[4];
    const float* ent1  = (const float*)d_in[5];
    const float* rel1  = (const float*)d_in[6];
    const float* Wih_f = (const float*)d_in[7];
    const float* Whh_f = (const float*)d_in[8];
    const float* b_f   = (const float*)d_in[9];
    const float* Wih_b = (const float*)d_in[10];
    const float* Whh_b = (const float*)d_in[11];
    const float* b_b   = (const float*)d_in[12];
    const float* Wih_p = (const float*)d_in[13];
    const float* Whh_p = (const float*)d_in[14];
    const float* b_p   = (const float*)d_in[15];
    const float* W1    = (const float*)d_in[16];
    const float* a1    = (const float*)d_in[17];
    const float* W2    = (const float*)d_in[18];
    const float* a2    = (const float*)d_in[19];

    float* out        = (float*)d_out;
    float* out2       = out;                          // [1024,600]
    float* out_att    = out + 1024*600;               // [2048,600]
    float* op2        = out + 1024*600 + 2048*600;    // [1024,100]
    float* output_att = op2 + 1024*100;               // [2048,100]

    cudaFuncSetAttribute(gat2_kernel, cudaFuncAttributeMaxDynamicSharedMemorySize, GAT2_SMEM);
    cudaFuncSetAttribute(mma_gemm,    cudaFuncAttributeMaxDynamicSharedMemorySize, MM_SMEM);
    cudaFuncSetAttribute(mma_f16,     cudaFuncAttributeMaxDynamicSharedMemorySize, MMF_SMEM);

    convB_kernel<<<(600*600 + 255)/256, 256>>>(W1);
    convW6_kernel<<<(6*400*100 + 255)/256, 256>>>(Whh_f, Whh_b, Whh_p, Wih_f, Wih_b, Wih_p);
    convE_kernel<<<(2*(NENT+NRELS)*100 + 255)/256, 256>>>(ent, ent1, rel, rel1);

    dim3 pe(4, NENT_P/64, 3);
    mma_gemm<<<pe, 256, MM_SMEM>>>(2);
    dim3 pr(4, 4, 3);
    mma_gemm<<<pr, 256, MM_SMEM>>>(3);

    step1_kernel<<<(3*NENT*100 + 255)/256, 256>>>(b_f, b_b, b_p);

    mma_gemm<<<pe, 256, MM_SMEM>>>(4);

    step12_kernel<<<M_TOTAL/64, 256>>>(bh, br, bt, b_f, b_b, b_p);

    dim3 rg(4, M_TOTAL/64, 3);
    mma_f16<<<rg, 256, MMF_SMEM>>>(1);

    step3_kernel<<<M_TOTAL/64, 256>>>(bh, bt, b_f, b_b, b_p);

    dim3 gg(5, M_TOTAL/64, 1);
    mma_f16<<<gg, 256, MMF_SMEM>>>(0);

    gat1_att<<<NGROUP, 256>>>(a1, out_att, out2);

    gat2_kernel<<<NGROUP, 256, GAT2_SMEM>>>(W2, a2, output_att, op2);

    (void)in_sizes; (void)n_in; (void)out_size;
}